// round 9
// baseline (speedup 1.0000x reference)
#include <cuda_runtime.h>
#include <cuda_bf16.h>
#include <math.h>
#include <stdint.h>

// ---------------- problem constants ----------------
#define DIM   256
#define HEADS 8
#define HD    32
#define B_    2
#define T_    8
#define H_    56
#define W_    56
#define WT    2
#define WH    7
#define WW    7
#define STs   1
#define SHs   3
#define SWs   3
#define NTOK  (B_*T_*H_*W_)   // 50176 = 392*128 = 784*64
#define BW_   512
#define N_    98
#define HID   1024

// ---------------- scratch (device globals) ----------
__device__ __nv_bfloat16 g_xw [NTOK*256];
__device__ __nv_bfloat16 g_qkv[(size_t)NTOK*768];
__device__ __nv_bfloat16 g_att[NTOK*256];
__device__ float         g_x2 [NTOK*256];
__device__ __nv_bfloat16 g_hn [NTOK*256];
__device__ __nv_bfloat16 g_wqkv [768*256];
__device__ __nv_bfloat16 g_wproj[256*256];
__device__ __nv_bfloat16 g_wfc1 [1024*256];
__device__ __nv_bfloat16 g_wfc2 [256*1024];
__device__ float         g_bm[8*HEADS*112*112];

// ---------------- PTX helpers ----------------------
__device__ __forceinline__ uint32_t smem_u32(const void* p) {
    uint32_t a;
    asm("{ .reg .u64 t; cvta.to.shared.u64 t, %1; cvt.u32.u64 %0, t; }" : "=r"(a) : "l"(p));
    return a;
}
#define CP_ASYNC16(sm, gp) \
    asm volatile("cp.async.cg.shared.global [%0], [%1], 16;" :: "r"(sm), "l"(gp))
#define CP_COMMIT() asm volatile("cp.async.commit_group;" ::: "memory")
#define CP_WAIT0()  asm volatile("cp.async.wait_group 0;" ::: "memory")
#define CP_WAIT1()  asm volatile("cp.async.wait_group 1;" ::: "memory")

#define LDMATRIX_X4(r0,r1,r2,r3,addr) \
    asm volatile("ldmatrix.sync.aligned.m8n8.x4.shared.b16 {%0,%1,%2,%3}, [%4];" \
        : "=r"(r0), "=r"(r1), "=r"(r2), "=r"(r3) : "r"(addr))
#define LDMATRIX_X4T(r0,r1,r2,r3,addr) \
    asm volatile("ldmatrix.sync.aligned.m8n8.x4.trans.shared.b16 {%0,%1,%2,%3}, [%4];" \
        : "=r"(r0), "=r"(r1), "=r"(r2), "=r"(r3) : "r"(addr))
#define MMA_BF16(c, a, b) \
    asm volatile("mma.sync.aligned.m16n8k16.row.col.f32.bf16.bf16.f32 " \
        "{%0,%1,%2,%3}, {%4,%5,%6,%7}, {%8,%9}, {%0,%1,%2,%3};" \
        : "+f"((c)[0]), "+f"((c)[1]), "+f"((c)[2]), "+f"((c)[3]) \
        : "r"((a)[0]), "r"((a)[1]), "r"((a)[2]), "r"((a)[3]), "r"((b)[0]), "r"((b)[1]))

// ---------------- bf16 store helpers ----------------
__device__ __forceinline__ uint32_t pack2(__nv_bfloat16 a, __nv_bfloat16 b) {
    return (uint32_t)__bfloat16_as_ushort(a) | ((uint32_t)__bfloat16_as_ushort(b) << 16);
}
__device__ __forceinline__ uint32_t pack2f(float a, float b) {
    return pack2(__float2bfloat16_rn(a), __float2bfloat16_rn(b));
}
__device__ __forceinline__ void plain_store4(__nv_bfloat16* rowp, int col,
                                             float a0, float a1, float a2, float a3) {
    uint2 u;
    u.x = pack2f(a0, a1);
    u.y = pack2f(a2, a3);
    *(uint2*)(rowp + col) = u;
}
__device__ __forceinline__ float gelu_f(float v) {
    return 0.5f * v * (1.0f + erff(v * 0.70710678118654752f));
}

// ---------------- fused setup: weight converts + bias/mask table -----------
#define NW_QKV (768*256)
#define NW_PROJ (256*256)
#define NW_FC1 (1024*256)
#define NW_FC2 (256*1024)
#define NBM    (8*112*112)
#define SETUP_ITEMS (NW_QKV + NW_PROJ + NW_FC1 + NW_FC2 + NBM)

__global__ void setup_kernel(const float* __restrict__ qkvw, const float* __restrict__ projw,
                             const float* __restrict__ fc1w, const float* __restrict__ fc2w,
                             const float* __restrict__ rpe) {
    int idx = blockIdx.x * 256 + threadIdx.x;
    if (idx >= SETUP_ITEMS) return;
    if (idx < NW_QKV) {
        g_wqkv[idx] = __float2bfloat16_rn(qkvw[idx]);
    } else if ((idx -= NW_QKV) < NW_PROJ) {
        g_wproj[idx] = __float2bfloat16_rn(projw[idx]);
    } else if ((idx -= NW_PROJ) < NW_FC1) {
        g_wfc1[idx] = __float2bfloat16_rn(fc1w[idx]);
    } else if ((idx -= NW_FC1) < NW_FC2) {
        g_wfc2[idx] = __float2bfloat16_rn(fc2w[idx]);
    } else {
        int i = idx - NW_FC2;
        int cat = i / (112*112);
        int rm = i % (112*112);
        int r = rm / 112, m = rm % 112;
        if (r < N_ && m < N_) {
            int ct = cat >> 2, ch = (cat >> 1) & 1, cw = cat & 1;
            int tr = r/49, hr = (r%49)/7, wr = r%7;
            int tm = m/49, hm = (m%49)/7, wm = m%7;
            int regr = (ct ? (tr==0?1:2) : 0)*9 + (ch ? (hr<4?1:2) : 0)*3 + (cw ? (wr<4?1:2) : 0);
            int regm = (ct ? (tm==0?1:2) : 0)*9 + (ch ? (hm<4?1:2) : 0)*3 + (cw ? (wm<4?1:2) : 0);
            int tix = (tr - tm + 1)*169 + (hr - hm + 6)*13 + (wr - wm + 6);
            float msk = (regr != regm) ? -100.0f : 0.0f;
            #pragma unroll
            for (int h = 0; h < HEADS; h++)
                g_bm[((cat*8 + h)*112 + r)*112 + m] = rpe[tix*HEADS + h] + msk;
        } else {
            float v = (m >= N_) ? -1e30f : 0.0f;
            #pragma unroll
            for (int h = 0; h < HEADS; h++)
                g_bm[((cat*8 + h)*112 + r)*112 + m] = v;
        }
    }
}

// ---------------- LN kernel (mode 0: +roll+partition; mode 1: plain) -------
__global__ void ln_kernel(const float* __restrict__ src, __nv_bfloat16* __restrict__ dst,
                          const float* __restrict__ w, const float* __restrict__ b, int mode) {
    int warp = threadIdx.x >> 5, lane = threadIdx.x & 31;
    int row = blockIdx.x * 8 + warp;
    const float* sr = src + (size_t)row * DIM;
    float4 v0 = *(const float4*)(sr + lane * 4);
    float4 v1 = *(const float4*)(sr + 128 + lane * 4);
    float s  = v0.x + v0.y + v0.z + v0.w + v1.x + v1.y + v1.z + v1.w;
    float ss = v0.x*v0.x + v0.y*v0.y + v0.z*v0.z + v0.w*v0.w
             + v1.x*v1.x + v1.y*v1.y + v1.z*v1.z + v1.w*v1.w;
    #pragma unroll
    for (int o = 16; o > 0; o >>= 1) {
        s  += __shfl_xor_sync(0xffffffffu, s, o);
        ss += __shfl_xor_sync(0xffffffffu, ss, o);
    }
    float mean = s * (1.0f / 256.0f);
    float var  = ss * (1.0f / 256.0f) - mean * mean;
    float inv  = rsqrtf(var + 1e-5f);
    int c0 = lane * 4, c1 = 128 + lane * 4;
    float o00 = (v0.x - mean) * inv * w[c0+0] + b[c0+0];
    float o01 = (v0.y - mean) * inv * w[c0+1] + b[c0+1];
    float o02 = (v0.z - mean) * inv * w[c0+2] + b[c0+2];
    float o03 = (v0.w - mean) * inv * w[c0+3] + b[c0+3];
    float o10 = (v1.x - mean) * inv * w[c1+0] + b[c1+0];
    float o11 = (v1.y - mean) * inv * w[c1+1] + b[c1+1];
    float o12 = (v1.z - mean) * inv * w[c1+2] + b[c1+2];
    float o13 = (v1.w - mean) * inv * w[c1+3] + b[c1+3];

    size_t drow = row;
    if (mode == 0) {
        int bb = row / (T_*H_*W_);
        int r2 = row % (T_*H_*W_);
        int t = r2 / (H_*W_);
        int r3 = r2 % (H_*W_);
        int h = r3 / W_, ww_ = r3 % W_;
        int t2 = t - STs; if (t2 < 0) t2 += T_;
        int h2 = h - SHs; if (h2 < 0) h2 += H_;
        int w2 = ww_ - SWs; if (w2 < 0) w2 += W_;
        int tw = t2 / WT, hw = h2 / WH, wwn = w2 / WW;
        int n = (t2 % WT) * 49 + (h2 % WH) * 7 + (w2 % WW);
        int bw = ((bb * 4 + tw) * 8 + hw) * 8 + wwn;
        drow = (size_t)bw * N_ + n;
    }
    __nv_bfloat16* dr = dst + drow * 256;
    plain_store4(dr, c0, o00, o01, o02, o03);
    plain_store4(dr, c1, o10, o11, o12, o13);
}

// ---------------- mma.sync GEMM (qkv / proj) --------------------------------
#define ABUF 18432
#define BUFSZ (2*ABUF)
#define GEMM_SMEM (3*BUFSZ)

template<int EPI>
__global__ __launch_bounds__(256) void gemm_mma(
        const __nv_bfloat16* __restrict__ A, const __nv_bfloat16* __restrict__ Wm,
        const float* __restrict__ bias, const float* __restrict__ resid,
        float* __restrict__ outF, __nv_bfloat16* __restrict__ outB, int K3) {
    extern __shared__ __align__(16) char smraw[];
    int tid = threadIdx.x, lane = tid & 31, wid = tid >> 5;
    int brow = blockIdx.y * 128, bcol = blockIdx.x * 128;
    int wm = wid & 1, wn = wid >> 1;
    uint32_t sb = smem_u32(smraw);

    float acc[4][4][4] = {};
    const int NC = K3 >> 6;

    const char* Agc = (const char*)(A  + (size_t)brow * K3);
    const char* Bgc = (const char*)(Wm + (size_t)bcol * K3);
    size_t rowstride = (size_t)K3 * 2;

    auto loadChunk = [&](int c, int buf) {
        uint32_t abase = sb + buf * BUFSZ;
        uint32_t bbase = abase + ABUF;
        const char* Ag = Agc + (size_t)c * 128;
        const char* Bg = Bgc + (size_t)c * 128;
        #pragma unroll
        for (int j = 0; j < 4; j++) {
            int x = tid + j * 256;
            int row = x >> 3, kc = x & 7;
            CP_ASYNC16(abase + row * 144 + kc * 16, Ag + (size_t)row * rowstride + kc * 16);
            CP_ASYNC16(bbase + row * 144 + kc * 16, Bg + (size_t)row * rowstride + kc * 16);
        }
        CP_COMMIT();
    };

    loadChunk(0, 0);
    if (NC > 1) loadChunk(1, 1);
    int bc = 0, bn2 = 2;
    for (int c = 0; c < NC; c++) {
        if (c + 1 < NC) CP_WAIT1(); else CP_WAIT0();
        __syncthreads();
        if (c + 2 < NC) loadChunk(c + 2, bn2);
        uint32_t abase = sb + bc * BUFSZ;
        uint32_t bbase = abase + ABUF;
        #pragma unroll
        for (int kh = 0; kh < 4; kh++) {
            uint32_t afr[4][4];
            #pragma unroll
            for (int mt = 0; mt < 4; mt++) {
                int row = wm * 64 + mt * 16 + ((lane >> 3) & 1) * 8 + (lane & 7);
                uint32_t addr = abase + row * 144 + kh * 32 + (lane >> 4) * 16;
                LDMATRIX_X4(afr[mt][0], afr[mt][1], afr[mt][2], afr[mt][3], addr);
            }
            uint32_t bfr[4][2];
            #pragma unroll
            for (int np = 0; np < 2; np++) {
                int nrow = wn * 32 + np * 16 + (lane >> 4) * 8 + (lane & 7);
                uint32_t addr = bbase + nrow * 144 + kh * 32 + ((lane >> 3) & 1) * 16;
                uint32_t r0, r1, r2, r3;
                LDMATRIX_X4(r0, r1, r2, r3, addr);
                bfr[np*2][0] = r0; bfr[np*2][1] = r1;
                bfr[np*2+1][0] = r2; bfr[np*2+1][1] = r3;
            }
            #pragma unroll
            for (int mt = 0; mt < 4; mt++)
                #pragma unroll
                for (int nt = 0; nt < 4; nt++)
                    MMA_BF16(acc[mt][nt], afr[mt], bfr[nt]);
        }
        bc++;  if (bc == 3)  bc = 0;
        bn2++; if (bn2 == 3) bn2 = 0;
    }
    __syncthreads();

    float* Cs = (float*)smraw;
    #pragma unroll
    for (int mt = 0; mt < 4; mt++)
        #pragma unroll
        for (int nt = 0; nt < 4; nt++) {
            int r0 = wm * 64 + mt * 16 + (lane >> 2);
            int cc = wn * 32 + nt * 8 + (lane & 3) * 2;
            Cs[r0 * 132 + cc]       = acc[mt][nt][0];
            Cs[r0 * 132 + cc + 1]   = acc[mt][nt][1];
            Cs[(r0+8) * 132 + cc]   = acc[mt][nt][2];
            Cs[(r0+8) * 132 + cc+1] = acc[mt][nt][3];
        }
    __syncthreads();

    float4 bs = *(const float4*)(bias + bcol + lane * 4);
    for (int r = wid; r < 128; r += 8) {
        float4 v = *(const float4*)&Cs[r * 132 + lane * 4];
        v.x += bs.x; v.y += bs.y; v.z += bs.z; v.w += bs.w;
        int grow = brow + r;
        int col = bcol + lane * 4;
        if (EPI == 0) {
            plain_store4(outB + (size_t)grow * 768, col, v.x, v.y, v.z, v.w);
        } else if (EPI == 2) {
            int bw = grow / N_, n = grow % N_;
            int bb = bw >> 8, wrem = bw & 255;
            int tw = wrem >> 6, hw = (wrem >> 3) & 7, wwn = wrem & 7;
            int nt = n / 49, nr = n % 49;
            int t2 = tw*WT + nt, h2 = hw*WH + nr/7, w2 = wwn*WW + nr%7;
            int t = t2 + STs; if (t >= T_) t -= T_;
            int h = h2 + SHs; if (h >= H_) h -= H_;
            int ww_ = w2 + SWs; if (ww_ >= W_) ww_ -= W_;
            size_t orow = ((size_t)((bb*T_ + t)*H_ + h))*W_ + ww_;
            float4 rr = *(const float4*)(resid + orow * 256 + col);
            v.x += rr.x; v.y += rr.y; v.z += rr.z; v.w += rr.w;
            *(float4*)(outF + orow * 256 + col) = v;
        }
    }
}

// ---------------- fused MLP: out = resid + fc2(gelu(fc1(hn))) ---------------
// 64-row stripe per block. hn rows resident in smem; loop over 16 hid-chunks
// of 64: GEMM1 (K=256) -> bias+GELU -> bf16 h in smem -> GEMM2 acc (K=64).
// w1/w2 chunks double-buffered cp.async (L2-resident weights).
#define OFF_A   0                   // 64 rows x 528B = 33792
#define OFF_W1  33792               // 2 x 33792
#define OFF_W2  101376              // 2 x 36864 (256 rows x 144B)
#define OFF_H   175104              // 64 rows x 144B = 9216
#define MLP_SMEM 184320

__global__ __launch_bounds__(256, 1) void mlp_fused(
        const __nv_bfloat16* __restrict__ hn, const __nv_bfloat16* __restrict__ w1,
        const float* __restrict__ b1, const __nv_bfloat16* __restrict__ w2,
        const float* __restrict__ b2, const float* __restrict__ resid,
        float* __restrict__ out) {
    extern __shared__ __align__(16) char sm[];
    uint32_t sb = smem_u32(sm);
    int tid = threadIdx.x, lane = tid & 31, wid = tid >> 5;
    int brow = blockIdx.x * 64;

    // A = hn rows (64 x 256 bf16), stride 528
    {
        const char* src = (const char*)(hn + (size_t)brow * 256);
        #pragma unroll
        for (int j = 0; j < 8; j++) {
            int x = tid + j * 256;
            int row = x >> 5, kc = x & 31;
            CP_ASYNC16(sb + OFF_A + row * 528 + kc * 16, src + (size_t)row * 512 + kc * 16);
        }
    }
    auto loadW = [&](int c, int buf) {
        const char* s1 = (const char*)(w1 + (size_t)c * 64 * 256);
        #pragma unroll
        for (int j = 0; j < 8; j++) {
            int x = tid + j * 256;
            int row = x >> 5, kc = x & 31;
            CP_ASYNC16(sb + OFF_W1 + buf * 33792 + row * 528 + kc * 16,
                       s1 + (size_t)row * 512 + kc * 16);
        }
        const char* s2 = (const char*)(w2 + (size_t)c * 64);
        #pragma unroll
        for (int j = 0; j < 8; j++) {
            int x = tid + j * 256;
            int row = x >> 3, kc = x & 7;
            CP_ASYNC16(sb + OFF_W2 + buf * 36864 + row * 144 + kc * 16,
                       s2 + (size_t)row * 2048 + kc * 16);
        }
    };
    loadW(0, 0); CP_COMMIT();   // group0 (includes A)
    loadW(1, 1); CP_COMMIT();   // group1

    float acc[4][4][4] = {};
    int wm1 = wid & 3, wn1 = wid >> 2;   // GEMM1: 4x2 grid, warp tile 16x32
    int wn2 = wid;                        // GEMM2: 1x8 grid, warp tile 64x32

    for (int c = 0; c < 16; c++) {
        if (c + 1 < 16) CP_WAIT1(); else CP_WAIT0();
        __syncthreads();
        int buf = c & 1;
        uint32_t w1b = sb + OFF_W1 + buf * 33792;
        uint32_t w2b = sb + OFF_W2 + buf * 36864;

        // ---- GEMM1: S1[64x64] = A @ w1_c^T, K=256 ----
        float s1[4][4] = {};
        #pragma unroll
        for (int ks = 0; ks < 16; ks++) {
            uint32_t a[4];
            {
                int row = wm1 * 16 + ((lane >> 3) & 1) * 8 + (lane & 7);
                uint32_t addr = sb + OFF_A + row * 528 + ks * 32 + (lane >> 4) * 16;
                LDMATRIX_X4(a[0], a[1], a[2], a[3], addr);
            }
            uint32_t bfr[4][2];
            #pragma unroll
            for (int np = 0; np < 2; np++) {
                int nrow = wn1 * 32 + np * 16 + (lane >> 4) * 8 + (lane & 7);
                uint32_t addr = w1b + nrow * 528 + ks * 32 + ((lane >> 3) & 1) * 16;
                uint32_t r0, r1, r2, r3;
                LDMATRIX_X4(r0, r1, r2, r3, addr);
                bfr[np*2][0] = r0; bfr[np*2][1] = r1;
                bfr[np*2+1][0] = r2; bfr[np*2+1][1] = r3;
            }
            #pragma unroll
            for (int nt = 0; nt < 4; nt++)
                MMA_BF16(s1[nt], a, bfr[nt]);
        }
        // bias1 + GELU -> Hbuf (bf16, stride 144)
        {
            int r0 = wm1 * 16 + (lane >> 2);
            #pragma unroll
            for (int nt = 0; nt < 4; nt++) {
                int coll = wn1 * 32 + nt * 8 + (lane & 3) * 2;
                float bb0 = __ldg(&b1[c*64 + coll]);
                float bb1 = __ldg(&b1[c*64 + coll + 1]);
                float g0 = gelu_f(s1[nt][0] + bb0);
                float g1 = gelu_f(s1[nt][1] + bb1);
                float g2 = gelu_f(s1[nt][2] + bb0);
                float g3 = gelu_f(s1[nt][3] + bb1);
                *(uint32_t*)(sm + OFF_H + r0 * 144 + coll * 2)       = pack2f(g0, g1);
                *(uint32_t*)(sm + OFF_H + (r0 + 8) * 144 + coll * 2) = pack2f(g2, g3);
            }
        }
        __syncthreads();

        // ---- GEMM2: acc += H[64x64] @ w2_c^T, K=64 ----
        #pragma unroll
        for (int kt = 0; kt < 4; kt++) {
            uint32_t afr[4][4];
            #pragma unroll
            for (int mt = 0; mt < 4; mt++) {
                int row = mt * 16 + ((lane >> 3) & 1) * 8 + (lane & 7);
                uint32_t addr = sb + OFF_H + row * 144 + kt * 32 + (lane >> 4) * 16;
                LDMATRIX_X4(afr[mt][0], afr[mt][1], afr[mt][2], afr[mt][3], addr);
            }
            uint32_t bfr[4][2];
            #pragma unroll
            for (int np = 0; np < 2; np++) {
                int nrow = wn2 * 32 + np * 16 + (lane >> 4) * 8 + (lane & 7);
                uint32_t addr = w2b + nrow * 144 + kt * 32 + ((lane >> 3) & 1) * 16;
                uint32_t r0, r1, r2, r3;
                LDMATRIX_X4(r0, r1, r2, r3, addr);
                bfr[np*2][0] = r0; bfr[np*2][1] = r1;
                bfr[np*2+1][0] = r2; bfr[np*2+1][1] = r3;
            }
            #pragma unroll
            for (int mt = 0; mt < 4; mt++)
                #pragma unroll
                for (int nt = 0; nt < 4; nt++)
                    MMA_BF16(acc[mt][nt], afr[mt], bfr[nt]);
        }
        __syncthreads();
        if (c + 2 < 16) { loadW(c + 2, buf); CP_COMMIT(); }
    }

    // ---- epilogue: stage fp32 (stride 264 floats), +bias2 +resid ----
    float* Cs = (float*)sm;
    #pragma unroll
    for (int mt = 0; mt < 4; mt++)
        #pragma unroll
        for (int nt = 0; nt < 4; nt++) {
            int r0 = mt * 16 + (lane >> 2);
            int cc = wn2 * 32 + nt * 8 + (lane & 3) * 2;
            Cs[r0 * 264 + cc]         = acc[mt][nt][0];
            Cs[r0 * 264 + cc + 1]     = acc[mt][nt][1];
            Cs[(r0+8) * 264 + cc]     = acc[mt][nt][2];
            Cs[(r0+8) * 264 + cc + 1] = acc[mt][nt][3];
        }
    __syncthreads();

    for (int r = wid; r < 64; r += 8) {
        #pragma unroll
        for (int half = 0; half < 2; half++) {
            int col = half * 128 + lane * 4;
            float4 v = *(const float4*)&Cs[r * 264 + col];
            float4 bs = *(const float4*)(b2 + col);
            float4 rr = *(const float4*)(resid + (size_t)(brow + r) * 256 + col);
            v.x += bs.x + rr.x; v.y += bs.y + rr.y;
            v.z += bs.z + rr.z; v.w += bs.w + rr.w;
            *(float4*)(out + (size_t)(brow + r) * 256 + col) = v;
        }
    }
}

// ---------------- register-resident tensor-core attention ------------------
#define QSTR 80
#define SM_Q  0
#define SM_K  (112*QSTR)
#define SM_V  (2*112*QSTR)
#define ATTN_SMEM (3*112*QSTR)

__global__ __launch_bounds__(128) void attn_tc() {
    extern __shared__ __align__(16) char asmem[];

    int tid = threadIdx.x, lane = tid & 31, wid = tid >> 5;
    int head = blockIdx.x & 7, bw = blockIdx.x >> 3;
    int wrem = bw & 255;
    int tw = wrem >> 6, hw = (wrem >> 3) & 7, wwn = wrem & 7;
    int cat = ((tw == 3) ? 4 : 0) | ((hw == 7) ? 2 : 0) | ((wwn == 7) ? 1 : 0);

    uint32_t uQ = smem_u32(asmem + SM_Q);
    uint32_t uK = smem_u32(asmem + SM_K);
    uint32_t uV = smem_u32(asmem + SM_V);

    if (tid < N_) {
        const uint4* g = (const uint4*)(g_qkv + ((size_t)(bw*N_ + tid)) * 768 + head * HD);
        #pragma unroll
        for (int j = 0; j < 4; j++) {
            *(uint4*)(asmem + SM_Q + tid*QSTR + j*16) = g[j];
            *(uint4*)(asmem + SM_K + tid*QSTR + j*16) = g[32 + j];
            *(uint4*)(asmem + SM_V + tid*QSTR + j*16) = g[64 + j];
        }
    } else if (tid < 112) {
        uint4 z = make_uint4(0,0,0,0);
        #pragma unroll
        for (int j = 0; j < 4; j++) {
            *(uint4*)(asmem + SM_Q + tid*QSTR + j*16) = z;
            *(uint4*)(asmem + SM_K + tid*QSTR + j*16) = z;
            *(uint4*)(asmem + SM_V + tid*QSTR + j*16) = z;
        }
    }
    __syncthreads();

    int nmt = (wid < 3) ? 2 : 1;
    float acc[2][14][4] = {};

    #pragma unroll
    for (int kh = 0; kh < 2; kh++) {
        uint32_t bfr[14][2];
        #pragma unroll
        for (int np = 0; np < 7; np++) {
            int nrow = np*16 + (lane >> 4) * 8 + (lane & 7);
            uint32_t addr = uK + nrow*QSTR + kh*32 + ((lane >> 3) & 1) * 16;
            uint32_t r0, r1, r2, r3;
            LDMATRIX_X4(r0, r1, r2, r3, addr);
            bfr[np*2][0] = r0; bfr[np*2][1] = r1;
            bfr[np*2+1][0] = r2; bfr[np*2+1][1] = r3;
        }
        for (int mtl = 0; mtl < nmt; mtl++) {
            int mt = wid + mtl*4;
            int row = mt*16 + ((lane >> 3) & 1) * 8 + (lane & 7);
            uint32_t addr = uQ + row*QSTR + kh*32 + (lane >> 4) * 16;
            uint32_t afr[4];
            LDMATRIX_X4(afr[0], afr[1], afr[2], afr[3], addr);
            #pragma unroll
            for (int nt = 0; nt < 14; nt++)
                MMA_BF16(acc[mtl][nt], afr, bfr[nt]);
        }
    }

    float inv0[2], inv1[2];
    for (int mtl = 0; mtl < nmt; mtl++) {
        int mt = wid + mtl*4;
        int row0 = mt*16 + (lane >> 2);
        const float* bm = g_bm + ((size_t)(cat*8 + head)*112 + row0)*112;
        int c0 = (lane & 3) * 2;
        float mx0 = -1e30f, mx1 = -1e30f;
        #pragma unroll
        for (int nt = 0; nt < 14; nt++) {
            float2 b0 = *(const float2*)(bm + nt*8 + c0);
            float2 b1 = *(const float2*)(bm + 8*112 + nt*8 + c0);
            float s0 = fmaf(acc[mtl][nt][0], 0.17677669529663687f, b0.x);
            float s1 = fmaf(acc[mtl][nt][1], 0.17677669529663687f, b0.y);
            float s2 = fmaf(acc[mtl][nt][2], 0.17677669529663687f, b1.x);
            float s3 = fmaf(acc[mtl][nt][3], 0.17677669529663687f, b1.y);
            acc[mtl][nt][0] = s0; acc[mtl][nt][1] = s1;
            acc[mtl][nt][2] = s2; acc[mtl][nt][3] = s3;
            mx0 = fmaxf(mx0, fmaxf(s0, s1));
            mx1 = fmaxf(mx1, fmaxf(s2, s3));
        }
        mx0 = fmaxf(mx0, __shfl_xor_sync(0xffffffffu, mx0, 1));
        mx0 = fmaxf(mx0, __shfl_xor_sync(0xffffffffu, mx0, 2));
        mx1 = fmaxf(mx1, __shfl_xor_sync(0xffffffffu, mx1, 1));
        mx1 = fmaxf(mx1, __shfl_xor_sync(0xffffffffu, mx1, 2));
        float sm0 = 0.f, sm1 = 0.f;
        #pragma unroll
        for (int nt = 0; nt < 14; nt++) {
            float e0 = __expf(acc[mtl][nt][0] - mx0);
            float e1 = __expf(acc[mtl][nt][1] - mx0);
            float e2 = __expf(acc[mtl][nt][2] - mx1);
            float e3 = __expf(acc[mtl][nt][3] - mx1);
            acc[mtl][nt][0] = e0; acc[mtl][nt][1] = e1;
            acc[mtl][nt][2] = e2; acc[mtl][nt][3] = e3;
            sm0 += e0 + e1; sm1 += e2 + e3;
        }
        sm0 += __shfl_xor_sync(0xffffffffu, sm0, 1);
        sm0 += __shfl_xor_sync(0xffffffffu, sm0, 2);
        sm1 += __shfl_xor_sync(0xffffffffu, sm1, 1);
        sm1 += __shfl_xor_sync(0xffffffffu, sm1, 2);
        inv0[mtl] = 1.0f / sm0;
        inv1[mtl] = 1.0f / sm1;
    }

    float av[2][4][4] = {};
    #pragma unroll
    for (int kt = 0; kt < 7; kt++) {
        uint32_t vfr[4][2];
        #pragma unroll
        for (int np = 0; np < 2; np++) {
            int krow = kt*16 + ((lane >> 3) & 1) * 8 + (lane & 7);
            int ncol = np*16 + (lane >> 4) * 8;
            uint32_t addr = uV + krow*QSTR + ncol*2;
            uint32_t r0, r1, r2, r3;
            LDMATRIX_X4T(r0, r1, r2, r3, addr);
            vfr[np*2][0] = r0; vfr[np*2][1] = r1;
            vfr[np*2+1][0] = r2; vfr[np*2+1][1] = r3;
        }
        for (int mtl = 0; mtl < nmt; mtl++) {
            uint32_t pa[4];
            pa[0] = pack2f(acc[mtl][2*kt][0],   acc[mtl][2*kt][1]);
            pa[1] = pack2f(acc[mtl][2*kt][2],   acc[mtl][2*kt][3]);
            pa[2] = pack2f(acc[mtl][2*kt+1][0], acc[mtl][2*kt+1][1]);
            pa[3] = pack2f(acc[mtl][2*kt+1][2], acc[mtl][2*kt+1][3]);
            #pragma unroll
            for (int nt = 0; nt < 4; nt++)
                MMA_BF16(av[mtl][nt], pa, vfr[nt]);
        }
    }

    for (int mtl = 0; mtl < nmt; mtl++) {
        int mt = wid + mtl*4;
        int r0 = mt*16 + (lane >> 2);
        int cb = head*HD + (lane & 3) * 2;
        #pragma unroll
        for (int nt = 0; nt < 4; nt++) {
            if (r0 < N_)
                *(uint32_t*)(g_att + ((size_t)(bw*N_ + r0))*256 + cb + nt*8)
                    = pack2f(av[mtl][nt][0]*inv0[mtl], av[mtl][nt][1]*inv0[mtl]);
            if (r0 + 8 < N_)
                *(uint32_t*)(g_att + ((size_t)(bw*N_ + r0 + 8))*256 + cb + nt*8)
                    = pack2f(av[mtl][nt][2]*inv1[mtl], av[mtl][nt][3]*inv1[mtl]);
        }
    }
}

// ---------------- host launcher ---------------------------------------------
extern "C" void kernel_launch(void* const* d_in, const int* in_sizes, int n_in,
                              void* d_out, int out_size) {
    const float* x     = (const float*)d_in[0];
    const float* n1w   = (const float*)d_in[1];
    const float* n1b   = (const float*)d_in[2];
    const float* qkvw  = (const float*)d_in[3];
    const float* qkvb  = (const float*)d_in[4];
    const float* projw = (const float*)d_in[5];
    const float* projb = (const float*)d_in[6];
    const float* rpe   = (const float*)d_in[7];
    const float* n2w   = (const float*)d_in[8];
    const float* n2b   = (const float*)d_in[9];
    const float* fc1w  = (const float*)d_in[10];
    const float* fc1b  = (const float*)d_in[11];
    const float* fc2w  = (const float*)d_in[12];
    const float* fc2b  = (const float*)d_in[13];
    float* out = (float*)d_out;

    __nv_bfloat16 *p_xw, *p_qkv, *p_att, *p_hn, *p_wqkv, *p_wproj, *p_wfc1, *p_wfc2;
    float *p_x2;
    cudaGetSymbolAddress((void**)&p_xw,  g_xw);
    cudaGetSymbolAddress((void**)&p_qkv, g_qkv);
    cudaGetSymbolAddress((void**)&p_att, g_att);
    cudaGetSymbolAddress((void**)&p_x2,  g_x2);
    cudaGetSymbolAddress((void**)&p_hn,  g_hn);
    cudaGetSymbolAddress((void**)&p_wqkv,  g_wqkv);
    cudaGetSymbolAddress((void**)&p_wproj, g_wproj);
    cudaGetSymbolAddress((void**)&p_wfc1,  g_wfc1);
    cudaGetSymbolAddress((void**)&p_wfc2,  g_wfc2);

    cudaFuncSetAttribute(attn_tc, cudaFuncAttributeMaxDynamicSharedMemorySize, ATTN_SMEM);
    cudaFuncSetAttribute(gemm_mma<0>, cudaFuncAttributeMaxDynamicSharedMemorySize, GEMM_SMEM);
    cudaFuncSetAttribute(gemm_mma<2>, cudaFuncAttributeMaxDynamicSharedMemorySize, GEMM_SMEM);
    cudaFuncSetAttribute(mlp_fused, cudaFuncAttributeMaxDynamicSharedMemorySize, MLP_SMEM);

    // fused setup (weights + bias/mask table)
    setup_kernel<<<(SETUP_ITEMS + 255)/256, 256>>>(qkvw, projw, fc1w, fc2w, rpe);

    // 1. LN1 + roll + window partition -> bf16
    ln_kernel<<<NTOK/8, 256>>>(x, p_xw, n1w, n1b, 0);
    // 2. QKV GEMM (K=256) -> bf16
    gemm_mma<0><<<dim3(6, 392), 256, GEMM_SMEM>>>(p_xw, p_wqkv, qkvb, nullptr, nullptr, p_qkv, 256);
    // 3. register-resident tensor-core attention
    attn_tc<<<BW_*HEADS, 128, ATTN_SMEM>>>();
    // 4. proj GEMM (K=256) + reverse/roll + residual
    gemm_mma<2><<<dim3(2, 392), 256, GEMM_SMEM>>>(p_att, p_wproj, projb, x, p_x2, nullptr, 256);
    // 5. LN2 -> bf16
    ln_kernel<<<NTOK/8, 256>>>(p_x2, p_hn, n2w, n2b, 1);
    // 6+7. fused MLP (fc1 + GELU + fc2 + residual) -> out
    mlp_fused<<<NTOK/64, 256, MLP_SMEM>>>(p_hn, p_wfc1, fc1b, p_wfc2, fc2b, p_x2, out);
}

// round 10
// speedup vs baseline: 1.1052x; 1.1052x over previous
#include <cuda_runtime.h>
#include <cuda_bf16.h>
#include <math.h>
#include <stdint.h>

// ---------------- problem constants ----------------
#define DIM   256
#define HEADS 8
#define HD    32
#define B_    2
#define T_    8
#define H_    56
#define W_    56
#define WT    2
#define WH    7
#define WW    7
#define STs   1
#define SHs   3
#define SWs   3
#define NTOK  (B_*T_*H_*W_)   // 50176 = 392*128
#define BW_   512
#define N_    98
#define HID   1024

// ---------------- scratch (device globals) ----------
__device__ __nv_bfloat16 g_xw [NTOK*256];
__device__ __nv_bfloat16 g_qkv[(size_t)NTOK*768];
__device__ __nv_bfloat16 g_att[NTOK*256];
__device__ float         g_x2 [NTOK*256];
__device__ __nv_bfloat16 g_hn [NTOK*256];
__device__ __nv_bfloat16 g_h3 [(size_t)NTOK*1024];
__device__ __nv_bfloat16 g_wqkv [768*256];
__device__ __nv_bfloat16 g_wproj[256*256];
__device__ __nv_bfloat16 g_wfc1 [1024*256];
__device__ __nv_bfloat16 g_wfc2 [256*1024];
__device__ __nv_bfloat16 g_bm[8*HEADS*112*112];   // bf16 bias+mask table

// ---------------- PTX helpers ----------------------
__device__ __forceinline__ uint32_t smem_u32(const void* p) {
    uint32_t a;
    asm("{ .reg .u64 t; cvta.to.shared.u64 t, %1; cvt.u32.u64 %0, t; }" : "=r"(a) : "l"(p));
    return a;
}
#define CP_ASYNC16(sm, gp) \
    asm volatile("cp.async.cg.shared.global [%0], [%1], 16;" :: "r"(sm), "l"(gp))
#define CP_COMMIT() asm volatile("cp.async.commit_group;" ::: "memory")
#define CP_WAIT0()  asm volatile("cp.async.wait_group 0;" ::: "memory")
#define CP_WAIT1()  asm volatile("cp.async.wait_group 1;" ::: "memory")

#define LDMATRIX_X4(r0,r1,r2,r3,addr) \
    asm volatile("ldmatrix.sync.aligned.m8n8.x4.shared.b16 {%0,%1,%2,%3}, [%4];" \
        : "=r"(r0), "=r"(r1), "=r"(r2), "=r"(r3) : "r"(addr))
#define LDMATRIX_X4T(r0,r1,r2,r3,addr) \
    asm volatile("ldmatrix.sync.aligned.m8n8.x4.trans.shared.b16 {%0,%1,%2,%3}, [%4];" \
        : "=r"(r0), "=r"(r1), "=r"(r2), "=r"(r3) : "r"(addr))
#define MMA_BF16(c, a, b) \
    asm volatile("mma.sync.aligned.m16n8k16.row.col.f32.bf16.bf16.f32 " \
        "{%0,%1,%2,%3}, {%4,%5,%6,%7}, {%8,%9}, {%0,%1,%2,%3};" \
        : "+f"((c)[0]), "+f"((c)[1]), "+f"((c)[2]), "+f"((c)[3]) \
        : "r"((a)[0]), "r"((a)[1]), "r"((a)[2]), "r"((a)[3]), "r"((b)[0]), "r"((b)[1]))

// ---------------- bf16 helpers ----------------
__device__ __forceinline__ uint32_t pack2(__nv_bfloat16 a, __nv_bfloat16 b) {
    return (uint32_t)__bfloat16_as_ushort(a) | ((uint32_t)__bfloat16_as_ushort(b) << 16);
}
__device__ __forceinline__ uint32_t pack2f(float a, float b) {
    return pack2(__float2bfloat16_rn(a), __float2bfloat16_rn(b));
}
__device__ __forceinline__ void plain_store4(__nv_bfloat16* rowp, int col,
                                             float a0, float a1, float a2, float a3) {
    uint2 u;
    u.x = pack2f(a0, a1);
    u.y = pack2f(a2, a3);
    *(uint2*)(rowp + col) = u;
}
__device__ __forceinline__ float2 bm2f(const __nv_bfloat16* p) {
    uint32_t u = *(const uint32_t*)p;
    __nv_bfloat162 t = *reinterpret_cast<__nv_bfloat162*>(&u);
    float2 r;
    r.x = __bfloat162float(t.x);
    r.y = __bfloat162float(t.y);
    return r;
}
__device__ __forceinline__ float gelu_f(float v) {
    return 0.5f * v * (1.0f + erff(v * 0.70710678118654752f));
}

// ---------------- fused setup: weight converts + bias/mask table -----------
#define NW_QKV (768*256)
#define NW_PROJ (256*256)
#define NW_FC1 (1024*256)
#define NW_FC2 (256*1024)
#define NBM    (8*112*112)
#define SETUP_ITEMS (NW_QKV + NW_PROJ + NW_FC1 + NW_FC2 + NBM)

__global__ void setup_kernel(const float* __restrict__ qkvw, const float* __restrict__ projw,
                             const float* __restrict__ fc1w, const float* __restrict__ fc2w,
                             const float* __restrict__ rpe) {
    int idx = blockIdx.x * 256 + threadIdx.x;
    if (idx >= SETUP_ITEMS) return;
    if (idx < NW_QKV) {
        g_wqkv[idx] = __float2bfloat16_rn(qkvw[idx]);
    } else if ((idx -= NW_QKV) < NW_PROJ) {
        g_wproj[idx] = __float2bfloat16_rn(projw[idx]);
    } else if ((idx -= NW_PROJ) < NW_FC1) {
        g_wfc1[idx] = __float2bfloat16_rn(fc1w[idx]);
    } else if ((idx -= NW_FC1) < NW_FC2) {
        g_wfc2[idx] = __float2bfloat16_rn(fc2w[idx]);
    } else {
        int i = idx - NW_FC2;
        int cat = i / (112*112);
        int rm = i % (112*112);
        int r = rm / 112, m = rm % 112;
        if (r < N_ && m < N_) {
            int ct = cat >> 2, ch = (cat >> 1) & 1, cw = cat & 1;
            int tr = r/49, hr = (r%49)/7, wr = r%7;
            int tm = m/49, hm = (m%49)/7, wm = m%7;
            int regr = (ct ? (tr==0?1:2) : 0)*9 + (ch ? (hr<4?1:2) : 0)*3 + (cw ? (wr<4?1:2) : 0);
            int regm = (ct ? (tm==0?1:2) : 0)*9 + (ch ? (hm<4?1:2) : 0)*3 + (cw ? (wm<4?1:2) : 0);
            int tix = (tr - tm + 1)*169 + (hr - hm + 6)*13 + (wr - wm + 6);
            float msk = (regr != regm) ? -100.0f : 0.0f;
            #pragma unroll
            for (int h = 0; h < HEADS; h++)
                g_bm[((cat*8 + h)*112 + r)*112 + m] = __float2bfloat16_rn(rpe[tix*HEADS + h] + msk);
        } else {
            float v = (m >= N_) ? -1e30f : 0.0f;
            #pragma unroll
            for (int h = 0; h < HEADS; h++)
                g_bm[((cat*8 + h)*112 + r)*112 + m] = __float2bfloat16_rn(v);
        }
    }
}

// ---------------- LN1 kernel (+roll+partition -> bf16 window layout) -------
__global__ void ln_kernel(const float* __restrict__ src, __nv_bfloat16* __restrict__ dst,
                          const float* __restrict__ w, const float* __restrict__ b) {
    int warp = threadIdx.x >> 5, lane = threadIdx.x & 31;
    int row = blockIdx.x * 8 + warp;
    const float* sr = src + (size_t)row * DIM;
    float4 v0 = *(const float4*)(sr + lane * 4);
    float4 v1 = *(const float4*)(sr + 128 + lane * 4);
    float s  = v0.x + v0.y + v0.z + v0.w + v1.x + v1.y + v1.z + v1.w;
    float ss = v0.x*v0.x + v0.y*v0.y + v0.z*v0.z + v0.w*v0.w
             + v1.x*v1.x + v1.y*v1.y + v1.z*v1.z + v1.w*v1.w;
    #pragma unroll
    for (int o = 16; o > 0; o >>= 1) {
        s  += __shfl_xor_sync(0xffffffffu, s, o);
        ss += __shfl_xor_sync(0xffffffffu, ss, o);
    }
    float mean = s * (1.0f / 256.0f);
    float var  = ss * (1.0f / 256.0f) - mean * mean;
    float inv  = rsqrtf(var + 1e-5f);
    int c0 = lane * 4, c1 = 128 + lane * 4;

    int bb = row / (T_*H_*W_);
    int r2 = row % (T_*H_*W_);
    int t = r2 / (H_*W_);
    int r3 = r2 % (H_*W_);
    int h = r3 / W_, ww_ = r3 % W_;
    int t2 = t - STs; if (t2 < 0) t2 += T_;
    int h2 = h - SHs; if (h2 < 0) h2 += H_;
    int w2 = ww_ - SWs; if (w2 < 0) w2 += W_;
    int tw = t2 / WT, hw = h2 / WH, wwn = w2 / WW;
    int n = (t2 % WT) * 49 + (h2 % WH) * 7 + (w2 % WW);
    int bw = ((bb * 4 + tw) * 8 + hw) * 8 + wwn;
    __nv_bfloat16* dr = dst + ((size_t)bw * N_ + n) * 256;
    plain_store4(dr, c0,
        (v0.x - mean) * inv * w[c0+0] + b[c0+0], (v0.y - mean) * inv * w[c0+1] + b[c0+1],
        (v0.z - mean) * inv * w[c0+2] + b[c0+2], (v0.w - mean) * inv * w[c0+3] + b[c0+3]);
    plain_store4(dr, c1,
        (v1.x - mean) * inv * w[c1+0] + b[c1+0], (v1.y - mean) * inv * w[c1+1] + b[c1+1],
        (v1.z - mean) * inv * w[c1+2] + b[c1+2], (v1.w - mean) * inv * w[c1+3] + b[c1+3]);
}

// ---------------- mma.sync GEMM: 128x256 block tile, 64x64 warp tiles -------
// EPI 0: +bias -> bf16 stride 768 (qkv)
// EPI 1: +bias,GELU -> bf16 stride 1024 (fc1)
// EPI 2: +bias, reverse+roll remap, +resid -> x2 fp32; fused LN2 -> hn bf16 (proj)
// EPI 3: +bias, +resid -> fp32 out (fc2)
#define ABUF 18432            // 128 rows x 144B
#define BBUF 36864            // 256 rows x 144B
#define STG  (ABUF + BBUF)    // 55296
#define GEMM_SMEM (3*STG)     // 165888

template<int EPI>
__global__ __launch_bounds__(256, 1) void gemm_mma(
        const __nv_bfloat16* __restrict__ A, const __nv_bfloat16* __restrict__ Wm,
        const float* __restrict__ bias, const float* __restrict__ resid,
        float* __restrict__ outF, __nv_bfloat16* __restrict__ outB,
        const float* __restrict__ lnw, const float* __restrict__ lnb, int K3) {
    extern __shared__ __align__(16) char smraw[];
    int tid = threadIdx.x, lane = tid & 31, wid = tid >> 5;
    int brow = blockIdx.y * 128, bcol = blockIdx.x * 256;
    int wm = wid & 1, wn = wid >> 1;
    uint32_t sb = smem_u32(smraw);

    float acc[4][8][4] = {};
    const int NC = K3 >> 6;

    const char* Agc = (const char*)(A  + (size_t)brow * K3);
    const char* Bgc = (const char*)(Wm + (size_t)bcol * K3);
    size_t rowstride = (size_t)K3 * 2;

    auto loadChunk = [&](int c, int buf) {
        uint32_t abase = sb + buf * STG;
        uint32_t bbase = abase + ABUF;
        const char* Ag = Agc + (size_t)c * 128;
        const char* Bg = Bgc + (size_t)c * 128;
        #pragma unroll
        for (int j = 0; j < 12; j++) {
            int x = tid + j * 256;           // 0..3071
            if (x < 1024) {
                int row = x >> 3, kc = x & 7;
                CP_ASYNC16(abase + row * 144 + kc * 16, Ag + (size_t)row * rowstride + kc * 16);
            } else {
                int y = x - 1024;
                int row = y >> 3, kc = y & 7;
                CP_ASYNC16(bbase + row * 144 + kc * 16, Bg + (size_t)row * rowstride + kc * 16);
            }
        }
        CP_COMMIT();
    };

    loadChunk(0, 0);
    if (NC > 1) loadChunk(1, 1);
    int bc = 0, bn2 = 2;
    for (int c = 0; c < NC; c++) {
        if (c + 1 < NC) CP_WAIT1(); else CP_WAIT0();
        __syncthreads();
        if (c + 2 < NC) loadChunk(c + 2, bn2);
        uint32_t abase = sb + bc * STG;
        uint32_t bbase = abase + ABUF;
        #pragma unroll
        for (int kh = 0; kh < 4; kh++) {
            uint32_t afr[4][4];
            #pragma unroll
            for (int mt = 0; mt < 4; mt++) {
                int row = wm * 64 + mt * 16 + ((lane >> 3) & 1) * 8 + (lane & 7);
                uint32_t addr = abase + row * 144 + kh * 32 + (lane >> 4) * 16;
                LDMATRIX_X4(afr[mt][0], afr[mt][1], afr[mt][2], afr[mt][3], addr);
            }
            uint32_t bfr[8][2];
            #pragma unroll
            for (int np = 0; np < 4; np++) {
                int nrow = wn * 64 + np * 16 + (lane >> 4) * 8 + (lane & 7);
                uint32_t addr = bbase + nrow * 144 + kh * 32 + ((lane >> 3) & 1) * 16;
                uint32_t r0, r1, r2, r3;
                LDMATRIX_X4(r0, r1, r2, r3, addr);
                bfr[np*2][0] = r0; bfr[np*2][1] = r1;
                bfr[np*2+1][0] = r2; bfr[np*2+1][1] = r3;
            }
            #pragma unroll
            for (int mt = 0; mt < 4; mt++)
                #pragma unroll
                for (int nt = 0; nt < 8; nt++)
                    MMA_BF16(acc[mt][nt], afr[mt], bfr[nt]);
        }
        bc++;  if (bc == 3)  bc = 0;
        bn2++; if (bn2 == 3) bn2 = 0;
    }
    __syncthreads();

    // ---- epilogue: stage fp32 (stride 264) -> full 256-col rows ----
    float* Cs = (float*)smraw;
    #pragma unroll
    for (int mt = 0; mt < 4; mt++)
        #pragma unroll
        for (int nt = 0; nt < 8; nt++) {
            int r0 = wm * 64 + mt * 16 + (lane >> 2);
            int cc = wn * 64 + nt * 8 + (lane & 3) * 2;
            Cs[r0 * 264 + cc]       = acc[mt][nt][0];
            Cs[r0 * 264 + cc + 1]   = acc[mt][nt][1];
            Cs[(r0+8) * 264 + cc]   = acc[mt][nt][2];
            Cs[(r0+8) * 264 + cc+1] = acc[mt][nt][3];
        }
    __syncthreads();

    int ca = lane * 4, cb2 = 128 + lane * 4;
    float4 bs0 = *(const float4*)(bias + bcol + ca);
    float4 bs1 = *(const float4*)(bias + bcol + cb2);
    float4 lw0, lw1, lb0, lb1;
    if (EPI == 2) {
        lw0 = *(const float4*)(lnw + ca); lw1 = *(const float4*)(lnw + cb2);
        lb0 = *(const float4*)(lnb + ca); lb1 = *(const float4*)(lnb + cb2);
    }
    for (int r = wid; r < 128; r += 8) {
        float4 v0 = *(const float4*)&Cs[r * 264 + ca];
        float4 v1 = *(const float4*)&Cs[r * 264 + cb2];
        v0.x += bs0.x; v0.y += bs0.y; v0.z += bs0.z; v0.w += bs0.w;
        v1.x += bs1.x; v1.y += bs1.y; v1.z += bs1.z; v1.w += bs1.w;
        int grow = brow + r;
        if (EPI == 0) {
            __nv_bfloat16* o = outB + (size_t)grow * 768 + bcol;
            plain_store4(o, ca,  v0.x, v0.y, v0.z, v0.w);
            plain_store4(o, cb2, v1.x, v1.y, v1.z, v1.w);
        } else if (EPI == 1) {
            __nv_bfloat16* o = outB + (size_t)grow * 1024 + bcol;
            plain_store4(o, ca,  gelu_f(v0.x), gelu_f(v0.y), gelu_f(v0.z), gelu_f(v0.w));
            plain_store4(o, cb2, gelu_f(v1.x), gelu_f(v1.y), gelu_f(v1.z), gelu_f(v1.w));
        } else if (EPI == 2) {
            // window reverse + roll-back remap
            int bw = grow / N_, n = grow % N_;
            int bb = bw >> 8, wrem = bw & 255;
            int tw = wrem >> 6, hw = (wrem >> 3) & 7, wwn = wrem & 7;
            int nt = n / 49, nr = n % 49;
            int t2 = tw*WT + nt, h2 = hw*WH + nr/7, w2 = wwn*WW + nr%7;
            int t = t2 + STs; if (t >= T_) t -= T_;
            int h = h2 + SHs; if (h >= H_) h -= H_;
            int ww_ = w2 + SWs; if (ww_ >= W_) ww_ -= W_;
            size_t orow = ((size_t)((bb*T_ + t)*H_ + h))*W_ + ww_;
            float4 r0 = *(const float4*)(resid + orow * 256 + ca);
            float4 r1 = *(const float4*)(resid + orow * 256 + cb2);
            v0.x += r0.x; v0.y += r0.y; v0.z += r0.z; v0.w += r0.w;
            v1.x += r1.x; v1.y += r1.y; v1.z += r1.z; v1.w += r1.w;
            *(float4*)(outF + orow * 256 + ca)  = v0;
            *(float4*)(outF + orow * 256 + cb2) = v1;
            // fused LN2 over the full 256-col row
            float s  = v0.x + v0.y + v0.z + v0.w + v1.x + v1.y + v1.z + v1.w;
            float ss = v0.x*v0.x + v0.y*v0.y + v0.z*v0.z + v0.w*v0.w
                     + v1.x*v1.x + v1.y*v1.y + v1.z*v1.z + v1.w*v1.w;
            #pragma unroll
            for (int o2 = 16; o2 > 0; o2 >>= 1) {
                s  += __shfl_xor_sync(0xffffffffu, s, o2);
                ss += __shfl_xor_sync(0xffffffffu, ss, o2);
            }
            float mean = s * (1.0f / 256.0f);
            float var  = ss * (1.0f / 256.0f) - mean * mean;
            float inv  = rsqrtf(var + 1e-5f);
            __nv_bfloat16* hnp = outB + orow * 256;
            plain_store4(hnp, ca,
                (v0.x - mean) * inv * lw0.x + lb0.x, (v0.y - mean) * inv * lw0.y + lb0.y,
                (v0.z - mean) * inv * lw0.z + lb0.z, (v0.w - mean) * inv * lw0.w + lb0.w);
            plain_store4(hnp, cb2,
                (v1.x - mean) * inv * lw1.x + lb1.x, (v1.y - mean) * inv * lw1.y + lb1.y,
                (v1.z - mean) * inv * lw1.z + lb1.z, (v1.w - mean) * inv * lw1.w + lb1.w);
        } else {
            float4 r0 = *(const float4*)(resid + (size_t)grow * 256 + ca);
            float4 r1 = *(const float4*)(resid + (size_t)grow * 256 + cb2);
            v0.x += r0.x; v0.y += r0.y; v0.z += r0.z; v0.w += r0.w;
            v1.x += r1.x; v1.y += r1.y; v1.z += r1.z; v1.w += r1.w;
            *(float4*)(outF + (size_t)grow * 256 + ca)  = v0;
            *(float4*)(outF + (size_t)grow * 256 + cb2) = v1;
        }
    }
}

// ---------------- register-resident tensor-core attention ------------------
#define QSTR 80
#define SM_Q  0
#define SM_K  (112*QSTR)
#define SM_V  (2*112*QSTR)
#define ATTN_SMEM (3*112*QSTR)

__global__ __launch_bounds__(128) void attn_tc() {
    extern __shared__ __align__(16) char asmem[];

    int tid = threadIdx.x, lane = tid & 31, wid = tid >> 5;
    int head = blockIdx.x & 7, bw = blockIdx.x >> 3;
    int wrem = bw & 255;
    int tw = wrem >> 6, hw = (wrem >> 3) & 7, wwn = wrem & 7;
    int cat = ((tw == 3) ? 4 : 0) | ((hw == 7) ? 2 : 0) | ((wwn == 7) ? 1 : 0);

    uint32_t uQ = smem_u32(asmem + SM_Q);
    uint32_t uK = smem_u32(asmem + SM_K);
    uint32_t uV = smem_u32(asmem + SM_V);

    if (tid < N_) {
        const uint4* g = (const uint4*)(g_qkv + ((size_t)(bw*N_ + tid)) * 768 + head * HD);
        #pragma unroll
        for (int j = 0; j < 4; j++) {
            *(uint4*)(asmem + SM_Q + tid*QSTR + j*16) = g[j];
            *(uint4*)(asmem + SM_K + tid*QSTR + j*16) = g[32 + j];
            *(uint4*)(asmem + SM_V + tid*QSTR + j*16) = g[64 + j];
        }
    } else if (tid < 112) {
        uint4 z = make_uint4(0,0,0,0);
        #pragma unroll
        for (int j = 0; j < 4; j++) {
            *(uint4*)(asmem + SM_Q + tid*QSTR + j*16) = z;
            *(uint4*)(asmem + SM_K + tid*QSTR + j*16) = z;
            *(uint4*)(asmem + SM_V + tid*QSTR + j*16) = z;
        }
    }
    __syncthreads();

    int nmt = (wid < 3) ? 2 : 1;
    float acc[2][14][4] = {};

    #pragma unroll
    for (int kh = 0; kh < 2; kh++) {
        uint32_t bfr[14][2];
        #pragma unroll
        for (int np = 0; np < 7; np++) {
            int nrow = np*16 + (lane >> 4) * 8 + (lane & 7);
            uint32_t addr = uK + nrow*QSTR + kh*32 + ((lane >> 3) & 1) * 16;
            uint32_t r0, r1, r2, r3;
            LDMATRIX_X4(r0, r1, r2, r3, addr);
            bfr[np*2][0] = r0; bfr[np*2][1] = r1;
            bfr[np*2+1][0] = r2; bfr[np*2+1][1] = r3;
        }
        for (int mtl = 0; mtl < nmt; mtl++) {
            int mt = wid + mtl*4;
            int row = mt*16 + ((lane >> 3) & 1) * 8 + (lane & 7);
            uint32_t addr = uQ + row*QSTR + kh*32 + (lane >> 4) * 16;
            uint32_t afr[4];
            LDMATRIX_X4(afr[0], afr[1], afr[2], afr[3], addr);
            #pragma unroll
            for (int nt = 0; nt < 14; nt++)
                MMA_BF16(acc[mtl][nt], afr, bfr[nt]);
        }
    }

    float inv0[2], inv1[2];
    for (int mtl = 0; mtl < nmt; mtl++) {
        int mt = wid + mtl*4;
        int row0 = mt*16 + (lane >> 2);
        const __nv_bfloat16* bm = g_bm + ((size_t)(cat*8 + head)*112 + row0)*112;
        int c0 = (lane & 3) * 2;
        float mx0 = -1e30f, mx1 = -1e30f;
        #pragma unroll
        for (int nt = 0; nt < 14; nt++) {
            float2 b0 = bm2f(bm + nt*8 + c0);
            float2 b1 = bm2f(bm + 8*112 + nt*8 + c0);
            float s0 = fmaf(acc[mtl][nt][0], 0.17677669529663687f, b0.x);
            float s1 = fmaf(acc[mtl][nt][1], 0.17677669529663687f, b0.y);
            float s2 = fmaf(acc[mtl][nt][2], 0.17677669529663687f, b1.x);
            float s3 = fmaf(acc[mtl][nt][3], 0.17677669529663687f, b1.y);
            acc[mtl][nt][0] = s0; acc[mtl][nt][1] = s1;
            acc[mtl][nt][2] = s2; acc[mtl][nt][3] = s3;
            mx0 = fmaxf(mx0, fmaxf(s0, s1));
            mx1 = fmaxf(mx1, fmaxf(s2, s3));
        }
        mx0 = fmaxf(mx0, __shfl_xor_sync(0xffffffffu, mx0, 1));
        mx0 = fmaxf(mx0, __shfl_xor_sync(0xffffffffu, mx0, 2));
        mx1 = fmaxf(mx1, __shfl_xor_sync(0xffffffffu, mx1, 1));
        mx1 = fmaxf(mx1, __shfl_xor_sync(0xffffffffu, mx1, 2));
        float sm0 = 0.f, sm1 = 0.f;
        #pragma unroll
        for (int nt = 0; nt < 14; nt++) {
            float e0 = __expf(acc[mtl][nt][0] - mx0);
            float e1 = __expf(acc[mtl][nt][1] - mx0);
            float e2 = __expf(acc[mtl][nt][2] - mx1);
            float e3 = __expf(acc[mtl][nt][3] - mx1);
            acc[mtl][nt][0] = e0; acc[mtl][nt][1] = e1;
            acc[mtl][nt][2] = e2; acc[mtl][nt][3] = e3;
            sm0 += e0 + e1; sm1 += e2 + e3;
        }
        sm0 += __shfl_xor_sync(0xffffffffu, sm0, 1);
        sm0 += __shfl_xor_sync(0xffffffffu, sm0, 2);
        sm1 += __shfl_xor_sync(0xffffffffu, sm1, 1);
        sm1 += __shfl_xor_sync(0xffffffffu, sm1, 2);
        inv0[mtl] = 1.0f / sm0;
        inv1[mtl] = 1.0f / sm1;
    }

    float av[2][4][4] = {};
    #pragma unroll
    for (int kt = 0; kt < 7; kt++) {
        uint32_t vfr[4][2];
        #pragma unroll
        for (int np = 0; np < 2; np++) {
            int krow = kt*16 + ((lane >> 3) & 1) * 8 + (lane & 7);
            int ncol = np*16 + (lane >> 4) * 8;
            uint32_t addr = uV + krow*QSTR + ncol*2;
            uint32_t r0, r1, r2, r3;
            LDMATRIX_X4T(r0, r1, r2, r3, addr);
            vfr[np*2][0] = r0; vfr[np*2][1] = r1;
            vfr[np*2+1][0] = r2; vfr[np*2+1][1] = r3;
        }
        for (int mtl = 0; mtl < nmt; mtl++) {
            uint32_t pa[4];
            pa[0] = pack2f(acc[mtl][2*kt][0],   acc[mtl][2*kt][1]);
            pa[1] = pack2f(acc[mtl][2*kt][2],   acc[mtl][2*kt][3]);
            pa[2] = pack2f(acc[mtl][2*kt+1][0], acc[mtl][2*kt+1][1]);
            pa[3] = pack2f(acc[mtl][2*kt+1][2], acc[mtl][2*kt+1][3]);
            #pragma unroll
            for (int nt = 0; nt < 4; nt++)
                MMA_BF16(av[mtl][nt], pa, vfr[nt]);
        }
    }

    for (int mtl = 0; mtl < nmt; mtl++) {
        int mt = wid + mtl*4;
        int r0 = mt*16 + (lane >> 2);
        int cb = head*HD + (lane & 3) * 2;
        #pragma unroll
        for (int nt = 0; nt < 4; nt++) {
            if (r0 < N_)
                *(uint32_t*)(g_att + ((size_t)(bw*N_ + r0))*256 + cb + nt*8)
                    = pack2f(av[mtl][nt][0]*inv0[mtl], av[mtl][nt][1]*inv0[mtl]);
            if (r0 + 8 < N_)
                *(uint32_t*)(g_att + ((size_t)(bw*N_ + r0 + 8))*256 + cb + nt*8)
                    = pack2f(av[mtl][nt][2]*inv1[mtl], av[mtl][nt][3]*inv1[mtl]);
        }
    }
}

// ---------------- host launcher ---------------------------------------------
extern "C" void kernel_launch(void* const* d_in, const int* in_sizes, int n_in,
                              void* d_out, int out_size) {
    const float* x     = (const float*)d_in[0];
    const float* n1w   = (const float*)d_in[1];
    const float* n1b   = (const float*)d_in[2];
    const float* qkvw  = (const float*)d_in[3];
    const float* qkvb  = (const float*)d_in[4];
    const float* projw = (const float*)d_in[5];
    const float* projb = (const float*)d_in[6];
    const float* rpe   = (const float*)d_in[7];
    const float* n2w   = (const float*)d_in[8];
    const float* n2b   = (const float*)d_in[9];
    const float* fc1w  = (const float*)d_in[10];
    const float* fc1b  = (const float*)d_in[11];
    const float* fc2w  = (const float*)d_in[12];
    const float* fc2b  = (const float*)d_in[13];
    float* out = (float*)d_out;

    __nv_bfloat16 *p_xw, *p_qkv, *p_att, *p_hn, *p_h3, *p_wqkv, *p_wproj, *p_wfc1, *p_wfc2;
    float *p_x2;
    cudaGetSymbolAddress((void**)&p_xw,  g_xw);
    cudaGetSymbolAddress((void**)&p_qkv, g_qkv);
    cudaGetSymbolAddress((void**)&p_att, g_att);
    cudaGetSymbolAddress((void**)&p_x2,  g_x2);
    cudaGetSymbolAddress((void**)&p_hn,  g_hn);
    cudaGetSymbolAddress((void**)&p_h3,  g_h3);
    cudaGetSymbolAddress((void**)&p_wqkv,  g_wqkv);
    cudaGetSymbolAddress((void**)&p_wproj, g_wproj);
    cudaGetSymbolAddress((void**)&p_wfc1,  g_wfc1);
    cudaGetSymbolAddress((void**)&p_wfc2,  g_wfc2);

    cudaFuncSetAttribute(attn_tc, cudaFuncAttributeMaxDynamicSharedMemorySize, ATTN_SMEM);
    cudaFuncSetAttribute(gemm_mma<0>, cudaFuncAttributeMaxDynamicSharedMemorySize, GEMM_SMEM);
    cudaFuncSetAttribute(gemm_mma<1>, cudaFuncAttributeMaxDynamicSharedMemorySize, GEMM_SMEM);
    cudaFuncSetAttribute(gemm_mma<2>, cudaFuncAttributeMaxDynamicSharedMemorySize, GEMM_SMEM);
    cudaFuncSetAttribute(gemm_mma<3>, cudaFuncAttributeMaxDynamicSharedMemorySize, GEMM_SMEM);

    // fused setup (weights + bias/mask table)
    setup_kernel<<<(SETUP_ITEMS + 255)/256, 256>>>(qkvw, projw, fc1w, fc2w, rpe);

    // 1. LN1 + roll + window partition -> bf16
    ln_kernel<<<NTOK/8, 256>>>(x, p_xw, n1w, n1b);
    // 2. QKV GEMM (K=256, N=768) -> bf16
    gemm_mma<0><<<dim3(3, 392), 256, GEMM_SMEM>>>(p_xw, p_wqkv, qkvb, nullptr, nullptr, p_qkv, nullptr, nullptr, 256);
    // 3. register-resident tensor-core attention
    attn_tc<<<BW_*HEADS, 128, ATTN_SMEM>>>();
    // 4. proj GEMM + reverse/roll + residual + fused LN2 -> x2 (fp32) + hn (bf16)
    gemm_mma<2><<<dim3(1, 392), 256, GEMM_SMEM>>>(p_att, p_wproj, projb, x, p_x2, p_hn, n2w, n2b, 256);
    // 5. fc1 GEMM (K=256, N=1024) + GELU -> bf16
    gemm_mma<1><<<dim3(4, 392), 256, GEMM_SMEM>>>(p_hn, p_wfc1, fc1b, nullptr, nullptr, p_h3, nullptr, nullptr, 256);
    // 6. fc2 GEMM (K=1024, N=256) + residual -> out
    gemm_mma<3><<<dim3(1, 392), 256, GEMM_SMEM>>>(p_h3, p_wfc2, fc2b, p_x2, out, nullptr, nullptr, nullptr, 1024);
}

// round 12
// speedup vs baseline: 1.1965x; 1.0826x over previous
#include <cuda_runtime.h>
#include <cuda_bf16.h>
#include <math.h>
#include <stdint.h>

// ---------------- problem constants ----------------
#define DIM   256
#define HEADS 8
#define HD    32
#define B_    2
#define T_    8
#define H_    56
#define W_    56
#define WT    2
#define WH    7
#define WW    7
#define STs   1
#define SHs   3
#define SWs   3
#define NTOK  (B_*T_*H_*W_)   // 50176 = 392*128
#define BW_   512
#define N_    98
#define HID   1024

// ---------------- scratch (device globals) ----------
__device__ __nv_bfloat16 g_xw [NTOK*256];
__device__ __nv_bfloat16 g_qkv[(size_t)NTOK*768];
__device__ __nv_bfloat16 g_att[NTOK*256];
__device__ float         g_x2 [NTOK*256];
__device__ __nv_bfloat16 g_hn [NTOK*256];
__device__ __nv_bfloat16 g_h3 [(size_t)NTOK*1024];
__device__ __nv_bfloat16 g_wqkv [768*256];
__device__ __nv_bfloat16 g_wproj[256*256];
__device__ __nv_bfloat16 g_wfc1 [1024*256];
__device__ __nv_bfloat16 g_wfc2 [256*1024];
__device__ __nv_bfloat16 g_bm[8*HEADS*112*112];   // bf16 bias+mask table

// ---------------- PTX helpers ----------------------
__device__ __forceinline__ uint32_t smem_u32(const void* p) {
    uint32_t a;
    asm("{ .reg .u64 t; cvta.to.shared.u64 t, %1; cvt.u32.u64 %0, t; }" : "=r"(a) : "l"(p));
    return a;
}
#define CP_ASYNC16(sm, gp) \
    asm volatile("cp.async.cg.shared.global [%0], [%1], 16;" :: "r"(sm), "l"(gp))
#define CP_COMMIT() asm volatile("cp.async.commit_group;" ::: "memory")
#define CP_WAIT0()  asm volatile("cp.async.wait_group 0;" ::: "memory")
#define CP_WAIT1()  asm volatile("cp.async.wait_group 1;" ::: "memory")

#define LDMATRIX_X4(r0,r1,r2,r3,addr) \
    asm volatile("ldmatrix.sync.aligned.m8n8.x4.shared.b16 {%0,%1,%2,%3}, [%4];" \
        : "=r"(r0), "=r"(r1), "=r"(r2), "=r"(r3) : "r"(addr))
#define LDMATRIX_X4T(r0,r1,r2,r3,addr) \
    asm volatile("ldmatrix.sync.aligned.m8n8.x4.trans.shared.b16 {%0,%1,%2,%3}, [%4];" \
        : "=r"(r0), "=r"(r1), "=r"(r2), "=r"(r3) : "r"(addr))
#define MMA_BF16(c, a, b) \
    asm volatile("mma.sync.aligned.m16n8k16.row.col.f32.bf16.bf16.f32 " \
        "{%0,%1,%2,%3}, {%4,%5,%6,%7}, {%8,%9}, {%0,%1,%2,%3};" \
        : "+f"((c)[0]), "+f"((c)[1]), "+f"((c)[2]), "+f"((c)[3]) \
        : "r"((a)[0]), "r"((a)[1]), "r"((a)[2]), "r"((a)[3]), "r"((b)[0]), "r"((b)[1]))

// ---------------- bf16 helpers ----------------
__device__ __forceinline__ uint32_t pack2(__nv_bfloat16 a, __nv_bfloat16 b) {
    return (uint32_t)__bfloat16_as_ushort(a) | ((uint32_t)__bfloat16_as_ushort(b) << 16);
}
__device__ __forceinline__ uint32_t pack2f(float a, float b) {
    return pack2(__float2bfloat16_rn(a), __float2bfloat16_rn(b));
}
__device__ __forceinline__ void plain_store4(__nv_bfloat16* rowp, int col,
                                             float a0, float a1, float a2, float a3) {
    uint2 u;
    u.x = pack2f(a0, a1);
    u.y = pack2f(a2, a3);
    *(uint2*)(rowp + col) = u;
}
__device__ __forceinline__ float2 bm2f(const __nv_bfloat16* p) {
    uint32_t u = *(const uint32_t*)p;
    __nv_bfloat162 t = *reinterpret_cast<__nv_bfloat162*>(&u);
    float2 r;
    r.x = __bfloat162float(t.x);
    r.y = __bfloat162float(t.y);
    return r;
}
__device__ __forceinline__ float gelu_f(float v) {
    return 0.5f * v * (1.0f + erff(v * 0.70710678118654752f));
}

// ---------------- fused setup: weight converts + bias/mask table -----------
#define NW_QKV (768*256)
#define NW_PROJ (256*256)
#define NW_FC1 (1024*256)
#define NW_FC2 (256*1024)
#define NBM    (8*112*112)
#define SETUP_ITEMS (NW_QKV + NW_PROJ + NW_FC1 + NW_FC2 + NBM)

__global__ void setup_kernel(const float* __restrict__ qkvw, const float* __restrict__ projw,
                             const float* __restrict__ fc1w, const float* __restrict__ fc2w,
                             const float* __restrict__ rpe) {
    int idx = blockIdx.x * 256 + threadIdx.x;
    if (idx >= SETUP_ITEMS) return;
    if (idx < NW_QKV) {
        g_wqkv[idx] = __float2bfloat16_rn(qkvw[idx]);
    } else if ((idx -= NW_QKV) < NW_PROJ) {
        g_wproj[idx] = __float2bfloat16_rn(projw[idx]);
    } else if ((idx -= NW_PROJ) < NW_FC1) {
        g_wfc1[idx] = __float2bfloat16_rn(fc1w[idx]);
    } else if ((idx -= NW_FC1) < NW_FC2) {
        g_wfc2[idx] = __float2bfloat16_rn(fc2w[idx]);
    } else {
        int i = idx - NW_FC2;
        int cat = i / (112*112);
        int rm = i % (112*112);
        int r = rm / 112, m = rm % 112;
        if (r < N_ && m < N_) {
            int ct = cat >> 2, ch = (cat >> 1) & 1, cw = cat & 1;
            int tr = r/49, hr = (r%49)/7, wr = r%7;
            int tm = m/49, hm = (m%49)/7, wm = m%7;
            int regr = (ct ? (tr==0?1:2) : 0)*9 + (ch ? (hr<4?1:2) : 0)*3 + (cw ? (wr<4?1:2) : 0);
            int regm = (ct ? (tm==0?1:2) : 0)*9 + (ch ? (hm<4?1:2) : 0)*3 + (cw ? (wm<4?1:2) : 0);
            int tix = (tr - tm + 1)*169 + (hr - hm + 6)*13 + (wr - wm + 6);
            float msk = (regr != regm) ? -100.0f : 0.0f;
            #pragma unroll
            for (int h = 0; h < HEADS; h++)
                g_bm[((cat*8 + h)*112 + r)*112 + m] = __float2bfloat16_rn(rpe[tix*HEADS + h] + msk);
        } else {
            float v = (m >= N_) ? -1e30f : 0.0f;
            #pragma unroll
            for (int h = 0; h < HEADS; h++)
                g_bm[((cat*8 + h)*112 + r)*112 + m] = __float2bfloat16_rn(v);
        }
    }
}

// ---------------- LN1 kernel (+roll+partition -> bf16 window layout) -------
__global__ void ln_kernel(const float* __restrict__ src, __nv_bfloat16* __restrict__ dst,
                          const float* __restrict__ w, const float* __restrict__ b) {
    int warp = threadIdx.x >> 5, lane = threadIdx.x & 31;
    int row = blockIdx.x * 8 + warp;
    const float* sr = src + (size_t)row * DIM;
    float4 v0 = *(const float4*)(sr + lane * 4);
    float4 v1 = *(const float4*)(sr + 128 + lane * 4);
    float s  = v0.x + v0.y + v0.z + v0.w + v1.x + v1.y + v1.z + v1.w;
    float ss = v0.x*v0.x + v0.y*v0.y + v0.z*v0.z + v0.w*v0.w
             + v1.x*v1.x + v1.y*v1.y + v1.z*v1.z + v1.w*v1.w;
    #pragma unroll
    for (int o = 16; o > 0; o >>= 1) {
        s  += __shfl_xor_sync(0xffffffffu, s, o);
        ss += __shfl_xor_sync(0xffffffffu, ss, o);
    }
    float mean = s * (1.0f / 256.0f);
    float var  = ss * (1.0f / 256.0f) - mean * mean;
    float inv  = rsqrtf(var + 1e-5f);
    int c0 = lane * 4, c1 = 128 + lane * 4;

    int bb = row / (T_*H_*W_);
    int r2 = row % (T_*H_*W_);
    int t = r2 / (H_*W_);
    int r3 = r2 % (H_*W_);
    int h = r3 / W_, ww_ = r3 % W_;
    int t2 = t - STs; if (t2 < 0) t2 += T_;
    int h2 = h - SHs; if (h2 < 0) h2 += H_;
    int w2 = ww_ - SWs; if (w2 < 0) w2 += W_;
    int tw = t2 / WT, hw = h2 / WH, wwn = w2 / WW;
    int n = (t2 % WT) * 49 + (h2 % WH) * 7 + (w2 % WW);
    int bw = ((bb * 4 + tw) * 8 + hw) * 8 + wwn;
    __nv_bfloat16* dr = dst + ((size_t)bw * N_ + n) * 256;
    plain_store4(dr, c0,
        (v0.x - mean) * inv * w[c0+0] + b[c0+0], (v0.y - mean) * inv * w[c0+1] + b[c0+1],
        (v0.z - mean) * inv * w[c0+2] + b[c0+2], (v0.w - mean) * inv * w[c0+3] + b[c0+3]);
    plain_store4(dr, c1,
        (v1.x - mean) * inv * w[c1+0] + b[c1+0], (v1.y - mean) * inv * w[c1+1] + b[c1+1],
        (v1.z - mean) * inv * w[c1+2] + b[c1+2], (v1.w - mean) * inv * w[c1+3] + b[c1+3]);
}

// ---------------- mma.sync GEMM 128x128, 3-stage, 2 CTA/SM (qkv/fc1/fc2) ----
// EPI 0: +bias -> bf16 stride 768 (qkv)
// EPI 1: +bias,GELU -> bf16 stride 1024 (fc1)
// EPI 3: +bias, +resid -> fp32 out (fc2)
#define ABUF 18432
#define BUFSZ (2*ABUF)
#define GEMM_SMEM (3*BUFSZ)   // 110592

template<int EPI>
__global__ __launch_bounds__(256) void gemm_mma(
        const __nv_bfloat16* __restrict__ A, const __nv_bfloat16* __restrict__ Wm,
        const float* __restrict__ bias, const float* __restrict__ resid,
        float* __restrict__ outF, __nv_bfloat16* __restrict__ outB, int K3) {
    extern __shared__ __align__(16) char smraw[];
    int tid = threadIdx.x, lane = tid & 31, wid = tid >> 5;
    int brow = blockIdx.y * 128, bcol = blockIdx.x * 128;
    int wm = wid & 1, wn = wid >> 1;
    uint32_t sb = smem_u32(smraw);

    float acc[4][4][4] = {};
    const int NC = K3 >> 6;

    const char* Agc = (const char*)(A  + (size_t)brow * K3);
    const char* Bgc = (const char*)(Wm + (size_t)bcol * K3);
    size_t rowstride = (size_t)K3 * 2;

    auto loadChunk = [&](int c, int buf) {
        uint32_t abase = sb + buf * BUFSZ;
        uint32_t bbase = abase + ABUF;
        const char* Ag = Agc + (size_t)c * 128;
        const char* Bg = Bgc + (size_t)c * 128;
        #pragma unroll
        for (int j = 0; j < 4; j++) {
            int x = tid + j * 256;
            int row = x >> 3, kc = x & 7;
            CP_ASYNC16(abase + row * 144 + kc * 16, Ag + (size_t)row * rowstride + kc * 16);
            CP_ASYNC16(bbase + row * 144 + kc * 16, Bg + (size_t)row * rowstride + kc * 16);
        }
        CP_COMMIT();
    };

    loadChunk(0, 0);
    if (NC > 1) loadChunk(1, 1);
    int bc = 0, bn2 = 2;
    for (int c = 0; c < NC; c++) {
        if (c + 1 < NC) CP_WAIT1(); else CP_WAIT0();
        __syncthreads();
        if (c + 2 < NC) loadChunk(c + 2, bn2);
        uint32_t abase = sb + bc * BUFSZ;
        uint32_t bbase = abase + ABUF;
        #pragma unroll
        for (int kh = 0; kh < 4; kh++) {
            uint32_t afr[4][4];
            #pragma unroll
            for (int mt = 0; mt < 4; mt++) {
                int row = wm * 64 + mt * 16 + ((lane >> 3) & 1) * 8 + (lane & 7);
                uint32_t addr = abase + row * 144 + kh * 32 + (lane >> 4) * 16;
                LDMATRIX_X4(afr[mt][0], afr[mt][1], afr[mt][2], afr[mt][3], addr);
            }
            uint32_t bfr[4][2];
            #pragma unroll
            for (int np = 0; np < 2; np++) {
                int nrow = wn * 32 + np * 16 + (lane >> 4) * 8 + (lane & 7);
                uint32_t addr = bbase + nrow * 144 + kh * 32 + ((lane >> 3) & 1) * 16;
                uint32_t r0, r1, r2, r3;
                LDMATRIX_X4(r0, r1, r2, r3, addr);
                bfr[np*2][0] = r0; bfr[np*2][1] = r1;
                bfr[np*2+1][0] = r2; bfr[np*2+1][1] = r3;
            }
            #pragma unroll
            for (int mt = 0; mt < 4; mt++)
                #pragma unroll
                for (int nt = 0; nt < 4; nt++)
                    MMA_BF16(acc[mt][nt], afr[mt], bfr[nt]);
        }
        bc++;  if (bc == 3)  bc = 0;
        bn2++; if (bn2 == 3) bn2 = 0;
    }
    __syncthreads();

    float* Cs = (float*)smraw;
    #pragma unroll
    for (int mt = 0; mt < 4; mt++)
        #pragma unroll
        for (int nt = 0; nt < 4; nt++) {
            int r0 = wm * 64 + mt * 16 + (lane >> 2);
            int cc = wn * 32 + nt * 8 + (lane & 3) * 2;
            Cs[r0 * 132 + cc]       = acc[mt][nt][0];
            Cs[r0 * 132 + cc + 1]   = acc[mt][nt][1];
            Cs[(r0+8) * 132 + cc]   = acc[mt][nt][2];
            Cs[(r0+8) * 132 + cc+1] = acc[mt][nt][3];
        }
    __syncthreads();

    float4 bs = *(const float4*)(bias + bcol + lane * 4);
    for (int r = wid; r < 128; r += 8) {
        float4 v = *(const float4*)&Cs[r * 132 + lane * 4];
        v.x += bs.x; v.y += bs.y; v.z += bs.z; v.w += bs.w;
        int grow = brow + r;
        int col = bcol + lane * 4;
        if (EPI == 0) {
            plain_store4(outB + (size_t)grow * 768, col, v.x, v.y, v.z, v.w);
        } else if (EPI == 1) {
            plain_store4(outB + (size_t)grow * 1024, col,
                         gelu_f(v.x), gelu_f(v.y), gelu_f(v.z), gelu_f(v.w));
        } else {
            float4 rr = *(const float4*)(resid + (size_t)grow * 256 + col);
            v.x += rr.x; v.y += rr.y; v.z += rr.z; v.w += rr.w;
            *(float4*)(outF + (size_t)grow * 256 + col) = v;
        }
    }
}

// ---------------- proj GEMM 128x256 + reverse/roll + residual + fused LN2 ---
#define PABUF 18432            // 128 rows x 144B
#define PBBUF 36864            // 256 rows x 144B
#define PSTG  (PABUF + PBBUF)  // 55296
#define PROJ_SMEM (3*PSTG)     // 165888

__global__ __launch_bounds__(256, 1) void gemm_proj(
        const __nv_bfloat16* __restrict__ A, const __nv_bfloat16* __restrict__ Wm,
        const float* __restrict__ bias, const float* __restrict__ resid,
        float* __restrict__ outF, __nv_bfloat16* __restrict__ outB,
        const float* __restrict__ lnw, const float* __restrict__ lnb) {
    extern __shared__ __align__(16) char smraw[];
    const int K3 = 256;
    int tid = threadIdx.x, lane = tid & 31, wid = tid >> 5;
    int brow = blockIdx.x * 128;
    int wm = wid & 1, wn = wid >> 1;
    uint32_t sb = smem_u32(smraw);

    float acc[4][8][4] = {};
    const int NC = 4;

    const char* Agc = (const char*)(A + (size_t)brow * K3);
    const char* Bgc = (const char*)Wm;
    size_t rowstride = (size_t)K3 * 2;

    auto loadChunk = [&](int c, int buf) {
        uint32_t abase = sb + buf * PSTG;
        uint32_t bbase = abase + PABUF;
        const char* Ag = Agc + (size_t)c * 128;
        const char* Bg = Bgc + (size_t)c * 128;
        #pragma unroll
        for (int j = 0; j < 12; j++) {
            int x = tid + j * 256;
            if (x < 1024) {
                int row = x >> 3, kc = x & 7;
                CP_ASYNC16(abase + row * 144 + kc * 16, Ag + (size_t)row * rowstride + kc * 16);
            } else {
                int y = x - 1024;
                int row = y >> 3, kc = y & 7;
                CP_ASYNC16(bbase + row * 144 + kc * 16, Bg + (size_t)row * rowstride + kc * 16);
            }
        }
        CP_COMMIT();
    };

    loadChunk(0, 0);
    loadChunk(1, 1);
    int bc = 0, bn2 = 2;
    for (int c = 0; c < NC; c++) {
        if (c + 1 < NC) CP_WAIT1(); else CP_WAIT0();
        __syncthreads();
        if (c + 2 < NC) loadChunk(c + 2, bn2);
        uint32_t abase = sb + bc * PSTG;
        uint32_t bbase = abase + PABUF;
        #pragma unroll
        for (int kh = 0; kh < 4; kh++) {
            uint32_t afr[4][4];
            #pragma unroll
            for (int mt = 0; mt < 4; mt++) {
                int row = wm * 64 + mt * 16 + ((lane >> 3) & 1) * 8 + (lane & 7);
                uint32_t addr = abase + row * 144 + kh * 32 + (lane >> 4) * 16;
                LDMATRIX_X4(afr[mt][0], afr[mt][1], afr[mt][2], afr[mt][3], addr);
            }
            uint32_t bfr[8][2];
            #pragma unroll
            for (int np = 0; np < 4; np++) {
                int nrow = wn * 64 + np * 16 + (lane >> 4) * 8 + (lane & 7);
                uint32_t addr = bbase + nrow * 144 + kh * 32 + ((lane >> 3) & 1) * 16;
                uint32_t r0, r1, r2, r3;
                LDMATRIX_X4(r0, r1, r2, r3, addr);
                bfr[np*2][0] = r0; bfr[np*2][1] = r1;
                bfr[np*2+1][0] = r2; bfr[np*2+1][1] = r3;
            }
            #pragma unroll
            for (int mt = 0; mt < 4; mt++)
                #pragma unroll
                for (int nt = 0; nt < 8; nt++)
                    MMA_BF16(acc[mt][nt], afr[mt], bfr[nt]);
        }
        bc++;  if (bc == 3)  bc = 0;
        bn2++; if (bn2 == 3) bn2 = 0;
    }
    __syncthreads();

    float* Cs = (float*)smraw;
    #pragma unroll
    for (int mt = 0; mt < 4; mt++)
        #pragma unroll
        for (int nt = 0; nt < 8; nt++) {
            int r0 = wm * 64 + mt * 16 + (lane >> 2);
            int cc = wn * 64 + nt * 8 + (lane & 3) * 2;
            Cs[r0 * 264 + cc]       = acc[mt][nt][0];
            Cs[r0 * 264 + cc + 1]   = acc[mt][nt][1];
            Cs[(r0+8) * 264 + cc]   = acc[mt][nt][2];
            Cs[(r0+8) * 264 + cc+1] = acc[mt][nt][3];
        }
    __syncthreads();

    int ca = lane * 4, cb2 = 128 + lane * 4;
    float4 bs0 = *(const float4*)(bias + ca);
    float4 bs1 = *(const float4*)(bias + cb2);
    float4 lw0 = *(const float4*)(lnw + ca), lw1 = *(const float4*)(lnw + cb2);
    float4 lb0 = *(const float4*)(lnb + ca), lb1 = *(const float4*)(lnb + cb2);
    for (int r = wid; r < 128; r += 8) {
        float4 v0 = *(const float4*)&Cs[r * 264 + ca];
        float4 v1 = *(const float4*)&Cs[r * 264 + cb2];
        v0.x += bs0.x; v0.y += bs0.y; v0.z += bs0.z; v0.w += bs0.w;
        v1.x += bs1.x; v1.y += bs1.y; v1.z += bs1.z; v1.w += bs1.w;
        int grow = brow + r;
        int bw = grow / N_, n = grow % N_;
        int bb = bw >> 8, wrem = bw & 255;
        int tw = wrem >> 6, hw = (wrem >> 3) & 7, wwn = wrem & 7;
        int nt = n / 49, nr = n % 49;
        int t2 = tw*WT + nt, h2 = hw*WH + nr/7, w2 = wwn*WW + nr%7;
        int t = t2 + STs; if (t >= T_) t -= T_;
        int h = h2 + SHs; if (h >= H_) h -= H_;
        int ww_ = w2 + SWs; if (ww_ >= W_) ww_ -= W_;
        size_t orow = ((size_t)((bb*T_ + t)*H_ + h))*W_ + ww_;
        float4 r0 = *(const float4*)(resid + orow * 256 + ca);
        float4 r1 = *(const float4*)(resid + orow * 256 + cb2);
        v0.x += r0.x; v0.y += r0.y; v0.z += r0.z; v0.w += r0.w;
        v1.x += r1.x; v1.y += r1.y; v1.z += r1.z; v1.w += r1.w;
        *(float4*)(outF + orow * 256 + ca)  = v0;
        *(float4*)(outF + orow * 256 + cb2) = v1;
        // fused LN2
        float s  = v0.x + v0.y + v0.z + v0.w + v1.x + v1.y + v1.z + v1.w;
        float ss = v0.x*v0.x + v0.y*v0.y + v0.z*v0.z + v0.w*v0.w
                 + v1.x*v1.x + v1.y*v1.y + v1.z*v1.z + v1.w*v1.w;
        #pragma unroll
        for (int o2 = 16; o2 > 0; o2 >>= 1) {
            s  += __shfl_xor_sync(0xffffffffu, s, o2);
            ss += __shfl_xor_sync(0xffffffffu, ss, o2);
        }
        float mean = s * (1.0f / 256.0f);
        float var  = ss * (1.0f / 256.0f) - mean * mean;
        float inv  = rsqrtf(var + 1e-5f);
        __nv_bfloat16* hnp = outB + orow * 256;
        plain_store4(hnp, ca,
            (v0.x - mean) * inv * lw0.x + lb0.x, (v0.y - mean) * inv * lw0.y + lb0.y,
            (v0.z - mean) * inv * lw0.z + lb0.z, (v0.w - mean) * inv * lw0.w + lb0.w);
        plain_store4(hnp, cb2,
            (v1.x - mean) * inv * lw1.x + lb1.x, (v1.y - mean) * inv * lw1.y + lb1.y,
            (v1.z - mean) * inv * lw1.z + lb1.z, (v1.w - mean) * inv * lw1.w + lb1.w);
    }
}

// ---------------- register-resident tensor-core attention ------------------
#define QSTR 80
#define SM_Q  0
#define SM_K  (112*QSTR)
#define SM_V  (2*112*QSTR)
#define ATTN_SMEM (3*112*QSTR)

__global__ __launch_bounds__(128) void attn_tc() {
    extern __shared__ __align__(16) char asmem[];

    int tid = threadIdx.x, lane = tid & 31, wid = tid >> 5;
    int head = blockIdx.x & 7, bw = blockIdx.x >> 3;
    int wrem = bw & 255;
    int tw = wrem >> 6, hw = (wrem >> 3) & 7, wwn = wrem & 7;
    int cat = ((tw == 3) ? 4 : 0) | ((hw == 7) ? 2 : 0) | ((wwn == 7) ? 1 : 0);

    uint32_t uQ = smem_u32(asmem + SM_Q);
    uint32_t uK = smem_u32(asmem + SM_K);
    uint32_t uV = smem_u32(asmem + SM_V);

    if (tid < N_) {
        const uint4* g = (const uint4*)(g_qkv + ((size_t)(bw*N_ + tid)) * 768 + head * HD);
        #pragma unroll
        for (int j = 0; j < 4; j++) {
            *(uint4*)(asmem + SM_Q + tid*QSTR + j*16) = g[j];
            *(uint4*)(asmem + SM_K + tid*QSTR + j*16) = g[32 + j];
            *(uint4*)(asmem + SM_V + tid*QSTR + j*16) = g[64 + j];
        }
    } else if (tid < 112) {
        uint4 z = make_uint4(0,0,0,0);
        #pragma unroll
        for (int j = 0; j < 4; j++) {
            *(uint4*)(asmem + SM_Q + tid*QSTR + j*16) = z;
            *(uint4*)(asmem + SM_K + tid*QSTR + j*16) = z;
            *(uint4*)(asmem + SM_V + tid*QSTR + j*16) = z;
        }
    }
    __syncthreads();

    int nmt = (wid < 3) ? 2 : 1;
    float acc[2][14][4] = {};

    #pragma unroll
    for (int kh = 0; kh < 2; kh++) {
        uint32_t bfr[14][2];
        #pragma unroll
        for (int np = 0; np < 7; np++) {
            int nrow = np*16 + (lane >> 4) * 8 + (lane & 7);
            uint32_t addr = uK + nrow*QSTR + kh*32 + ((lane >> 3) & 1) * 16;
            uint32_t r0, r1, r2, r3;
            LDMATRIX_X4(r0, r1, r2, r3, addr);
            bfr[np*2][0] = r0; bfr[np*2][1] = r1;
            bfr[np*2+1][0] = r2; bfr[np*2+1][1] = r3;
        }
        for (int mtl = 0; mtl < nmt; mtl++) {
            int mt = wid + mtl*4;
            int row = mt*16 + ((lane >> 3) & 1) * 8 + (lane & 7);
            uint32_t addr = uQ + row*QSTR + kh*32 + (lane >> 4) * 16;
            uint32_t afr[4];
            LDMATRIX_X4(afr[0], afr[1], afr[2], afr[3], addr);
            #pragma unroll
            for (int nt = 0; nt < 14; nt++)
                MMA_BF16(acc[mtl][nt], afr, bfr[nt]);
        }
    }

    float inv0[2], inv1[2];
    for (int mtl = 0; mtl < nmt; mtl++) {
        int mt = wid + mtl*4;
        int row0 = mt*16 + (lane >> 2);
        const __nv_bfloat16* bm = g_bm + ((size_t)(cat*8 + head)*112 + row0)*112;
        int c0 = (lane & 3) * 2;
        float mx0 = -1e30f, mx1 = -1e30f;
        #pragma unroll
        for (int nt = 0; nt < 14; nt++) {
            float2 b0 = bm2f(bm + nt*8 + c0);
            float2 b1 = bm2f(bm + 8*112 + nt*8 + c0);
            float s0 = fmaf(acc[mtl][nt][0], 0.17677669529663687f, b0.x);
            float s1 = fmaf(acc[mtl][nt][1], 0.17677669529663687f, b0.y);
            float s2 = fmaf(acc[mtl][nt][2], 0.17677669529663687f, b1.x);
            float s3 = fmaf(acc[mtl][nt][3], 0.17677669529663687f, b1.y);
            acc[mtl][nt][0] = s0; acc[mtl][nt][1] = s1;
            acc[mtl][nt][2] = s2; acc[mtl][nt][3] = s3;
            mx0 = fmaxf(mx0, fmaxf(s0, s1));
            mx1 = fmaxf(mx1, fmaxf(s2, s3));
        }
        mx0 = fmaxf(mx0, __shfl_xor_sync(0xffffffffu, mx0, 1));
        mx0 = fmaxf(mx0, __shfl_xor_sync(0xffffffffu, mx0, 2));
        mx1 = fmaxf(mx1, __shfl_xor_sync(0xffffffffu, mx1, 1));
        mx1 = fmaxf(mx1, __shfl_xor_sync(0xffffffffu, mx1, 2));
        float sm0 = 0.f, sm1 = 0.f;
        #pragma unroll
        for (int nt = 0; nt < 14; nt++) {
            float e0 = __expf(acc[mtl][nt][0] - mx0);
            float e1 = __expf(acc[mtl][nt][1] - mx0);
            float e2 = __expf(acc[mtl][nt][2] - mx1);
            float e3 = __expf(acc[mtl][nt][3] - mx1);
            acc[mtl][nt][0] = e0; acc[mtl][nt][1] = e1;
            acc[mtl][nt][2] = e2; acc[mtl][nt][3] = e3;
            sm0 += e0 + e1; sm1 += e2 + e3;
        }
        sm0 += __shfl_xor_sync(0xffffffffu, sm0, 1);
        sm0 += __shfl_xor_sync(0xffffffffu, sm0, 2);
        sm1 += __shfl_xor_sync(0xffffffffu, sm1, 1);
        sm1 += __shfl_xor_sync(0xffffffffu, sm1, 2);
        inv0[mtl] = 1.0f / sm0;
        inv1[mtl] = 1.0f / sm1;
    }

    float av[2][4][4] = {};
    #pragma unroll
    for (int kt = 0; kt < 7; kt++) {
        uint32_t vfr[4][2];
        #pragma unroll
        for (int np = 0; np < 2; np++) {
            int krow = kt*16 + ((lane >> 3) & 1) * 8 + (lane & 7);
            int ncol = np*16 + (lane >> 4) * 8;
            uint32_t addr = uV + krow*QSTR + ncol*2;
            uint32_t r0, r1, r2, r3;
            LDMATRIX_X4T(r0, r1, r2, r3, addr);
            vfr[np*2][0] = r0; vfr[np*2][1] = r1;
            vfr[np*2+1][0] = r2; vfr[np*2+1][1] = r3;
        }
        for (int mtl = 0; mtl < nmt; mtl++) {
            uint32_t pa[4];
            pa[0] = pack2f(acc[mtl][2*kt][0],   acc[mtl][2*kt][1]);
            pa[1] = pack2f(acc[mtl][2*kt][2],   acc[mtl][2*kt][3]);
            pa[2] = pack2f(acc[mtl][2*kt+1][0], acc[mtl][2*kt+1][1]);
            pa[3] = pack2f(acc[mtl][2*kt+1][2], acc[mtl][2*kt+1][3]);
            #pragma unroll
            for (int nt = 0; nt < 4; nt++)
                MMA_BF16(av[mtl][nt], pa, vfr[nt]);
        }
    }

    for (int mtl = 0; mtl < nmt; mtl++) {
        int mt = wid + mtl*4;
        int r0 = mt*16 + (lane >> 2);
        int cb = head*HD + (lane & 3) * 2;
        #pragma unroll
        for (int nt = 0; nt < 4; nt++) {
            if (r0 < N_)
                *(uint32_t*)(g_att + ((size_t)(bw*N_ + r0))*256 + cb + nt*8)
                    = pack2f(av[mtl][nt][0]*inv0[mtl], av[mtl][nt][1]*inv0[mtl]);
            if (r0 + 8 < N_)
                *(uint32_t*)(g_att + ((size_t)(bw*N_ + r0 + 8))*256 + cb + nt*8)
                    = pack2f(av[mtl][nt][2]*inv1[mtl], av[mtl][nt][3]*inv1[mtl]);
        }
    }
}

// ---------------- host launcher ---------------------------------------------
extern "C" void kernel_launch(void* const* d_in, const int* in_sizes, int n_in,
                              void* d_out, int out_size) {
    const float* x     = (const float*)d_in[0];
    const float* n1w   = (const float*)d_in[1];
    const float* n1b   = (const float*)d_in[2];
    const float* qkvw  = (const float*)d_in[3];
    const float* qkvb  = (const float*)d_in[4];
    const float* projw = (const float*)d_in[5];
    const float* projb = (const float*)d_in[6];
    const float* rpe   = (const float*)d_in[7];
    const float* n2w   = (const float*)d_in[8];
    const float* n2b   = (const float*)d_in[9];
    const float* fc1w  = (const float*)d_in[10];
    const float* fc1b  = (const float*)d_in[11];
    const float* fc2w  = (const float*)d_in[12];
    const float* fc2b  = (const float*)d_in[13];
    float* out = (float*)d_out;

    __nv_bfloat16 *p_xw, *p_qkv, *p_att, *p_hn, *p_h3, *p_wqkv, *p_wproj, *p_wfc1, *p_wfc2;
    float *p_x2;
    cudaGetSymbolAddress((void**)&p_xw,  g_xw);
    cudaGetSymbolAddress((void**)&p_qkv, g_qkv);
    cudaGetSymbolAddress((void**)&p_att, g_att);
    cudaGetSymbolAddress((void**)&p_x2,  g_x2);
    cudaGetSymbolAddress((void**)&p_hn,  g_hn);
    cudaGetSymbolAddress((void**)&p_h3,  g_h3);
    cudaGetSymbolAddress((void**)&p_wqkv,  g_wqkv);
    cudaGetSymbolAddress((void**)&p_wproj, g_wproj);
    cudaGetSymbolAddress((void**)&p_wfc1,  g_wfc1);
    cudaGetSymbolAddress((void**)&p_wfc2,  g_wfc2);

    cudaFuncSetAttribute(attn_tc, cudaFuncAttributeMaxDynamicSharedMemorySize, ATTN_SMEM);
    cudaFuncSetAttribute(gemm_mma<0>, cudaFuncAttributeMaxDynamicSharedMemorySize, GEMM_SMEM);
    cudaFuncSetAttribute(gemm_mma<1>, cudaFuncAttributeMaxDynamicSharedMemorySize, GEMM_SMEM);
    cudaFuncSetAttribute(gemm_mma<3>, cudaFuncAttributeMaxDynamicSharedMemorySize, GEMM_SMEM);
    cudaFuncSetAttribute(gemm_proj, cudaFuncAttributeMaxDynamicSharedMemorySize, PROJ_SMEM);

    // fused setup (weights + bias/mask table)
    setup_kernel<<<(SETUP_ITEMS + 255)/256, 256>>>(qkvw, projw, fc1w, fc2w, rpe);

    // 1. LN1 + roll + window partition -> bf16
    ln_kernel<<<NTOK/8, 256>>>(x, p_xw, n1w, n1b);
    // 2. QKV GEMM (128x128 tile, K=256, N=768) -> bf16
    gemm_mma<0><<<dim3(6, 392), 256, GEMM_SMEM>>>(p_xw, p_wqkv, qkvb, nullptr, nullptr, p_qkv, 256);
    // 3. register-resident tensor-core attention
    attn_tc<<<BW_*HEADS, 128, ATTN_SMEM>>>();
    // 4. proj GEMM (128x256 tile) + reverse/roll + residual + fused LN2
    gemm_proj<<<392, 256, PROJ_SMEM>>>(p_att, p_wproj, projb, x, p_x2, p_hn, n2w, n2b);
    // 5. fc1 GEMM (128x128, K=256, N=1024) + GELU -> bf16
    gemm_mma<1><<<dim3(8, 392), 256, GEMM_SMEM>>>(p_hn, p_wfc1, fc1b, nullptr, nullptr, p_h3, 256);
    // 6. fc2 GEMM (128x128, K=1024, N=256) + residual -> out
    gemm_mma<3><<<dim3(2, 392), 256, GEMM_SMEM>>>(p_h3, p_wfc2, fc2b, p_x2, out, nullptr, 1024);
}

// round 13
// speedup vs baseline: 1.2096x; 1.0109x over previous
#include <cuda_runtime.h>
#include <cuda_bf16.h>
#include <math.h>
#include <stdint.h>

// ---------------- problem constants ----------------
#define DIM   256
#define HEADS 8
#define HD    32
#define B_    2
#define T_    8
#define H_    56
#define W_    56
#define WT    2
#define WH    7
#define WW    7
#define STs   1
#define SHs   3
#define SWs   3
#define NTOK  (B_*T_*H_*W_)   // 50176 = 392*128
#define BW_   512
#define N_    98
#define HID   1024

// ---------------- scratch (device globals) ----------
__device__ __nv_bfloat16 g_xw [NTOK*256];
__device__ __nv_bfloat16 g_qkv[(size_t)NTOK*768];
__device__ __nv_bfloat16 g_att[NTOK*256];
__device__ float         g_x2 [NTOK*256];
__device__ __nv_bfloat16 g_hn [NTOK*256];
__device__ __nv_bfloat16 g_h3 [(size_t)NTOK*1024];
__device__ __nv_bfloat16 g_wqkv [768*256];
__device__ __nv_bfloat16 g_wproj[256*256];
__device__ __nv_bfloat16 g_wfc1 [1024*256];
__device__ __nv_bfloat16 g_wfc2 [256*1024];
__device__ __nv_bfloat16 g_bm[8*HEADS*112*112];   // bf16 bias+mask table

// ---------------- PTX helpers ----------------------
__device__ __forceinline__ uint32_t smem_u32(const void* p) {
    uint32_t a;
    asm("{ .reg .u64 t; cvta.to.shared.u64 t, %1; cvt.u32.u64 %0, t; }" : "=r"(a) : "l"(p));
    return a;
}
#define CP_ASYNC16(sm, gp) \
    asm volatile("cp.async.cg.shared.global [%0], [%1], 16;" :: "r"(sm), "l"(gp))
#define CP_COMMIT() asm volatile("cp.async.commit_group;" ::: "memory")
#define CP_WAIT0()  asm volatile("cp.async.wait_group 0;" ::: "memory")
#define CP_WAIT1()  asm volatile("cp.async.wait_group 1;" ::: "memory")

#define LDMATRIX_X4(r0,r1,r2,r3,addr) \
    asm volatile("ldmatrix.sync.aligned.m8n8.x4.shared.b16 {%0,%1,%2,%3}, [%4];" \
        : "=r"(r0), "=r"(r1), "=r"(r2), "=r"(r3) : "r"(addr))
#define LDMATRIX_X4T(r0,r1,r2,r3,addr) \
    asm volatile("ldmatrix.sync.aligned.m8n8.x4.trans.shared.b16 {%0,%1,%2,%3}, [%4];" \
        : "=r"(r0), "=r"(r1), "=r"(r2), "=r"(r3) : "r"(addr))
#define MMA_BF16(c, a, b) \
    asm volatile("mma.sync.aligned.m16n8k16.row.col.f32.bf16.bf16.f32 " \
        "{%0,%1,%2,%3}, {%4,%5,%6,%7}, {%8,%9}, {%0,%1,%2,%3};" \
        : "+f"((c)[0]), "+f"((c)[1]), "+f"((c)[2]), "+f"((c)[3]) \
        : "r"((a)[0]), "r"((a)[1]), "r"((a)[2]), "r"((a)[3]), "r"((b)[0]), "r"((b)[1]))

// ---------------- bf16 helpers ----------------
__device__ __forceinline__ uint32_t pack2(__nv_bfloat16 a, __nv_bfloat16 b) {
    return (uint32_t)__bfloat16_as_ushort(a) | ((uint32_t)__bfloat16_as_ushort(b) << 16);
}
__device__ __forceinline__ uint32_t pack2f(float a, float b) {
    return pack2(__float2bfloat16_rn(a), __float2bfloat16_rn(b));
}
__device__ __forceinline__ void plain_store4(__nv_bfloat16* rowp, int col,
                                             float a0, float a1, float a2, float a3) {
    uint2 u;
    u.x = pack2f(a0, a1);
    u.y = pack2f(a2, a3);
    *(uint2*)(rowp + col) = u;
}
__device__ __forceinline__ float2 bm2f(const __nv_bfloat16* p) {
    uint32_t u = *(const uint32_t*)p;
    __nv_bfloat162 t = *reinterpret_cast<__nv_bfloat162*>(&u);
    float2 r;
    r.x = __bfloat162float(t.x);
    r.y = __bfloat162float(t.y);
    return r;
}
__device__ __forceinline__ float gelu_f(float v) {
    return 0.5f * v * (1.0f + erff(v * 0.70710678118654752f));
}

// ---------------- fused setup: weight converts + bias/mask table -----------
#define NW_QKV (768*256)
#define NW_PROJ (256*256)
#define NW_FC1 (1024*256)
#define NW_FC2 (256*1024)
#define NBM    (8*112*112)
#define SETUP_ITEMS (NW_QKV + NW_PROJ + NW_FC1 + NW_FC2 + NBM)

__global__ void setup_kernel(const float* __restrict__ qkvw, const float* __restrict__ projw,
                             const float* __restrict__ fc1w, const float* __restrict__ fc2w,
                             const float* __restrict__ rpe) {
    int idx = blockIdx.x * 256 + threadIdx.x;
    if (idx >= SETUP_ITEMS) return;
    if (idx < NW_QKV) {
        g_wqkv[idx] = __float2bfloat16_rn(qkvw[idx]);
    } else if ((idx -= NW_QKV) < NW_PROJ) {
        g_wproj[idx] = __float2bfloat16_rn(projw[idx]);
    } else if ((idx -= NW_PROJ) < NW_FC1) {
        g_wfc1[idx] = __float2bfloat16_rn(fc1w[idx]);
    } else if ((idx -= NW_FC1) < NW_FC2) {
        g_wfc2[idx] = __float2bfloat16_rn(fc2w[idx]);
    } else {
        int i = idx - NW_FC2;
        int cat = i / (112*112);
        int rm = i % (112*112);
        int r = rm / 112, m = rm % 112;
        if (r < N_ && m < N_) {
            int ct = cat >> 2, ch = (cat >> 1) & 1, cw = cat & 1;
            int tr = r/49, hr = (r%49)/7, wr = r%7;
            int tm = m/49, hm = (m%49)/7, wm = m%7;
            int regr = (ct ? (tr==0?1:2) : 0)*9 + (ch ? (hr<4?1:2) : 0)*3 + (cw ? (wr<4?1:2) : 0);
            int regm = (ct ? (tm==0?1:2) : 0)*9 + (ch ? (hm<4?1:2) : 0)*3 + (cw ? (wm<4?1:2) : 0);
            int tix = (tr - tm + 1)*169 + (hr - hm + 6)*13 + (wr - wm + 6);
            float msk = (regr != regm) ? -100.0f : 0.0f;
            #pragma unroll
            for (int h = 0; h < HEADS; h++)
                g_bm[((cat*8 + h)*112 + r)*112 + m] = __float2bfloat16_rn(rpe[tix*HEADS + h] + msk);
        } else {
            float v = (m >= N_) ? -1e30f : 0.0f;
            #pragma unroll
            for (int h = 0; h < HEADS; h++)
                g_bm[((cat*8 + h)*112 + r)*112 + m] = __float2bfloat16_rn(v);
        }
    }
}

// ---------------- LN1 kernel (+roll+partition -> bf16 window layout) -------
__global__ void ln_kernel(const float* __restrict__ src, __nv_bfloat16* __restrict__ dst,
                          const float* __restrict__ w, const float* __restrict__ b) {
    int warp = threadIdx.x >> 5, lane = threadIdx.x & 31;
    int row = blockIdx.x * 8 + warp;
    const float* sr = src + (size_t)row * DIM;
    float4 v0 = *(const float4*)(sr + lane * 4);
    float4 v1 = *(const float4*)(sr + 128 + lane * 4);
    float s  = v0.x + v0.y + v0.z + v0.w + v1.x + v1.y + v1.z + v1.w;
    float ss = v0.x*v0.x + v0.y*v0.y + v0.z*v0.z + v0.w*v0.w
             + v1.x*v1.x + v1.y*v1.y + v1.z*v1.z + v1.w*v1.w;
    #pragma unroll
    for (int o = 16; o > 0; o >>= 1) {
        s  += __shfl_xor_sync(0xffffffffu, s, o);
        ss += __shfl_xor_sync(0xffffffffu, ss, o);
    }
    float mean = s * (1.0f / 256.0f);
    float var  = ss * (1.0f / 256.0f) - mean * mean;
    float inv  = rsqrtf(var + 1e-5f);
    int c0 = lane * 4, c1 = 128 + lane * 4;

    int bb = row / (T_*H_*W_);
    int r2 = row % (T_*H_*W_);
    int t = r2 / (H_*W_);
    int r3 = r2 % (H_*W_);
    int h = r3 / W_, ww_ = r3 % W_;
    int t2 = t - STs; if (t2 < 0) t2 += T_;
    int h2 = h - SHs; if (h2 < 0) h2 += H_;
    int w2 = ww_ - SWs; if (w2 < 0) w2 += W_;
    int tw = t2 / WT, hw = h2 / WH, wwn = w2 / WW;
    int n = (t2 % WT) * 49 + (h2 % WH) * 7 + (w2 % WW);
    int bw = ((bb * 4 + tw) * 8 + hw) * 8 + wwn;
    __nv_bfloat16* dr = dst + ((size_t)bw * N_ + n) * 256;
    plain_store4(dr, c0,
        (v0.x - mean) * inv * w[c0+0] + b[c0+0], (v0.y - mean) * inv * w[c0+1] + b[c0+1],
        (v0.z - mean) * inv * w[c0+2] + b[c0+2], (v0.w - mean) * inv * w[c0+3] + b[c0+3]);
    plain_store4(dr, c1,
        (v1.x - mean) * inv * w[c1+0] + b[c1+0], (v1.y - mean) * inv * w[c1+1] + b[c1+1],
        (v1.z - mean) * inv * w[c1+2] + b[c1+2], (v1.w - mean) * inv * w[c1+3] + b[c1+3]);
}

// ---------------- mma.sync GEMM 128x128, 3-stage, 2 CTA/SM (qkv/fc1/fc2) ----
#define ABUF 18432
#define BUFSZ (2*ABUF)
#define GEMM_SMEM (3*BUFSZ)   // 110592

template<int EPI>
__global__ __launch_bounds__(256) void gemm_mma(
        const __nv_bfloat16* __restrict__ A, const __nv_bfloat16* __restrict__ Wm,
        const float* __restrict__ bias, const float* __restrict__ resid,
        float* __restrict__ outF, __nv_bfloat16* __restrict__ outB, int K3) {
    extern __shared__ __align__(16) char smraw[];
    int tid = threadIdx.x, lane = tid & 31, wid = tid >> 5;
    int brow = blockIdx.y * 128, bcol = blockIdx.x * 128;
    int wm = wid & 1, wn = wid >> 1;
    uint32_t sb = smem_u32(smraw);

    float acc[4][4][4] = {};
    const int NC = K3 >> 6;

    const char* Agc = (const char*)(A  + (size_t)brow * K3);
    const char* Bgc = (const char*)(Wm + (size_t)bcol * K3);
    size_t rowstride = (size_t)K3 * 2;

    auto loadChunk = [&](int c, int buf) {
        uint32_t abase = sb + buf * BUFSZ;
        uint32_t bbase = abase + ABUF;
        const char* Ag = Agc + (size_t)c * 128;
        const char* Bg = Bgc + (size_t)c * 128;
        #pragma unroll
        for (int j = 0; j < 4; j++) {
            int x = tid + j * 256;
            int row = x >> 3, kc = x & 7;
            CP_ASYNC16(abase + row * 144 + kc * 16, Ag + (size_t)row * rowstride + kc * 16);
            CP_ASYNC16(bbase + row * 144 + kc * 16, Bg + (size_t)row * rowstride + kc * 16);
        }
        CP_COMMIT();
    };

    loadChunk(0, 0);
    if (NC > 1) loadChunk(1, 1);
    int bc = 0, bn2 = 2;
    for (int c = 0; c < NC; c++) {
        if (c + 1 < NC) CP_WAIT1(); else CP_WAIT0();
        __syncthreads();
        if (c + 2 < NC) loadChunk(c + 2, bn2);
        uint32_t abase = sb + bc * BUFSZ;
        uint32_t bbase = abase + ABUF;
        #pragma unroll
        for (int kh = 0; kh < 4; kh++) {
            uint32_t afr[4][4];
            #pragma unroll
            for (int mt = 0; mt < 4; mt++) {
                int row = wm * 64 + mt * 16 + ((lane >> 3) & 1) * 8 + (lane & 7);
                uint32_t addr = abase + row * 144 + kh * 32 + (lane >> 4) * 16;
                LDMATRIX_X4(afr[mt][0], afr[mt][1], afr[mt][2], afr[mt][3], addr);
            }
            uint32_t bfr[4][2];
            #pragma unroll
            for (int np = 0; np < 2; np++) {
                int nrow = wn * 32 + np * 16 + (lane >> 4) * 8 + (lane & 7);
                uint32_t addr = bbase + nrow * 144 + kh * 32 + ((lane >> 3) & 1) * 16;
                uint32_t r0, r1, r2, r3;
                LDMATRIX_X4(r0, r1, r2, r3, addr);
                bfr[np*2][0] = r0; bfr[np*2][1] = r1;
                bfr[np*2+1][0] = r2; bfr[np*2+1][1] = r3;
            }
            #pragma unroll
            for (int mt = 0; mt < 4; mt++)
                #pragma unroll
                for (int nt = 0; nt < 4; nt++)
                    MMA_BF16(acc[mt][nt], afr[mt], bfr[nt]);
        }
        bc++;  if (bc == 3)  bc = 0;
        bn2++; if (bn2 == 3) bn2 = 0;
    }
    __syncthreads();

    float* Cs = (float*)smraw;
    #pragma unroll
    for (int mt = 0; mt < 4; mt++)
        #pragma unroll
        for (int nt = 0; nt < 4; nt++) {
            int r0 = wm * 64 + mt * 16 + (lane >> 2);
            int cc = wn * 32 + nt * 8 + (lane & 3) * 2;
            Cs[r0 * 132 + cc]       = acc[mt][nt][0];
            Cs[r0 * 132 + cc + 1]   = acc[mt][nt][1];
            Cs[(r0+8) * 132 + cc]   = acc[mt][nt][2];
            Cs[(r0+8) * 132 + cc+1] = acc[mt][nt][3];
        }
    __syncthreads();

    float4 bs = *(const float4*)(bias + bcol + lane * 4);
    for (int r = wid; r < 128; r += 8) {
        float4 v = *(const float4*)&Cs[r * 132 + lane * 4];
        v.x += bs.x; v.y += bs.y; v.z += bs.z; v.w += bs.w;
        int grow = brow + r;
        int col = bcol + lane * 4;
        if (EPI == 0) {
            plain_store4(outB + (size_t)grow * 768, col, v.x, v.y, v.z, v.w);
        } else if (EPI == 1) {
            plain_store4(outB + (size_t)grow * 1024, col,
                         gelu_f(v.x), gelu_f(v.y), gelu_f(v.z), gelu_f(v.w));
        } else {
            float4 rr = *(const float4*)(resid + (size_t)grow * 256 + col);
            v.x += rr.x; v.y += rr.y; v.z += rr.z; v.w += rr.w;
            *(float4*)(outF + (size_t)grow * 256 + col) = v;
        }
    }
}

// ---------------- proj GEMM 128x256 + reverse/roll + residual + fused LN2 ---
#define PABUF 18432
#define PBBUF 36864
#define PSTG  (PABUF + PBBUF)
#define PROJ_SMEM (3*PSTG)

__global__ __launch_bounds__(256, 1) void gemm_proj(
        const __nv_bfloat16* __restrict__ A, const __nv_bfloat16* __restrict__ Wm,
        const float* __restrict__ bias, const float* __restrict__ resid,
        float* __restrict__ outF, __nv_bfloat16* __restrict__ outB,
        const float* __restrict__ lnw, const float* __restrict__ lnb) {
    extern __shared__ __align__(16) char smraw[];
    const int K3 = 256;
    int tid = threadIdx.x, lane = tid & 31, wid = tid >> 5;
    int brow = blockIdx.x * 128;
    int wm = wid & 1, wn = wid >> 1;
    uint32_t sb = smem_u32(smraw);

    float acc[4][8][4] = {};
    const int NC = 4;

    const char* Agc = (const char*)(A + (size_t)brow * K3);
    const char* Bgc = (const char*)Wm;
    size_t rowstride = (size_t)K3 * 2;

    auto loadChunk = [&](int c, int buf) {
        uint32_t abase = sb + buf * PSTG;
        uint32_t bbase = abase + PABUF;
        const char* Ag = Agc + (size_t)c * 128;
        const char* Bg = Bgc + (size_t)c * 128;
        #pragma unroll
        for (int j = 0; j < 12; j++) {
            int x = tid + j * 256;
            if (x < 1024) {
                int row = x >> 3, kc = x & 7;
                CP_ASYNC16(abase + row * 144 + kc * 16, Ag + (size_t)row * rowstride + kc * 16);
            } else {
                int y = x - 1024;
                int row = y >> 3, kc = y & 7;
                CP_ASYNC16(bbase + row * 144 + kc * 16, Bg + (size_t)row * rowstride + kc * 16);
            }
        }
        CP_COMMIT();
    };

    loadChunk(0, 0);
    loadChunk(1, 1);
    int bc = 0, bn2 = 2;
    for (int c = 0; c < NC; c++) {
        if (c + 1 < NC) CP_WAIT1(); else CP_WAIT0();
        __syncthreads();
        if (c + 2 < NC) loadChunk(c + 2, bn2);
        uint32_t abase = sb + bc * PSTG;
        uint32_t bbase = abase + PABUF;
        #pragma unroll
        for (int kh = 0; kh < 4; kh++) {
            uint32_t afr[4][4];
            #pragma unroll
            for (int mt = 0; mt < 4; mt++) {
                int row = wm * 64 + mt * 16 + ((lane >> 3) & 1) * 8 + (lane & 7);
                uint32_t addr = abase + row * 144 + kh * 32 + (lane >> 4) * 16;
                LDMATRIX_X4(afr[mt][0], afr[mt][1], afr[mt][2], afr[mt][3], addr);
            }
            uint32_t bfr[8][2];
            #pragma unroll
            for (int np = 0; np < 4; np++) {
                int nrow = wn * 64 + np * 16 + (lane >> 4) * 8 + (lane & 7);
                uint32_t addr = bbase + nrow * 144 + kh * 32 + ((lane >> 3) & 1) * 16;
                uint32_t r0, r1, r2, r3;
                LDMATRIX_X4(r0, r1, r2, r3, addr);
                bfr[np*2][0] = r0; bfr[np*2][1] = r1;
                bfr[np*2+1][0] = r2; bfr[np*2+1][1] = r3;
            }
            #pragma unroll
            for (int mt = 0; mt < 4; mt++)
                #pragma unroll
                for (int nt = 0; nt < 8; nt++)
                    MMA_BF16(acc[mt][nt], afr[mt], bfr[nt]);
        }
        bc++;  if (bc == 3)  bc = 0;
        bn2++; if (bn2 == 3) bn2 = 0;
    }
    __syncthreads();

    float* Cs = (float*)smraw;
    #pragma unroll
    for (int mt = 0; mt < 4; mt++)
        #pragma unroll
        for (int nt = 0; nt < 8; nt++) {
            int r0 = wm * 64 + mt * 16 + (lane >> 2);
            int cc = wn * 64 + nt * 8 + (lane & 3) * 2;
            Cs[r0 * 264 + cc]       = acc[mt][nt][0];
            Cs[r0 * 264 + cc + 1]   = acc[mt][nt][1];
            Cs[(r0+8) * 264 + cc]   = acc[mt][nt][2];
            Cs[(r0+8) * 264 + cc+1] = acc[mt][nt][3];
        }
    __syncthreads();

    int ca = lane * 4, cb2 = 128 + lane * 4;
    float4 bs0 = *(const float4*)(bias + ca);
    float4 bs1 = *(const float4*)(bias + cb2);
    float4 lw0 = *(const float4*)(lnw + ca), lw1 = *(const float4*)(lnw + cb2);
    float4 lb0 = *(const float4*)(lnb + ca), lb1 = *(const float4*)(lnb + cb2);
    for (int r = wid; r < 128; r += 8) {
        float4 v0 = *(const float4*)&Cs[r * 264 + ca];
        float4 v1 = *(const float4*)&Cs[r * 264 + cb2];
        v0.x += bs0.x; v0.y += bs0.y; v0.z += bs0.z; v0.w += bs0.w;
        v1.x += bs1.x; v1.y += bs1.y; v1.z += bs1.z; v1.w += bs1.w;
        int grow = brow + r;
        int bw = grow / N_, n = grow % N_;
        int bb = bw >> 8, wrem = bw & 255;
        int tw = wrem >> 6, hw = (wrem >> 3) & 7, wwn = wrem & 7;
        int nt = n / 49, nr = n % 49;
        int t2 = tw*WT + nt, h2 = hw*WH + nr/7, w2 = wwn*WW + nr%7;
        int t = t2 + STs; if (t >= T_) t -= T_;
        int h = h2 + SHs; if (h >= H_) h -= H_;
        int ww_ = w2 + SWs; if (ww_ >= W_) ww_ -= W_;
        size_t orow = ((size_t)((bb*T_ + t)*H_ + h))*W_ + ww_;
        float4 r0 = *(const float4*)(resid + orow * 256 + ca);
        float4 r1 = *(const float4*)(resid + orow * 256 + cb2);
        v0.x += r0.x; v0.y += r0.y; v0.z += r0.z; v0.w += r0.w;
        v1.x += r1.x; v1.y += r1.y; v1.z += r1.z; v1.w += r1.w;
        *(float4*)(outF + orow * 256 + ca)  = v0;
        *(float4*)(outF + orow * 256 + cb2) = v1;
        // fused LN2
        float s  = v0.x + v0.y + v0.z + v0.w + v1.x + v1.y + v1.z + v1.w;
        float ss = v0.x*v0.x + v0.y*v0.y + v0.z*v0.z + v0.w*v0.w
                 + v1.x*v1.x + v1.y*v1.y + v1.z*v1.z + v1.w*v1.w;
        #pragma unroll
        for (int o2 = 16; o2 > 0; o2 >>= 1) {
            s  += __shfl_xor_sync(0xffffffffu, s, o2);
            ss += __shfl_xor_sync(0xffffffffu, ss, o2);
        }
        float mean = s * (1.0f / 256.0f);
        float var  = ss * (1.0f / 256.0f) - mean * mean;
        float inv  = rsqrtf(var + 1e-5f);
        __nv_bfloat16* hnp = outB + orow * 256;
        plain_store4(hnp, ca,
            (v0.x - mean) * inv * lw0.x + lb0.x, (v0.y - mean) * inv * lw0.y + lb0.y,
            (v0.z - mean) * inv * lw0.z + lb0.z, (v0.w - mean) * inv * lw0.w + lb0.w);
        plain_store4(hnp, cb2,
            (v1.x - mean) * inv * lw1.x + lb1.x, (v1.y - mean) * inv * lw1.y + lb1.y,
            (v1.z - mean) * inv * lw1.z + lb1.z, (v1.w - mean) * inv * lw1.w + lb1.w);
    }
}

// ---------------- register-resident attention: 7 warps, 1 m-tile/warp ------
#define QSTR 80
#define SM_Q  0
#define SM_K  (112*QSTR)
#define SM_V  (2*112*QSTR)
#define ATTN_SMEM (3*112*QSTR)

__global__ __launch_bounds__(224) void attn_tc() {
    extern __shared__ __align__(16) char asmem[];

    int tid = threadIdx.x, lane = tid & 31, wid = tid >> 5;   // wid 0..6
    int head = blockIdx.x & 7, bw = blockIdx.x >> 3;
    int wrem = bw & 255;
    int tw = wrem >> 6, hw = (wrem >> 3) & 7, wwn = wrem & 7;
    int cat = ((tw == 3) ? 4 : 0) | ((hw == 7) ? 2 : 0) | ((wwn == 7) ? 1 : 0);

    uint32_t uQ = smem_u32(asmem + SM_Q);
    uint32_t uK = smem_u32(asmem + SM_K);
    uint32_t uV = smem_u32(asmem + SM_V);

    if (tid < N_) {
        const uint4* g = (const uint4*)(g_qkv + ((size_t)(bw*N_ + tid)) * 768 + head * HD);
        #pragma unroll
        for (int j = 0; j < 4; j++) {
            *(uint4*)(asmem + SM_Q + tid*QSTR + j*16) = g[j];
            *(uint4*)(asmem + SM_K + tid*QSTR + j*16) = g[32 + j];
            *(uint4*)(asmem + SM_V + tid*QSTR + j*16) = g[64 + j];
        }
    } else if (tid < 112) {
        uint4 z = make_uint4(0,0,0,0);
        #pragma unroll
        for (int j = 0; j < 4; j++) {
            *(uint4*)(asmem + SM_Q + tid*QSTR + j*16) = z;
            *(uint4*)(asmem + SM_K + tid*QSTR + j*16) = z;
            *(uint4*)(asmem + SM_V + tid*QSTR + j*16) = z;
        }
    }
    __syncthreads();

    float acc[14][4] = {};

    // ---- QK^T: warp wid owns m-tile rows [16*wid, 16*wid+16) ----
    #pragma unroll
    for (int kh = 0; kh < 2; kh++) {
        uint32_t bfr[14][2];
        #pragma unroll
        for (int np = 0; np < 7; np++) {
            int nrow = np*16 + (lane >> 4) * 8 + (lane & 7);
            uint32_t addr = uK + nrow*QSTR + kh*32 + ((lane >> 3) & 1) * 16;
            uint32_t r0, r1, r2, r3;
            LDMATRIX_X4(r0, r1, r2, r3, addr);
            bfr[np*2][0] = r0; bfr[np*2][1] = r1;
            bfr[np*2+1][0] = r2; bfr[np*2+1][1] = r3;
        }
        int row = wid*16 + ((lane >> 3) & 1) * 8 + (lane & 7);
        uint32_t addr = uQ + row*QSTR + kh*32 + (lane >> 4) * 16;
        uint32_t afr[4];
        LDMATRIX_X4(afr[0], afr[1], afr[2], afr[3], addr);
        #pragma unroll
        for (int nt = 0; nt < 14; nt++)
            MMA_BF16(acc[nt], afr, bfr[nt]);
    }

    // ---- register softmax (bias+mask table; unnormalized exp) ----
    float inv0, inv1;
    {
        int row0 = wid*16 + (lane >> 2);
        const __nv_bfloat16* bm = g_bm + ((size_t)(cat*8 + head)*112 + row0)*112;
        int c0 = (lane & 3) * 2;
        float mx0 = -1e30f, mx1 = -1e30f;
        #pragma unroll
        for (int nt = 0; nt < 14; nt++) {
            float2 b0 = bm2f(bm + nt*8 + c0);
            float2 b1 = bm2f(bm + 8*112 + nt*8 + c0);
            float s0 = fmaf(acc[nt][0], 0.17677669529663687f, b0.x);
            float s1 = fmaf(acc[nt][1], 0.17677669529663687f, b0.y);
            float s2 = fmaf(acc[nt][2], 0.17677669529663687f, b1.x);
            float s3 = fmaf(acc[nt][3], 0.17677669529663687f, b1.y);
            acc[nt][0] = s0; acc[nt][1] = s1;
            acc[nt][2] = s2; acc[nt][3] = s3;
            mx0 = fmaxf(mx0, fmaxf(s0, s1));
            mx1 = fmaxf(mx1, fmaxf(s2, s3));
        }
        mx0 = fmaxf(mx0, __shfl_xor_sync(0xffffffffu, mx0, 1));
        mx0 = fmaxf(mx0, __shfl_xor_sync(0xffffffffu, mx0, 2));
        mx1 = fmaxf(mx1, __shfl_xor_sync(0xffffffffu, mx1, 1));
        mx1 = fmaxf(mx1, __shfl_xor_sync(0xffffffffu, mx1, 2));
        float sm0 = 0.f, sm1 = 0.f;
        #pragma unroll
        for (int nt = 0; nt < 14; nt++) {
            float e0 = __expf(acc[nt][0] - mx0);
            float e1 = __expf(acc[nt][1] - mx0);
            float e2 = __expf(acc[nt][2] - mx1);
            float e3 = __expf(acc[nt][3] - mx1);
            acc[nt][0] = e0; acc[nt][1] = e1;
            acc[nt][2] = e2; acc[nt][3] = e3;
            sm0 += e0 + e1; sm1 += e2 + e3;
        }
        sm0 += __shfl_xor_sync(0xffffffffu, sm0, 1);
        sm0 += __shfl_xor_sync(0xffffffffu, sm0, 2);
        sm1 += __shfl_xor_sync(0xffffffffu, sm1, 1);
        sm1 += __shfl_xor_sync(0xffffffffu, sm1, 2);
        inv0 = 1.0f / sm0;
        inv1 = 1.0f / sm1;
    }

    // ---- AV: P fragments straight from registers ----
    float av[4][4] = {};
    #pragma unroll
    for (int kt = 0; kt < 7; kt++) {
        uint32_t vfr[4][2];
        #pragma unroll
        for (int np = 0; np < 2; np++) {
            int krow = kt*16 + ((lane >> 3) & 1) * 8 + (lane & 7);
            int ncol = np*16 + (lane >> 4) * 8;
            uint32_t addr = uV + krow*QSTR + ncol*2;
            uint32_t r0, r1, r2, r3;
            LDMATRIX_X4T(r0, r1, r2, r3, addr);
            vfr[np*2][0] = r0; vfr[np*2][1] = r1;
            vfr[np*2+1][0] = r2; vfr[np*2+1][1] = r3;
        }
        uint32_t pa[4];
        pa[0] = pack2f(acc[2*kt][0],   acc[2*kt][1]);
        pa[1] = pack2f(acc[2*kt][2],   acc[2*kt][3]);
        pa[2] = pack2f(acc[2*kt+1][0], acc[2*kt+1][1]);
        pa[3] = pack2f(acc[2*kt+1][2], acc[2*kt+1][3]);
        #pragma unroll
        for (int nt = 0; nt < 4; nt++)
            MMA_BF16(av[nt], pa, vfr[nt]);
    }

    // ---- store (apply 1/sum here) ----
    {
        int r0 = wid*16 + (lane >> 2);
        int cb = head*HD + (lane & 3) * 2;
        #pragma unroll
        for (int nt = 0; nt < 4; nt++) {
            if (r0 < N_)
                *(uint32_t*)(g_att + ((size_t)(bw*N_ + r0))*256 + cb + nt*8)
                    = pack2f(av[nt][0]*inv0, av[nt][1]*inv0);
            if (r0 + 8 < N_)
                *(uint32_t*)(g_att + ((size_t)(bw*N_ + r0 + 8))*256 + cb + nt*8)
                    = pack2f(av[nt][2]*inv1, av[nt][3]*inv1);
        }
    }
}

// ---------------- host launcher ---------------------------------------------
extern "C" void kernel_launch(void* const* d_in, const int* in_sizes, int n_in,
                              void* d_out, int out_size) {
    const float* x     = (const float*)d_in[0];
    const float* n1w   = (const float*)d_in[1];
    const float* n1b   = (const float*)d_in[2];
    const float* qkvw  = (const float*)d_in[3];
    const float* qkvb  = (const float*)d_in[4];
    const float* projw = (const float*)d_in[5];
    const float* projb = (const float*)d_in[6];
    const float* rpe   = (const float*)d_in[7];
    const float* n2w   = (const float*)d_in[8];
    const float* n2b   = (const float*)d_in[9];
    const float* fc1w  = (const float*)d_in[10];
    const float* fc1b  = (const float*)d_in[11];
    const float* fc2w  = (const float*)d_in[12];
    const float* fc2b  = (const float*)d_in[13];
    float* out = (float*)d_out;

    __nv_bfloat16 *p_xw, *p_qkv, *p_att, *p_hn, *p_h3, *p_wqkv, *p_wproj, *p_wfc1, *p_wfc2;
    float *p_x2;
    cudaGetSymbolAddress((void**)&p_xw,  g_xw);
    cudaGetSymbolAddress((void**)&p_qkv, g_qkv);
    cudaGetSymbolAddress((void**)&p_att, g_att);
    cudaGetSymbolAddress((void**)&p_x2,  g_x2);
    cudaGetSymbolAddress((void**)&p_hn,  g_hn);
    cudaGetSymbolAddress((void**)&p_h3,  g_h3);
    cudaGetSymbolAddress((void**)&p_wqkv,  g_wqkv);
    cudaGetSymbolAddress((void**)&p_wproj, g_wproj);
    cudaGetSymbolAddress((void**)&p_wfc1,  g_wfc1);
    cudaGetSymbolAddress((void**)&p_wfc2,  g_wfc2);

    cudaFuncSetAttribute(attn_tc, cudaFuncAttributeMaxDynamicSharedMemorySize, ATTN_SMEM);
    cudaFuncSetAttribute(gemm_mma<0>, cudaFuncAttributeMaxDynamicSharedMemorySize, GEMM_SMEM);
    cudaFuncSetAttribute(gemm_mma<1>, cudaFuncAttributeMaxDynamicSharedMemorySize, GEMM_SMEM);
    cudaFuncSetAttribute(gemm_mma<3>, cudaFuncAttributeMaxDynamicSharedMemorySize, GEMM_SMEM);
    cudaFuncSetAttribute(gemm_proj, cudaFuncAttributeMaxDynamicSharedMemorySize, PROJ_SMEM);

    // fused setup (weights + bias/mask table)
    setup_kernel<<<(SETUP_ITEMS + 255)/256, 256>>>(qkvw, projw, fc1w, fc2w, rpe);

    // 1. LN1 + roll + window partition -> bf16
    ln_kernel<<<NTOK/8, 256>>>(x, p_xw, n1w, n1b);
    // 2. QKV GEMM (128x128 tile, K=256, N=768) -> bf16
    gemm_mma<0><<<dim3(6, 392), 256, GEMM_SMEM>>>(p_xw, p_wqkv, qkvb, nullptr, nullptr, p_qkv, 256);
    // 3. register-resident attention (7 warps, 1 m-tile/warp)
    attn_tc<<<BW_*HEADS, 224, ATTN_SMEM>>>();
    // 4. proj GEMM (128x256 tile) + reverse/roll + residual + fused LN2
    gemm_proj<<<392, 256, PROJ_SMEM>>>(p_att, p_wproj, projb, x, p_x2, p_hn, n2w, n2b);
    // 5. fc1 GEMM (128x128, K=256, N=1024) + GELU -> bf16
    gemm_mma<1><<<dim3(8, 392), 256, GEMM_SMEM>>>(p_hn, p_wfc1, fc1b, nullptr, nullptr, p_h3, 256);
    // 6. fc2 GEMM (128x128, K=1024, N=256) + residual -> out
    gemm_mma<3><<<dim3(2, 392), 256, GEMM_SMEM>>>(p_h3, p_wfc2, fc2b, p_x2, out, nullptr, 1024);
}

// round 14
// speedup vs baseline: 1.2353x; 1.0213x over previous
#include <cuda_runtime.h>
#include <cuda_bf16.h>
#include <math.h>
#include <stdint.h>

// ---------------- problem constants ----------------
#define DIM   256
#define HEADS 8
#define HD    32
#define B_    2
#define T_    8
#define H_    56
#define W_    56
#define WT    2
#define WH    7
#define WW    7
#define STs   1
#define SHs   3
#define SWs   3
#define NTOK  (B_*T_*H_*W_)   // 50176 = 392*128
#define BW_   512
#define N_    98
#define HID   1024

// ---------------- scratch (device globals) ----------
__device__ __nv_bfloat16 g_xw [NTOK*256];
__device__ __nv_bfloat16 g_qkv[(size_t)NTOK*768];
__device__ __nv_bfloat16 g_att[NTOK*256];
__device__ float         g_x2 [NTOK*256];
__device__ __nv_bfloat16 g_hn [NTOK*256];
__device__ __nv_bfloat16 g_h3 [(size_t)NTOK*1024];
__device__ __nv_bfloat16 g_wqkv [768*256];
__device__ __nv_bfloat16 g_wproj[256*256];
__device__ __nv_bfloat16 g_wfc1 [1024*256];
__device__ __nv_bfloat16 g_wfc2 [256*1024];
__device__ __nv_bfloat16 g_bm[8*HEADS*112*112];   // bf16 bias+mask table

// ---------------- PTX helpers ----------------------
__device__ __forceinline__ uint32_t smem_u32(const void* p) {
    uint32_t a;
    asm("{ .reg .u64 t; cvta.to.shared.u64 t, %1; cvt.u32.u64 %0, t; }" : "=r"(a) : "l"(p));
    return a;
}
#define CP_ASYNC16(sm, gp) \
    asm volatile("cp.async.cg.shared.global [%0], [%1], 16;" :: "r"(sm), "l"(gp))
#define CP_COMMIT() asm volatile("cp.async.commit_group;" ::: "memory")
#define CP_WAIT0()  asm volatile("cp.async.wait_group 0;" ::: "memory")
#define CP_WAIT1()  asm volatile("cp.async.wait_group 1;" ::: "memory")

#define LDMATRIX_X4(r0,r1,r2,r3,addr) \
    asm volatile("ldmatrix.sync.aligned.m8n8.x4.shared.b16 {%0,%1,%2,%3}, [%4];" \
        : "=r"(r0), "=r"(r1), "=r"(r2), "=r"(r3) : "r"(addr))
#define LDMATRIX_X4T(r0,r1,r2,r3,addr) \
    asm volatile("ldmatrix.sync.aligned.m8n8.x4.trans.shared.b16 {%0,%1,%2,%3}, [%4];" \
        : "=r"(r0), "=r"(r1), "=r"(r2), "=r"(r3) : "r"(addr))
#define MMA_BF16(c, a, b) \
    asm volatile("mma.sync.aligned.m16n8k16.row.col.f32.bf16.bf16.f32 " \
        "{%0,%1,%2,%3}, {%4,%5,%6,%7}, {%8,%9}, {%0,%1,%2,%3};" \
        : "+f"((c)[0]), "+f"((c)[1]), "+f"((c)[2]), "+f"((c)[3]) \
        : "r"((a)[0]), "r"((a)[1]), "r"((a)[2]), "r"((a)[3]), "r"((b)[0]), "r"((b)[1]))

// ---------------- bf16 helpers ----------------
__device__ __forceinline__ uint32_t pack2(__nv_bfloat16 a, __nv_bfloat16 b) {
    return (uint32_t)__bfloat16_as_ushort(a) | ((uint32_t)__bfloat16_as_ushort(b) << 16);
}
__device__ __forceinline__ uint32_t pack2f(float a, float b) {
    return pack2(__float2bfloat16_rn(a), __float2bfloat16_rn(b));
}
__device__ __forceinline__ void plain_store4(__nv_bfloat16* rowp, int col,
                                             float a0, float a1, float a2, float a3) {
    uint2 u;
    u.x = pack2f(a0, a1);
    u.y = pack2f(a2, a3);
    *(uint2*)(rowp + col) = u;
}
__device__ __forceinline__ float2 bm2f(const __nv_bfloat16* p) {
    uint32_t u = *(const uint32_t*)p;
    __nv_bfloat162 t = *reinterpret_cast<__nv_bfloat162*>(&u);
    float2 r;
    r.x = __bfloat162float(t.x);
    r.y = __bfloat162float(t.y);
    return r;
}
__device__ __forceinline__ float gelu_f(float v) {
    return 0.5f * v * (1.0f + erff(v * 0.70710678118654752f));
}

// ---------------- merged setup (weights + bm table) + LN1 -------------------
#define NW_QKV (768*256)
#define NW_PROJ (256*256)
#define NW_FC1 (1024*256)
#define NW_FC2 (256*1024)
#define NBM    (8*112*112)
#define SETUP_ITEMS (NW_QKV + NW_PROJ + NW_FC1 + NW_FC2 + NBM)
#define SETUP_BLOCKS ((SETUP_ITEMS + 255)/256)
#define LN_BLOCKS (NTOK/8)

__global__ void setup_ln_kernel(const float* __restrict__ qkvw, const float* __restrict__ projw,
                                const float* __restrict__ fc1w, const float* __restrict__ fc2w,
                                const float* __restrict__ rpe,
                                const float* __restrict__ src, __nv_bfloat16* __restrict__ dst,
                                const float* __restrict__ w, const float* __restrict__ b) {
    if (blockIdx.x < SETUP_BLOCKS) {
        int idx = blockIdx.x * 256 + threadIdx.x;
        if (idx >= SETUP_ITEMS) return;
        if (idx < NW_QKV) {
            g_wqkv[idx] = __float2bfloat16_rn(qkvw[idx]);
        } else if ((idx -= NW_QKV) < NW_PROJ) {
            g_wproj[idx] = __float2bfloat16_rn(projw[idx]);
        } else if ((idx -= NW_PROJ) < NW_FC1) {
            g_wfc1[idx] = __float2bfloat16_rn(fc1w[idx]);
        } else if ((idx -= NW_FC1) < NW_FC2) {
            g_wfc2[idx] = __float2bfloat16_rn(fc2w[idx]);
        } else {
            int i = idx - NW_FC2;
            int cat = i / (112*112);
            int rm = i % (112*112);
            int r = rm / 112, m = rm % 112;
            if (r < N_ && m < N_) {
                int ct = cat >> 2, ch = (cat >> 1) & 1, cw = cat & 1;
                int tr = r/49, hr = (r%49)/7, wr = r%7;
                int tm = m/49, hm = (m%49)/7, wm = m%7;
                int regr = (ct ? (tr==0?1:2) : 0)*9 + (ch ? (hr<4?1:2) : 0)*3 + (cw ? (wr<4?1:2) : 0);
                int regm = (ct ? (tm==0?1:2) : 0)*9 + (ch ? (hm<4?1:2) : 0)*3 + (cw ? (wm<4?1:2) : 0);
                int tix = (tr - tm + 1)*169 + (hr - hm + 6)*13 + (wr - wm + 6);
                float msk = (regr != regm) ? -100.0f : 0.0f;
                #pragma unroll
                for (int h = 0; h < HEADS; h++)
                    g_bm[((cat*8 + h)*112 + r)*112 + m] = __float2bfloat16_rn(rpe[tix*HEADS + h] + msk);
            } else {
                float v = (m >= N_) ? -1e30f : 0.0f;
                #pragma unroll
                for (int h = 0; h < HEADS; h++)
                    g_bm[((cat*8 + h)*112 + r)*112 + m] = __float2bfloat16_rn(v);
            }
        }
        return;
    }
    // ---- LN1 + roll + window partition ----
    int warp = threadIdx.x >> 5, lane = threadIdx.x & 31;
    int row = (blockIdx.x - SETUP_BLOCKS) * 8 + warp;
    const float* sr = src + (size_t)row * DIM;
    float4 v0 = *(const float4*)(sr + lane * 4);
    float4 v1 = *(const float4*)(sr + 128 + lane * 4);
    float s  = v0.x + v0.y + v0.z + v0.w + v1.x + v1.y + v1.z + v1.w;
    float ss = v0.x*v0.x + v0.y*v0.y + v0.z*v0.z + v0.w*v0.w
             + v1.x*v1.x + v1.y*v1.y + v1.z*v1.z + v1.w*v1.w;
    #pragma unroll
    for (int o = 16; o > 0; o >>= 1) {
        s  += __shfl_xor_sync(0xffffffffu, s, o);
        ss += __shfl_xor_sync(0xffffffffu, ss, o);
    }
    float mean = s * (1.0f / 256.0f);
    float var  = ss * (1.0f / 256.0f) - mean * mean;
    float inv  = rsqrtf(var + 1e-5f);
    int c0 = lane * 4, c1 = 128 + lane * 4;

    int bb = row / (T_*H_*W_);
    int r2 = row % (T_*H_*W_);
    int t = r2 / (H_*W_);
    int r3 = r2 % (H_*W_);
    int h = r3 / W_, ww_ = r3 % W_;
    int t2 = t - STs; if (t2 < 0) t2 += T_;
    int h2 = h - SHs; if (h2 < 0) h2 += H_;
    int w2 = ww_ - SWs; if (w2 < 0) w2 += W_;
    int tw = t2 / WT, hw = h2 / WH, wwn = w2 / WW;
    int n = (t2 % WT) * 49 + (h2 % WH) * 7 + (w2 % WW);
    int bw = ((bb * 4 + tw) * 8 + hw) * 8 + wwn;
    __nv_bfloat16* dr = dst + ((size_t)bw * N_ + n) * 256;
    plain_store4(dr, c0,
        (v0.x - mean) * inv * w[c0+0] + b[c0+0], (v0.y - mean) * inv * w[c0+1] + b[c0+1],
        (v0.z - mean) * inv * w[c0+2] + b[c0+2], (v0.w - mean) * inv * w[c0+3] + b[c0+3]);
    plain_store4(dr, c1,
        (v1.x - mean) * inv * w[c1+0] + b[c1+0], (v1.y - mean) * inv * w[c1+1] + b[c1+1],
        (v1.z - mean) * inv * w[c1+2] + b[c1+2], (v1.w - mean) * inv * w[c1+3] + b[c1+3]);
}

// ---------------- mma.sync GEMM 128x128, 3-stage, 2 CTA/SM (qkv/fc1/fc2) ----
#define ABUF 18432
#define BUFSZ (2*ABUF)
#define GEMM_SMEM (3*BUFSZ)   // 110592

template<int EPI>
__global__ __launch_bounds__(256) void gemm_mma(
        const __nv_bfloat16* __restrict__ A, const __nv_bfloat16* __restrict__ Wm,
        const float* __restrict__ bias, const float* __restrict__ resid,
        float* __restrict__ outF, __nv_bfloat16* __restrict__ outB, int K3) {
    extern __shared__ __align__(16) char smraw[];
    int tid = threadIdx.x, lane = tid & 31, wid = tid >> 5;
    int brow = blockIdx.y * 128, bcol = blockIdx.x * 128;
    int wm = wid & 1, wn = wid >> 1;
    uint32_t sb = smem_u32(smraw);

    float acc[4][4][4] = {};
    const int NC = K3 >> 6;

    const char* Agc = (const char*)(A  + (size_t)brow * K3);
    const char* Bgc = (const char*)(Wm + (size_t)bcol * K3);
    size_t rowstride = (size_t)K3 * 2;

    auto loadChunk = [&](int c, int buf) {
        uint32_t abase = sb + buf * BUFSZ;
        uint32_t bbase = abase + ABUF;
        const char* Ag = Agc + (size_t)c * 128;
        const char* Bg = Bgc + (size_t)c * 128;
        #pragma unroll
        for (int j = 0; j < 4; j++) {
            int x = tid + j * 256;
            int row = x >> 3, kc = x & 7;
            CP_ASYNC16(abase + row * 144 + kc * 16, Ag + (size_t)row * rowstride + kc * 16);
            CP_ASYNC16(bbase + row * 144 + kc * 16, Bg + (size_t)row * rowstride + kc * 16);
        }
        CP_COMMIT();
    };

    loadChunk(0, 0);
    if (NC > 1) loadChunk(1, 1);
    int bc = 0, bn2 = 2;
    for (int c = 0; c < NC; c++) {
        if (c + 1 < NC) CP_WAIT1(); else CP_WAIT0();
        __syncthreads();
        if (c + 2 < NC) loadChunk(c + 2, bn2);
        uint32_t abase = sb + bc * BUFSZ;
        uint32_t bbase = abase + ABUF;
        #pragma unroll
        for (int kh = 0; kh < 4; kh++) {
            uint32_t afr[4][4];
            #pragma unroll
            for (int mt = 0; mt < 4; mt++) {
                int row = wm * 64 + mt * 16 + ((lane >> 3) & 1) * 8 + (lane & 7);
                uint32_t addr = abase + row * 144 + kh * 32 + (lane >> 4) * 16;
                LDMATRIX_X4(afr[mt][0], afr[mt][1], afr[mt][2], afr[mt][3], addr);
            }
            uint32_t bfr[4][2];
            #pragma unroll
            for (int np = 0; np < 2; np++) {
                int nrow = wn * 32 + np * 16 + (lane >> 4) * 8 + (lane & 7);
                uint32_t addr = bbase + nrow * 144 + kh * 32 + ((lane >> 3) & 1) * 16;
                uint32_t r0, r1, r2, r3;
                LDMATRIX_X4(r0, r1, r2, r3, addr);
                bfr[np*2][0] = r0; bfr[np*2][1] = r1;
                bfr[np*2+1][0] = r2; bfr[np*2+1][1] = r3;
            }
            #pragma unroll
            for (int mt = 0; mt < 4; mt++)
                #pragma unroll
                for (int nt = 0; nt < 4; nt++)
                    MMA_BF16(acc[mt][nt], afr[mt], bfr[nt]);
        }
        bc++;  if (bc == 3)  bc = 0;
        bn2++; if (bn2 == 3) bn2 = 0;
    }
    __syncthreads();

    float* Cs = (float*)smraw;
    #pragma unroll
    for (int mt = 0; mt < 4; mt++)
        #pragma unroll
        for (int nt = 0; nt < 4; nt++) {
            int r0 = wm * 64 + mt * 16 + (lane >> 2);
            int cc = wn * 32 + nt * 8 + (lane & 3) * 2;
            Cs[r0 * 132 + cc]       = acc[mt][nt][0];
            Cs[r0 * 132 + cc + 1]   = acc[mt][nt][1];
            Cs[(r0+8) * 132 + cc]   = acc[mt][nt][2];
            Cs[(r0+8) * 132 + cc+1] = acc[mt][nt][3];
        }
    __syncthreads();

    float4 bs = *(const float4*)(bias + bcol + lane * 4);
    for (int r = wid; r < 128; r += 8) {
        float4 v = *(const float4*)&Cs[r * 132 + lane * 4];
        v.x += bs.x; v.y += bs.y; v.z += bs.z; v.w += bs.w;
        int grow = brow + r;
        int col = bcol + lane * 4;
        if (EPI == 0) {
            plain_store4(outB + (size_t)grow * 768, col, v.x, v.y, v.z, v.w);
        } else if (EPI == 1) {
            plain_store4(outB + (size_t)grow * 1024, col,
                         gelu_f(v.x), gelu_f(v.y), gelu_f(v.z), gelu_f(v.w));
        } else {
            float4 rr = *(const float4*)(resid + (size_t)grow * 256 + col);
            v.x += rr.x; v.y += rr.y; v.z += rr.z; v.w += rr.w;
            *(float4*)(outF + (size_t)grow * 256 + col) = v;
        }
    }
}

// ---------------- proj GEMM 128x256 + reverse/roll + residual + fused LN2 ---
#define PABUF 18432
#define PBBUF 36864
#define PSTG  (PABUF + PBBUF)
#define PROJ_SMEM (3*PSTG)

__global__ __launch_bounds__(256, 1) void gemm_proj(
        const __nv_bfloat16* __restrict__ A, const __nv_bfloat16* __restrict__ Wm,
        const float* __restrict__ bias, const float* __restrict__ resid,
        float* __restrict__ outF, __nv_bfloat16* __restrict__ outB,
        const float* __restrict__ lnw, const float* __restrict__ lnb) {
    extern __shared__ __align__(16) char smraw[];
    const int K3 = 256;
    int tid = threadIdx.x, lane = tid & 31, wid = tid >> 5;
    int brow = blockIdx.x * 128;
    int wm = wid & 1, wn = wid >> 1;
    uint32_t sb = smem_u32(smraw);

    float acc[4][8][4] = {};
    const int NC = 4;

    const char* Agc = (const char*)(A + (size_t)brow * K3);
    const char* Bgc = (const char*)Wm;
    size_t rowstride = (size_t)K3 * 2;

    auto loadChunk = [&](int c, int buf) {
        uint32_t abase = sb + buf * PSTG;
        uint32_t bbase = abase + PABUF;
        const char* Ag = Agc + (size_t)c * 128;
        const char* Bg = Bgc + (size_t)c * 128;
        #pragma unroll
        for (int j = 0; j < 12; j++) {
            int x = tid + j * 256;
            if (x < 1024) {
                int row = x >> 3, kc = x & 7;
                CP_ASYNC16(abase + row * 144 + kc * 16, Ag + (size_t)row * rowstride + kc * 16);
            } else {
                int y = x - 1024;
                int row = y >> 3, kc = y & 7;
                CP_ASYNC16(bbase + row * 144 + kc * 16, Bg + (size_t)row * rowstride + kc * 16);
            }
        }
        CP_COMMIT();
    };

    loadChunk(0, 0);
    loadChunk(1, 1);
    int bc = 0, bn2 = 2;
    for (int c = 0; c < NC; c++) {
        if (c + 1 < NC) CP_WAIT1(); else CP_WAIT0();
        __syncthreads();
        if (c + 2 < NC) loadChunk(c + 2, bn2);
        uint32_t abase = sb + bc * PSTG;
        uint32_t bbase = abase + PABUF;
        #pragma unroll
        for (int kh = 0; kh < 4; kh++) {
            uint32_t afr[4][4];
            #pragma unroll
            for (int mt = 0; mt < 4; mt++) {
                int row = wm * 64 + mt * 16 + ((lane >> 3) & 1) * 8 + (lane & 7);
                uint32_t addr = abase + row * 144 + kh * 32 + (lane >> 4) * 16;
                LDMATRIX_X4(afr[mt][0], afr[mt][1], afr[mt][2], afr[mt][3], addr);
            }
            uint32_t bfr[8][2];
            #pragma unroll
            for (int np = 0; np < 4; np++) {
                int nrow = wn * 64 + np * 16 + (lane >> 4) * 8 + (lane & 7);
                uint32_t addr = bbase + nrow * 144 + kh * 32 + ((lane >> 3) & 1) * 16;
                uint32_t r0, r1, r2, r3;
                LDMATRIX_X4(r0, r1, r2, r3, addr);
                bfr[np*2][0] = r0; bfr[np*2][1] = r1;
                bfr[np*2+1][0] = r2; bfr[np*2+1][1] = r3;
            }
            #pragma unroll
            for (int mt = 0; mt < 4; mt++)
                #pragma unroll
                for (int nt = 0; nt < 8; nt++)
                    MMA_BF16(acc[mt][nt], afr[mt], bfr[nt]);
        }
        bc++;  if (bc == 3)  bc = 0;
        bn2++; if (bn2 == 3) bn2 = 0;
    }
    __syncthreads();

    float* Cs = (float*)smraw;
    #pragma unroll
    for (int mt = 0; mt < 4; mt++)
        #pragma unroll
        for (int nt = 0; nt < 8; nt++) {
            int r0 = wm * 64 + mt * 16 + (lane >> 2);
            int cc = wn * 64 + nt * 8 + (lane & 3) * 2;
            Cs[r0 * 264 + cc]       = acc[mt][nt][0];
            Cs[r0 * 264 + cc + 1]   = acc[mt][nt][1];
            Cs[(r0+8) * 264 + cc]   = acc[mt][nt][2];
            Cs[(r0+8) * 264 + cc+1] = acc[mt][nt][3];
        }
    __syncthreads();

    int ca = lane * 4, cb2 = 128 + lane * 4;
    float4 bs0 = *(const float4*)(bias + ca);
    float4 bs1 = *(const float4*)(bias + cb2);
    float4 lw0 = *(const float4*)(lnw + ca), lw1 = *(const float4*)(lnw + cb2);
    float4 lb0 = *(const float4*)(lnb + ca), lb1 = *(const float4*)(lnb + cb2);
    for (int r = wid; r < 128; r += 8) {
        float4 v0 = *(const float4*)&Cs[r * 264 + ca];
        float4 v1 = *(const float4*)&Cs[r * 264 + cb2];
        v0.x += bs0.x; v0.y += bs0.y; v0.z += bs0.z; v0.w += bs0.w;
        v1.x += bs1.x; v1.y += bs1.y; v1.z += bs1.z; v1.w += bs1.w;
        int grow = brow + r;
        int bw = grow / N_, n = grow % N_;
        int bb = bw >> 8, wrem = bw & 255;
        int tw = wrem >> 6, hw = (wrem >> 3) & 7, wwn = wrem & 7;
        int nt = n / 49, nr = n % 49;
        int t2 = tw*WT + nt, h2 = hw*WH + nr/7, w2 = wwn*WW + nr%7;
        int t = t2 + STs; if (t >= T_) t -= T_;
        int h = h2 + SHs; if (h >= H_) h -= H_;
        int ww_ = w2 + SWs; if (ww_ >= W_) ww_ -= W_;
        size_t orow = ((size_t)((bb*T_ + t)*H_ + h))*W_ + ww_;
        float4 r0 = *(const float4*)(resid + orow * 256 + ca);
        float4 r1 = *(const float4*)(resid + orow * 256 + cb2);
        v0.x += r0.x; v0.y += r0.y; v0.z += r0.z; v0.w += r0.w;
        v1.x += r1.x; v1.y += r1.y; v1.z += r1.z; v1.w += r1.w;
        *(float4*)(outF + orow * 256 + ca)  = v0;
        *(float4*)(outF + orow * 256 + cb2) = v1;
        // fused LN2
        float s  = v0.x + v0.y + v0.z + v0.w + v1.x + v1.y + v1.z + v1.w;
        float ss = v0.x*v0.x + v0.y*v0.y + v0.z*v0.z + v0.w*v0.w
                 + v1.x*v1.x + v1.y*v1.y + v1.z*v1.z + v1.w*v1.w;
        #pragma unroll
        for (int o2 = 16; o2 > 0; o2 >>= 1) {
            s  += __shfl_xor_sync(0xffffffffu, s, o2);
            ss += __shfl_xor_sync(0xffffffffu, ss, o2);
        }
        float mean = s * (1.0f / 256.0f);
        float var  = ss * (1.0f / 256.0f) - mean * mean;
        float inv  = rsqrtf(var + 1e-5f);
        __nv_bfloat16* hnp = outB + orow * 256;
        plain_store4(hnp, ca,
            (v0.x - mean) * inv * lw0.x + lb0.x, (v0.y - mean) * inv * lw0.y + lb0.y,
            (v0.z - mean) * inv * lw0.z + lb0.z, (v0.w - mean) * inv * lw0.w + lb0.w);
        plain_store4(hnp, cb2,
            (v1.x - mean) * inv * lw1.x + lb1.x, (v1.y - mean) * inv * lw1.y + lb1.y,
            (v1.z - mean) * inv * lw1.z + lb1.z, (v1.w - mean) * inv * lw1.w + lb1.w);
    }
}

// ---------------- register-resident attention: 7 warps + smem bm prefetch --
#define QSTR 80
#define SM_Q  0
#define SM_K  (112*QSTR)
#define SM_V  (2*112*QSTR)
#define SM_BM (3*112*QSTR)          // 26880
#define ATTN_SMEM (SM_BM + 112*112*2)  // 51968

__global__ __launch_bounds__(224) void attn_tc() {
    extern __shared__ __align__(16) char asmem[];

    int tid = threadIdx.x, lane = tid & 31, wid = tid >> 5;   // wid 0..6
    int head = blockIdx.x & 7, bw = blockIdx.x >> 3;
    int wrem = bw & 255;
    int tw = wrem >> 6, hw = (wrem >> 3) & 7, wwn = wrem & 7;
    int cat = ((tw == 3) ? 4 : 0) | ((hw == 7) ? 2 : 0) | ((wwn == 7) ? 1 : 0);

    uint32_t uQ = smem_u32(asmem + SM_Q);
    uint32_t uK = smem_u32(asmem + SM_K);
    uint32_t uV = smem_u32(asmem + SM_V);
    uint32_t uBM = smem_u32(asmem + SM_BM);

    // prefetch this block's 112x112 bf16 bias/mask tile (25088 B) via cp.async
    {
        const char* bmsrc = (const char*)(g_bm + ((size_t)(cat*8 + head)) * (112*112));
        #pragma unroll
        for (int j = 0; j < 7; j++) {
            int x = tid + j * 224;   // 0..1567
            CP_ASYNC16(uBM + x * 16, bmsrc + x * 16);
        }
        CP_COMMIT();
    }

    if (tid < N_) {
        const uint4* g = (const uint4*)(g_qkv + ((size_t)(bw*N_ + tid)) * 768 + head * HD);
        #pragma unroll
        for (int j = 0; j < 4; j++) {
            *(uint4*)(asmem + SM_Q + tid*QSTR + j*16) = g[j];
            *(uint4*)(asmem + SM_K + tid*QSTR + j*16) = g[32 + j];
            *(uint4*)(asmem + SM_V + tid*QSTR + j*16) = g[64 + j];
        }
    } else if (tid < 112) {
        uint4 z = make_uint4(0,0,0,0);
        #pragma unroll
        for (int j = 0; j < 4; j++) {
            *(uint4*)(asmem + SM_Q + tid*QSTR + j*16) = z;
            *(uint4*)(asmem + SM_K + tid*QSTR + j*16) = z;
            *(uint4*)(asmem + SM_V + tid*QSTR + j*16) = z;
        }
    }
    __syncthreads();

    float acc[14][4] = {};

    // ---- QK^T: warp wid owns m-tile rows [16*wid, 16*wid+16) ----
    #pragma unroll
    for (int kh = 0; kh < 2; kh++) {
        uint32_t bfr[14][2];
        #pragma unroll
        for (int np = 0; np < 7; np++) {
            int nrow = np*16 + (lane >> 4) * 8 + (lane & 7);
            uint32_t addr = uK + nrow*QSTR + kh*32 + ((lane >> 3) & 1) * 16;
            uint32_t r0, r1, r2, r3;
            LDMATRIX_X4(r0, r1, r2, r3, addr);
            bfr[np*2][0] = r0; bfr[np*2][1] = r1;
            bfr[np*2+1][0] = r2; bfr[np*2+1][1] = r3;
        }
        int row = wid*16 + ((lane >> 3) & 1) * 8 + (lane & 7);
        uint32_t addr = uQ + row*QSTR + kh*32 + (lane >> 4) * 16;
        uint32_t afr[4];
        LDMATRIX_X4(afr[0], afr[1], afr[2], afr[3], addr);
        #pragma unroll
        for (int nt = 0; nt < 14; nt++)
            MMA_BF16(acc[nt], afr, bfr[nt]);
    }

    // bm tile must be fully resident (loaded by all threads) before softmax
    CP_WAIT0();
    __syncthreads();

    // ---- register softmax (bias+mask from smem; unnormalized exp) ----
    float inv0, inv1;
    {
        int row0 = wid*16 + (lane >> 2);
        const __nv_bfloat16* bm = (const __nv_bfloat16*)(asmem + SM_BM) + row0*112;
        int c0 = (lane & 3) * 2;
        float mx0 = -1e30f, mx1 = -1e30f;
        #pragma unroll
        for (int nt = 0; nt < 14; nt++) {
            float2 b0 = bm2f(bm + nt*8 + c0);
            float2 b1 = bm2f(bm + 8*112 + nt*8 + c0);
            float s0 = fmaf(acc[nt][0], 0.17677669529663687f, b0.x);
            float s1 = fmaf(acc[nt][1], 0.17677669529663687f, b0.y);
            float s2 = fmaf(acc[nt][2], 0.17677669529663687f, b1.x);
            float s3 = fmaf(acc[nt][3], 0.17677669529663687f, b1.y);
            acc[nt][0] = s0; acc[nt][1] = s1;
            acc[nt][2] = s2; acc[nt][3] = s3;
            mx0 = fmaxf(mx0, fmaxf(s0, s1));
            mx1 = fmaxf(mx1, fmaxf(s2, s3));
        }
        mx0 = fmaxf(mx0, __shfl_xor_sync(0xffffffffu, mx0, 1));
        mx0 = fmaxf(mx0, __shfl_xor_sync(0xffffffffu, mx0, 2));
        mx1 = fmaxf(mx1, __shfl_xor_sync(0xffffffffu, mx1, 1));
        mx1 = fmaxf(mx1, __shfl_xor_sync(0xffffffffu, mx1, 2));
        float sm0 = 0.f, sm1 = 0.f;
        #pragma unroll
        for (int nt = 0; nt < 14; nt++) {
            float e0 = __expf(acc[nt][0] - mx0);
            float e1 = __expf(acc[nt][1] - mx0);
            float e2 = __expf(acc[nt][2] - mx1);
            float e3 = __expf(acc[nt][3] - mx1);
            acc[nt][0] = e0; acc[nt][1] = e1;
            acc[nt][2] = e2; acc[nt][3] = e3;
            sm0 += e0 + e1; sm1 += e2 + e3;
        }
        sm0 += __shfl_xor_sync(0xffffffffu, sm0, 1);
        sm0 += __shfl_xor_sync(0xffffffffu, sm0, 2);
        sm1 += __shfl_xor_sync(0xffffffffu, sm1, 1);
        sm1 += __shfl_xor_sync(0xffffffffu, sm1, 2);
        inv0 = 1.0f / sm0;
        inv1 = 1.0f / sm1;
    }

    // ---- AV: P fragments straight from registers ----
    float av[4][4] = {};
    #pragma unroll
    for (int kt = 0; kt < 7; kt++) {
        uint32_t vfr[4][2];
        #pragma unroll
        for (int np = 0; np < 2; np++) {
            int krow = kt*16 + ((lane >> 3) & 1) * 8 + (lane & 7);
            int ncol = np*16 + (lane >> 4) * 8;
            uint32_t addr = uV + krow*QSTR + ncol*2;
            uint32_t r0, r1, r2, r3;
            LDMATRIX_X4T(r0, r1, r2, r3, addr);
            vfr[np*2][0] = r0; vfr[np*2][1] = r1;
            vfr[np*2+1][0] = r2; vfr[np*2+1][1] = r3;
        }
        uint32_t pa[4];
        pa[0] = pack2f(acc[2*kt][0],   acc[2*kt][1]);
        pa[1] = pack2f(acc[2*kt][2],   acc[2*kt][3]);
        pa[2] = pack2f(acc[2*kt+1][0], acc[2*kt+1][1]);
        pa[3] = pack2f(acc[2*kt+1][2], acc[2*kt+1][3]);
        #pragma unroll
        for (int nt = 0; nt < 4; nt++)
            MMA_BF16(av[nt], pa, vfr[nt]);
    }

    // ---- store (apply 1/sum here) ----
    {
        int r0 = wid*16 + (lane >> 2);
        int cb = head*HD + (lane & 3) * 2;
        #pragma unroll
        for (int nt = 0; nt < 4; nt++) {
            if (r0 < N_)
                *(uint32_t*)(g_att + ((size_t)(bw*N_ + r0))*256 + cb + nt*8)
                    = pack2f(av[nt][0]*inv0, av[nt][1]*inv0);
            if (r0 + 8 < N_)
                *(uint32_t*)(g_att + ((size_t)(bw*N_ + r0 + 8))*256 + cb + nt*8)
                    = pack2f(av[nt][2]*inv1, av[nt][3]*inv1);
        }
    }
}

// ---------------- host launcher ---------------------------------------------
extern "C" void kernel_launch(void* const* d_in, const int* in_sizes, int n_in,
                              void* d_out, int out_size) {
    const float* x     = (const float*)d_in[0];
    const float* n1w   = (const float*)d_in[1];
    const float* n1b   = (const float*)d_in[2];
    const float* qkvw  = (const float*)d_in[3];
    const float* qkvb  = (const float*)d_in[4];
    const float* projw = (const float*)d_in[5];
    const float* projb = (const float*)d_in[6];
    const float* rpe   = (const float*)d_in[7];
    const float* n2w   = (const float*)d_in[8];
    const float* n2b   = (const float*)d_in[9];
    const float* fc1w  = (const float*)d_in[10];
    const float* fc1b  = (const float*)d_in[11];
    const float* fc2w  = (const float*)d_in[12];
    const float* fc2b  = (const float*)d_in[13];
    float* out = (float*)d_out;

    __nv_bfloat16 *p_xw, *p_qkv, *p_att, *p_hn, *p_h3, *p_wqkv, *p_wproj, *p_wfc1, *p_wfc2;
    float *p_x2;
    cudaGetSymbolAddress((void**)&p_xw,  g_xw);
    cudaGetSymbolAddress((void**)&p_qkv, g_qkv);
    cudaGetSymbolAddress((void**)&p_att, g_att);
    cudaGetSymbolAddress((void**)&p_x2,  g_x2);
    cudaGetSymbolAddress((void**)&p_hn,  g_hn);
    cudaGetSymbolAddress((void**)&p_h3,  g_h3);
    cudaGetSymbolAddress((void**)&p_wqkv,  g_wqkv);
    cudaGetSymbolAddress((void**)&p_wproj, g_wproj);
    cudaGetSymbolAddress((void**)&p_wfc1,  g_wfc1);
    cudaGetSymbolAddress((void**)&p_wfc2,  g_wfc2);

    cudaFuncSetAttribute(attn_tc, cudaFuncAttributeMaxDynamicSharedMemorySize, ATTN_SMEM);
    cudaFuncSetAttribute(gemm_mma<0>, cudaFuncAttributeMaxDynamicSharedMemorySize, GEMM_SMEM);
    cudaFuncSetAttribute(gemm_mma<1>, cudaFuncAttributeMaxDynamicSharedMemorySize, GEMM_SMEM);
    cudaFuncSetAttribute(gemm_mma<3>, cudaFuncAttributeMaxDynamicSharedMemorySize, GEMM_SMEM);
    cudaFuncSetAttribute(gemm_proj, cudaFuncAttributeMaxDynamicSharedMemorySize, PROJ_SMEM);

    // 0+1. merged setup (weights + bm table) and LN1
    setup_ln_kernel<<<SETUP_BLOCKS + LN_BLOCKS, 256>>>(qkvw, projw, fc1w, fc2w, rpe,
                                                       x, p_xw, n1w, n1b);
    // 2. QKV GEMM (128x128 tile, K=256, N=768) -> bf16
    gemm_mma<0><<<dim3(6, 392), 256, GEMM_SMEM>>>(p_xw, p_wqkv, qkvb, nullptr, nullptr, p_qkv, 256);
    // 3. register-resident attention (7 warps + smem bm prefetch)
    attn_tc<<<BW_*HEADS, 224, ATTN_SMEM>>>();
    // 4. proj GEMM (128x256 tile) + reverse/roll + residual + fused LN2
    gemm_proj<<<392, 256, PROJ_SMEM>>>(p_att, p_wproj, projb, x, p_x2, p_hn, n2w, n2b);
    // 5. fc1 GEMM (128x128, K=256, N=1024) + GELU -> bf16
    gemm_mma<1><<<dim3(8, 392), 256, GEMM_SMEM>>>(p_hn, p_wfc1, fc1b, nullptr, nullptr, p_h3, 256);
    // 6. fc2 GEMM (128x128, K=1024, N=256) + residual -> out
    gemm_mma<3><<<dim3(2, 392), 256, GEMM_SMEM>>>(p_h3, p_wfc2, fc2b, p_x2, out, nullptr, 1024);
}

// round 15
// speedup vs baseline: 1.2941x; 1.0476x over previous
#include <cuda_runtime.h>
#include <cuda_bf16.h>
#include <math.h>
#include <stdint.h>

// ---------------- problem constants ----------------
#define DIM   256
#define HEADS 8
#define HD    32
#define B_    2
#define T_    8
#define H_    56
#define W_    56
#define WT    2
#define WH    7
#define WW    7
#define STs   1
#define SHs   3
#define SWs   3
#define NTOK  (B_*T_*H_*W_)   // 50176 = 392*128
#define BW_   512
#define N_    98
#define HID   1024

// ---------------- scratch (device globals) ----------
__device__ __nv_bfloat16 g_xw [NTOK*256];
__device__ __nv_bfloat16 g_qkv[(size_t)NTOK*768];
__device__ __nv_bfloat16 g_att[NTOK*256];
__device__ float         g_x2 [NTOK*256];
__device__ __nv_bfloat16 g_hn [NTOK*256];
__device__ __nv_bfloat16 g_h3 [(size_t)NTOK*1024];
__device__ __nv_bfloat16 g_wqkv [768*256];
__device__ __nv_bfloat16 g_wproj[256*256];
__device__ __nv_bfloat16 g_wfc1 [1024*256];
__device__ __nv_bfloat16 g_wfc2 [256*1024];
__device__ __nv_bfloat16 g_bm[8*HEADS*112*112];   // bf16 bias+mask table

// ---------------- PTX helpers ----------------------
__device__ __forceinline__ uint32_t smem_u32(const void* p) {
    uint32_t a;
    asm("{ .reg .u64 t; cvta.to.shared.u64 t, %1; cvt.u32.u64 %0, t; }" : "=r"(a) : "l"(p));
    return a;
}
#define CP_ASYNC16(sm, gp) \
    asm volatile("cp.async.cg.shared.global [%0], [%1], 16;" :: "r"(sm), "l"(gp))
#define CP_COMMIT() asm volatile("cp.async.commit_group;" ::: "memory")
#define CP_WAIT0()  asm volatile("cp.async.wait_group 0;" ::: "memory")
#define CP_WAIT1()  asm volatile("cp.async.wait_group 1;" ::: "memory")

#define LDMATRIX_X4(r0,r1,r2,r3,addr) \
    asm volatile("ldmatrix.sync.aligned.m8n8.x4.shared.b16 {%0,%1,%2,%3}, [%4];" \
        : "=r"(r0), "=r"(r1), "=r"(r2), "=r"(r3) : "r"(addr))
#define LDMATRIX_X4T(r0,r1,r2,r3,addr) \
    asm volatile("ldmatrix.sync.aligned.m8n8.x4.trans.shared.b16 {%0,%1,%2,%3}, [%4];" \
        : "=r"(r0), "=r"(r1), "=r"(r2), "=r"(r3) : "r"(addr))
#define MMA_BF16(c, a, b) \
    asm volatile("mma.sync.aligned.m16n8k16.row.col.f32.bf16.bf16.f32 " \
        "{%0,%1,%2,%3}, {%4,%5,%6,%7}, {%8,%9}, {%0,%1,%2,%3};" \
        : "+f"((c)[0]), "+f"((c)[1]), "+f"((c)[2]), "+f"((c)[3]) \
        : "r"((a)[0]), "r"((a)[1]), "r"((a)[2]), "r"((a)[3]), "r"((b)[0]), "r"((b)[1]))

// ---------------- bf16 helpers ----------------
__device__ __forceinline__ uint32_t pack2(__nv_bfloat16 a, __nv_bfloat16 b) {
    return (uint32_t)__bfloat16_as_ushort(a) | ((uint32_t)__bfloat16_as_ushort(b) << 16);
}
__device__ __forceinline__ uint32_t pack2f(float a, float b) {
    return pack2(__float2bfloat16_rn(a), __float2bfloat16_rn(b));
}
__device__ __forceinline__ void plain_store4(__nv_bfloat16* rowp, int col,
                                             float a0, float a1, float a2, float a3) {
    uint2 u;
    u.x = pack2f(a0, a1);
    u.y = pack2f(a2, a3);
    *(uint2*)(rowp + col) = u;
}
__device__ __forceinline__ float2 bm2f(const __nv_bfloat16* p) {
    uint32_t u = *(const uint32_t*)p;
    __nv_bfloat162 t = *reinterpret_cast<__nv_bfloat162*>(&u);
    float2 r;
    r.x = __bfloat162float(t.x);
    r.y = __bfloat162float(t.y);
    return r;
}
__device__ __forceinline__ float gelu_f(float v) {
    return 0.5f * v * (1.0f + erff(v * 0.70710678118654752f));
}

// ---------------- merged setup (weights + bm table) + LN1 -------------------
#define NW_QKV (768*256)
#define NW_PROJ (256*256)
#define NW_FC1 (1024*256)
#define NW_FC2 (256*1024)
#define NBM    (8*112*112)
#define SETUP_ITEMS (NW_QKV + NW_PROJ + NW_FC1 + NW_FC2 + NBM)
#define SETUP_BLOCKS ((SETUP_ITEMS + 255)/256)
#define LN_BLOCKS (NTOK/8)

__global__ void setup_ln_kernel(const float* __restrict__ qkvw, const float* __restrict__ projw,
                                const float* __restrict__ fc1w, const float* __restrict__ fc2w,
                                const float* __restrict__ rpe,
                                const float* __restrict__ src, __nv_bfloat16* __restrict__ dst,
                                const float* __restrict__ w, const float* __restrict__ b) {
    if (blockIdx.x < SETUP_BLOCKS) {
        int idx = blockIdx.x * 256 + threadIdx.x;
        if (idx >= SETUP_ITEMS) return;
        if (idx < NW_QKV) {
            g_wqkv[idx] = __float2bfloat16_rn(qkvw[idx]);
        } else if ((idx -= NW_QKV) < NW_PROJ) {
            g_wproj[idx] = __float2bfloat16_rn(projw[idx]);
        } else if ((idx -= NW_PROJ) < NW_FC1) {
            g_wfc1[idx] = __float2bfloat16_rn(fc1w[idx]);
        } else if ((idx -= NW_FC1) < NW_FC2) {
            g_wfc2[idx] = __float2bfloat16_rn(fc2w[idx]);
        } else {
            int i = idx - NW_FC2;
            int cat = i / (112*112);
            int rm = i % (112*112);
            int r = rm / 112, m = rm % 112;
            if (r < N_ && m < N_) {
                int ct = cat >> 2, ch = (cat >> 1) & 1, cw = cat & 1;
                int tr = r/49, hr = (r%49)/7, wr = r%7;
                int tm = m/49, hm = (m%49)/7, wm = m%7;
                int regr = (ct ? (tr==0?1:2) : 0)*9 + (ch ? (hr<4?1:2) : 0)*3 + (cw ? (wr<4?1:2) : 0);
                int regm = (ct ? (tm==0?1:2) : 0)*9 + (ch ? (hm<4?1:2) : 0)*3 + (cw ? (wm<4?1:2) : 0);
                int tix = (tr - tm + 1)*169 + (hr - hm + 6)*13 + (wr - wm + 6);
                float msk = (regr != regm) ? -100.0f : 0.0f;
                #pragma unroll
                for (int h = 0; h < HEADS; h++)
                    g_bm[((cat*8 + h)*112 + r)*112 + m] = __float2bfloat16_rn(rpe[tix*HEADS + h] + msk);
            } else {
                float v = (m >= N_) ? -1e30f : 0.0f;
                #pragma unroll
                for (int h = 0; h < HEADS; h++)
                    g_bm[((cat*8 + h)*112 + r)*112 + m] = __float2bfloat16_rn(v);
            }
        }
        return;
    }
    // ---- LN1 + roll + window partition ----
    int warp = threadIdx.x >> 5, lane = threadIdx.x & 31;
    int row = (blockIdx.x - SETUP_BLOCKS) * 8 + warp;
    const float* sr = src + (size_t)row * DIM;
    float4 v0 = *(const float4*)(sr + lane * 4);
    float4 v1 = *(const float4*)(sr + 128 + lane * 4);
    float s  = v0.x + v0.y + v0.z + v0.w + v1.x + v1.y + v1.z + v1.w;
    float ss = v0.x*v0.x + v0.y*v0.y + v0.z*v0.z + v0.w*v0.w
             + v1.x*v1.x + v1.y*v1.y + v1.z*v1.z + v1.w*v1.w;
    #pragma unroll
    for (int o = 16; o > 0; o >>= 1) {
        s  += __shfl_xor_sync(0xffffffffu, s, o);
        ss += __shfl_xor_sync(0xffffffffu, ss, o);
    }
    float mean = s * (1.0f / 256.0f);
    float var  = ss * (1.0f / 256.0f) - mean * mean;
    float inv  = rsqrtf(var + 1e-5f);
    int c0 = lane * 4, c1 = 128 + lane * 4;

    int bb = row / (T_*H_*W_);
    int r2 = row % (T_*H_*W_);
    int t = r2 / (H_*W_);
    int r3 = r2 % (H_*W_);
    int h = r3 / W_, ww_ = r3 % W_;
    int t2 = t - STs; if (t2 < 0) t2 += T_;
    int h2 = h - SHs; if (h2 < 0) h2 += H_;
    int w2 = ww_ - SWs; if (w2 < 0) w2 += W_;
    int tw = t2 / WT, hw = h2 / WH, wwn = w2 / WW;
    int n = (t2 % WT) * 49 + (h2 % WH) * 7 + (w2 % WW);
    int bw = ((bb * 4 + tw) * 8 + hw) * 8 + wwn;
    __nv_bfloat16* dr = dst + ((size_t)bw * N_ + n) * 256;
    plain_store4(dr, c0,
        (v0.x - mean) * inv * w[c0+0] + b[c0+0], (v0.y - mean) * inv * w[c0+1] + b[c0+1],
        (v0.z - mean) * inv * w[c0+2] + b[c0+2], (v0.w - mean) * inv * w[c0+3] + b[c0+3]);
    plain_store4(dr, c1,
        (v1.x - mean) * inv * w[c1+0] + b[c1+0], (v1.y - mean) * inv * w[c1+1] + b[c1+1],
        (v1.z - mean) * inv * w[c1+2] + b[c1+2], (v1.w - mean) * inv * w[c1+3] + b[c1+3]);
}

// ---------------- mma.sync GEMM 128x128, 3-stage, 2 CTA/SM (qkv/fc1/fc2) ----
#define ABUF 18432
#define BUFSZ (2*ABUF)
#define GEMM_SMEM (3*BUFSZ)   // 110592

template<int EPI>
__global__ __launch_bounds__(256) void gemm_mma(
        const __nv_bfloat16* __restrict__ A, const __nv_bfloat16* __restrict__ Wm,
        const float* __restrict__ bias, const float* __restrict__ resid,
        float* __restrict__ outF, __nv_bfloat16* __restrict__ outB, int K3) {
    extern __shared__ __align__(16) char smraw[];
    int tid = threadIdx.x, lane = tid & 31, wid = tid >> 5;
    int brow = blockIdx.y * 128, bcol = blockIdx.x * 128;
    int wm = wid & 1, wn = wid >> 1;
    uint32_t sb = smem_u32(smraw);

    float acc[4][4][4] = {};
    const int NC = K3 >> 6;

    const char* Agc = (const char*)(A  + (size_t)brow * K3);
    const char* Bgc = (const char*)(Wm + (size_t)bcol * K3);
    size_t rowstride = (size_t)K3 * 2;

    auto loadChunk = [&](int c, int buf) {
        uint32_t abase = sb + buf * BUFSZ;
        uint32_t bbase = abase + ABUF;
        const char* Ag = Agc + (size_t)c * 128;
        const char* Bg = Bgc + (size_t)c * 128;
        #pragma unroll
        for (int j = 0; j < 4; j++) {
            int x = tid + j * 256;
            int row = x >> 3, kc = x & 7;
            CP_ASYNC16(abase + row * 144 + kc * 16, Ag + (size_t)row * rowstride + kc * 16);
            CP_ASYNC16(bbase + row * 144 + kc * 16, Bg + (size_t)row * rowstride + kc * 16);
        }
        CP_COMMIT();
    };

    loadChunk(0, 0);
    if (NC > 1) loadChunk(1, 1);
    int bc = 0, bn2 = 2;
    for (int c = 0; c < NC; c++) {
        if (c + 1 < NC) CP_WAIT1(); else CP_WAIT0();
        __syncthreads();
        if (c + 2 < NC) loadChunk(c + 2, bn2);
        uint32_t abase = sb + bc * BUFSZ;
        uint32_t bbase = abase + ABUF;
        #pragma unroll
        for (int kh = 0; kh < 4; kh++) {
            uint32_t afr[4][4];
            #pragma unroll
            for (int mt = 0; mt < 4; mt++) {
                int row = wm * 64 + mt * 16 + ((lane >> 3) & 1) * 8 + (lane & 7);
                uint32_t addr = abase + row * 144 + kh * 32 + (lane >> 4) * 16;
                LDMATRIX_X4(afr[mt][0], afr[mt][1], afr[mt][2], afr[mt][3], addr);
            }
            uint32_t bfr[4][2];
            #pragma unroll
            for (int np = 0; np < 2; np++) {
                int nrow = wn * 32 + np * 16 + (lane >> 4) * 8 + (lane & 7);
                uint32_t addr = bbase + nrow * 144 + kh * 32 + ((lane >> 3) & 1) * 16;
                uint32_t r0, r1, r2, r3;
                LDMATRIX_X4(r0, r1, r2, r3, addr);
                bfr[np*2][0] = r0; bfr[np*2][1] = r1;
                bfr[np*2+1][0] = r2; bfr[np*2+1][1] = r3;
            }
            #pragma unroll
            for (int mt = 0; mt < 4; mt++)
                #pragma unroll
                for (int nt = 0; nt < 4; nt++)
                    MMA_BF16(acc[mt][nt], afr[mt], bfr[nt]);
        }
        bc++;  if (bc == 3)  bc = 0;
        bn2++; if (bn2 == 3) bn2 = 0;
    }
    __syncthreads();

    float* Cs = (float*)smraw;
    #pragma unroll
    for (int mt = 0; mt < 4; mt++)
        #pragma unroll
        for (int nt = 0; nt < 4; nt++) {
            int r0 = wm * 64 + mt * 16 + (lane >> 2);
            int cc = wn * 32 + nt * 8 + (lane & 3) * 2;
            Cs[r0 * 132 + cc]       = acc[mt][nt][0];
            Cs[r0 * 132 + cc + 1]   = acc[mt][nt][1];
            Cs[(r0+8) * 132 + cc]   = acc[mt][nt][2];
            Cs[(r0+8) * 132 + cc+1] = acc[mt][nt][3];
        }
    __syncthreads();

    float4 bs = *(const float4*)(bias + bcol + lane * 4);
    for (int r = wid; r < 128; r += 8) {
        float4 v = *(const float4*)&Cs[r * 132 + lane * 4];
        v.x += bs.x; v.y += bs.y; v.z += bs.z; v.w += bs.w;
        int grow = brow + r;
        int col = bcol + lane * 4;
        if (EPI == 0) {
            plain_store4(outB + (size_t)grow * 768, col, v.x, v.y, v.z, v.w);
        } else if (EPI == 1) {
            plain_store4(outB + (size_t)grow * 1024, col,
                         gelu_f(v.x), gelu_f(v.y), gelu_f(v.z), gelu_f(v.w));
        } else {
            float4 rr = *(const float4*)(resid + (size_t)grow * 256 + col);
            v.x += rr.x; v.y += rr.y; v.z += rr.z; v.w += rr.w;
            *(float4*)(outF + (size_t)grow * 256 + col) = v;
        }
    }
}

// ---- proj GEMM 128x256, 512 threads / 16 warps (64x32 warp tiles) ----------
// + reverse/roll + residual + fused LN2
#define PABUF 18432
#define PBBUF 36864
#define PSTG  (PABUF + PBBUF)
#define PROJ_SMEM (3*PSTG)

__global__ __launch_bounds__(512, 1) void gemm_proj(
        const __nv_bfloat16* __restrict__ A, const __nv_bfloat16* __restrict__ Wm,
        const float* __restrict__ bias, const float* __restrict__ resid,
        float* __restrict__ outF, __nv_bfloat16* __restrict__ outB,
        const float* __restrict__ lnw, const float* __restrict__ lnb) {
    extern __shared__ __align__(16) char smraw[];
    const int K3 = 256;
    int tid = threadIdx.x, lane = tid & 31, wid = tid >> 5;   // wid 0..15
    int brow = blockIdx.x * 128;
    int wm = wid & 1, wn = wid >> 1;                          // 2 x 8 warp grid
    uint32_t sb = smem_u32(smraw);

    float acc[4][4][4] = {};
    const int NC = 4;

    const char* Agc = (const char*)(A + (size_t)brow * K3);
    const char* Bgc = (const char*)Wm;
    size_t rowstride = (size_t)K3 * 2;

    auto loadChunk = [&](int c, int buf) {
        uint32_t abase = sb + buf * PSTG;
        uint32_t bbase = abase + PABUF;
        const char* Ag = Agc + (size_t)c * 128;
        const char* Bg = Bgc + (size_t)c * 128;
        #pragma unroll
        for (int j = 0; j < 6; j++) {
            int x = tid + j * 512;            // 0..3071
            if (x < 1024) {
                int row = x >> 3, kc = x & 7;
                CP_ASYNC16(abase + row * 144 + kc * 16, Ag + (size_t)row * rowstride + kc * 16);
            } else {
                int y = x - 1024;
                int row = y >> 3, kc = y & 7;
                CP_ASYNC16(bbase + row * 144 + kc * 16, Bg + (size_t)row * rowstride + kc * 16);
            }
        }
        CP_COMMIT();
    };

    loadChunk(0, 0);
    loadChunk(1, 1);
    int bc = 0, bn2 = 2;
    for (int c = 0; c < NC; c++) {
        if (c + 1 < NC) CP_WAIT1(); else CP_WAIT0();
        __syncthreads();
        if (c + 2 < NC) loadChunk(c + 2, bn2);
        uint32_t abase = sb + bc * PSTG;
        uint32_t bbase = abase + PABUF;
        #pragma unroll
        for (int kh = 0; kh < 4; kh++) {
            uint32_t afr[4][4];
            #pragma unroll
            for (int mt = 0; mt < 4; mt++) {
                int row = wm * 64 + mt * 16 + ((lane >> 3) & 1) * 8 + (lane & 7);
                uint32_t addr = abase + row * 144 + kh * 32 + (lane >> 4) * 16;
                LDMATRIX_X4(afr[mt][0], afr[mt][1], afr[mt][2], afr[mt][3], addr);
            }
            uint32_t bfr[4][2];
            #pragma unroll
            for (int np = 0; np < 2; np++) {
                int nrow = wn * 32 + np * 16 + (lane >> 4) * 8 + (lane & 7);
                uint32_t addr = bbase + nrow * 144 + kh * 32 + ((lane >> 3) & 1) * 16;
                uint32_t r0, r1, r2, r3;
                LDMATRIX_X4(r0, r1, r2, r3, addr);
                bfr[np*2][0] = r0; bfr[np*2][1] = r1;
                bfr[np*2+1][0] = r2; bfr[np*2+1][1] = r3;
            }
            #pragma unroll
            for (int mt = 0; mt < 4; mt++)
                #pragma unroll
                for (int nt = 0; nt < 4; nt++)
                    MMA_BF16(acc[mt][nt], afr[mt], bfr[nt]);
        }
        bc++;  if (bc == 3)  bc = 0;
        bn2++; if (bn2 == 3) bn2 = 0;
    }
    __syncthreads();

    float* Cs = (float*)smraw;
    #pragma unroll
    for (int mt = 0; mt < 4; mt++)
        #pragma unroll
        for (int nt = 0; nt < 4; nt++) {
            int r0 = wm * 64 + mt * 16 + (lane >> 2);
            int cc = wn * 32 + nt * 8 + (lane & 3) * 2;
            Cs[r0 * 264 + cc]       = acc[mt][nt][0];
            Cs[r0 * 264 + cc + 1]   = acc[mt][nt][1];
            Cs[(r0+8) * 264 + cc]   = acc[mt][nt][2];
            Cs[(r0+8) * 264 + cc+1] = acc[mt][nt][3];
        }
    __syncthreads();

    int ca = lane * 4, cb2 = 128 + lane * 4;
    float4 bs0 = *(const float4*)(bias + ca);
    float4 bs1 = *(const float4*)(bias + cb2);
    float4 lw0 = *(const float4*)(lnw + ca), lw1 = *(const float4*)(lnw + cb2);
    float4 lb0 = *(const float4*)(lnb + ca), lb1 = *(const float4*)(lnb + cb2);
    for (int r = wid; r < 128; r += 16) {
        float4 v0 = *(const float4*)&Cs[r * 264 + ca];
        float4 v1 = *(const float4*)&Cs[r * 264 + cb2];
        v0.x += bs0.x; v0.y += bs0.y; v0.z += bs0.z; v0.w += bs0.w;
        v1.x += bs1.x; v1.y += bs1.y; v1.z += bs1.z; v1.w += bs1.w;
        int grow = brow + r;
        int bw = grow / N_, n = grow % N_;
        int bb = bw >> 8, wrem = bw & 255;
        int tw = wrem >> 6, hw = (wrem >> 3) & 7, wwn = wrem & 7;
        int nt = n / 49, nr = n % 49;
        int t2 = tw*WT + nt, h2 = hw*WH + nr/7, w2 = wwn*WW + nr%7;
        int t = t2 + STs; if (t >= T_) t -= T_;
        int h = h2 + SHs; if (h >= H_) h -= H_;
        int ww_ = w2 + SWs; if (ww_ >= W_) ww_ -= W_;
        size_t orow = ((size_t)((bb*T_ + t)*H_ + h))*W_ + ww_;
        float4 r0 = *(const float4*)(resid + orow * 256 + ca);
        float4 r1 = *(const float4*)(resid + orow * 256 + cb2);
        v0.x += r0.x; v0.y += r0.y; v0.z += r0.z; v0.w += r0.w;
        v1.x += r1.x; v1.y += r1.y; v1.z += r1.z; v1.w += r1.w;
        *(float4*)(outF + orow * 256 + ca)  = v0;
        *(float4*)(outF + orow * 256 + cb2) = v1;
        // fused LN2
        float s  = v0.x + v0.y + v0.z + v0.w + v1.x + v1.y + v1.z + v1.w;
        float ss = v0.x*v0.x + v0.y*v0.y + v0.z*v0.z + v0.w*v0.w
                 + v1.x*v1.x + v1.y*v1.y + v1.z*v1.z + v1.w*v1.w;
        #pragma unroll
        for (int o2 = 16; o2 > 0; o2 >>= 1) {
            s  += __shfl_xor_sync(0xffffffffu, s, o2);
            ss += __shfl_xor_sync(0xffffffffu, ss, o2);
        }
        float mean = s * (1.0f / 256.0f);
        float var  = ss * (1.0f / 256.0f) - mean * mean;
        float inv  = rsqrtf(var + 1e-5f);
        __nv_bfloat16* hnp = outB + orow * 256;
        plain_store4(hnp, ca,
            (v0.x - mean) * inv * lw0.x + lb0.x, (v0.y - mean) * inv * lw0.y + lb0.y,
            (v0.z - mean) * inv * lw0.z + lb0.z, (v0.w - mean) * inv * lw0.w + lb0.w);
        plain_store4(hnp, cb2,
            (v1.x - mean) * inv * lw1.x + lb1.x, (v1.y - mean) * inv * lw1.y + lb1.y,
            (v1.z - mean) * inv * lw1.z + lb1.z, (v1.w - mean) * inv * lw1.w + lb1.w);
    }
}

// ---------------- register-resident attention: 7 warps + smem bm prefetch --
#define QSTR 80
#define SM_Q  0
#define SM_K  (112*QSTR)
#define SM_V  (2*112*QSTR)
#define SM_BM (3*112*QSTR)          // 26880
#define ATTN_SMEM (SM_BM + 112*112*2)  // 51968

__global__ __launch_bounds__(224) void attn_tc() {
    extern __shared__ __align__(16) char asmem[];

    int tid = threadIdx.x, lane = tid & 31, wid = tid >> 5;   // wid 0..6
    int head = blockIdx.x & 7, bw = blockIdx.x >> 3;
    int wrem = bw & 255;
    int tw = wrem >> 6, hw = (wrem >> 3) & 7, wwn = wrem & 7;
    int cat = ((tw == 3) ? 4 : 0) | ((hw == 7) ? 2 : 0) | ((wwn == 7) ? 1 : 0);

    uint32_t uQ = smem_u32(asmem + SM_Q);
    uint32_t uK = smem_u32(asmem + SM_K);
    uint32_t uV = smem_u32(asmem + SM_V);
    uint32_t uBM = smem_u32(asmem + SM_BM);

    // prefetch this block's 112x112 bf16 bias/mask tile via cp.async
    {
        const char* bmsrc = (const char*)(g_bm + ((size_t)(cat*8 + head)) * (112*112));
        #pragma unroll
        for (int j = 0; j < 7; j++) {
            int x = tid + j * 224;
            CP_ASYNC16(uBM + x * 16, bmsrc + x * 16);
        }
        CP_COMMIT();
    }

    if (tid < N_) {
        const uint4* g = (const uint4*)(g_qkv + ((size_t)(bw*N_ + tid)) * 768 + head * HD);
        #pragma unroll
        for (int j = 0; j < 4; j++) {
            *(uint4*)(asmem + SM_Q + tid*QSTR + j*16) = g[j];
            *(uint4*)(asmem + SM_K + tid*QSTR + j*16) = g[32 + j];
            *(uint4*)(asmem + SM_V + tid*QSTR + j*16) = g[64 + j];
        }
    } else if (tid < 112) {
        uint4 z = make_uint4(0,0,0,0);
        #pragma unroll
        for (int j = 0; j < 4; j++) {
            *(uint4*)(asmem + SM_Q + tid*QSTR + j*16) = z;
            *(uint4*)(asmem + SM_K + tid*QSTR + j*16) = z;
            *(uint4*)(asmem + SM_V + tid*QSTR + j*16) = z;
        }
    }
    __syncthreads();

    float acc[14][4] = {};

    // ---- QK^T ----
    #pragma unroll
    for (int kh = 0; kh < 2; kh++) {
        uint32_t bfr[14][2];
        #pragma unroll
        for (int np = 0; np < 7; np++) {
            int nrow = np*16 + (lane >> 4) * 8 + (lane & 7);
            uint32_t addr = uK + nrow*QSTR + kh*32 + ((lane >> 3) & 1) * 16;
            uint32_t r0, r1, r2, r3;
            LDMATRIX_X4(r0, r1, r2, r3, addr);
            bfr[np*2][0] = r0; bfr[np*2][1] = r1;
            bfr[np*2+1][0] = r2; bfr[np*2+1][1] = r3;
        }
        int row = wid*16 + ((lane >> 3) & 1) * 8 + (lane & 7);
        uint32_t addr = uQ + row*QSTR + kh*32 + (lane >> 4) * 16;
        uint32_t afr[4];
        LDMATRIX_X4(afr[0], afr[1], afr[2], afr[3], addr);
        #pragma unroll
        for (int nt = 0; nt < 14; nt++)
            MMA_BF16(acc[nt], afr, bfr[nt]);
    }

    CP_WAIT0();
    __syncthreads();

    // ---- register softmax (bias+mask from smem) ----
    float inv0, inv1;
    {
        int row0 = wid*16 + (lane >> 2);
        const __nv_bfloat16* bm = (const __nv_bfloat16*)(asmem + SM_BM) + row0*112;
        int c0 = (lane & 3) * 2;
        float mx0 = -1e30f, mx1 = -1e30f;
        #pragma unroll
        for (int nt = 0; nt < 14; nt++) {
            float2 b0 = bm2f(bm + nt*8 + c0);
            float2 b1 = bm2f(bm + 8*112 + nt*8 + c0);
            float s0 = fmaf(acc[nt][0], 0.17677669529663687f, b0.x);
            float s1 = fmaf(acc[nt][1], 0.17677669529663687f, b0.y);
            float s2 = fmaf(acc[nt][2], 0.17677669529663687f, b1.x);
            float s3 = fmaf(acc[nt][3], 0.17677669529663687f, b1.y);
            acc[nt][0] = s0; acc[nt][1] = s1;
            acc[nt][2] = s2; acc[nt][3] = s3;
            mx0 = fmaxf(mx0, fmaxf(s0, s1));
            mx1 = fmaxf(mx1, fmaxf(s2, s3));
        }
        mx0 = fmaxf(mx0, __shfl_xor_sync(0xffffffffu, mx0, 1));
        mx0 = fmaxf(mx0, __shfl_xor_sync(0xffffffffu, mx0, 2));
        mx1 = fmaxf(mx1, __shfl_xor_sync(0xffffffffu, mx1, 1));
        mx1 = fmaxf(mx1, __shfl_xor_sync(0xffffffffu, mx1, 2));
        float sm0 = 0.f, sm1 = 0.f;
        #pragma unroll
        for (int nt = 0; nt < 14; nt++) {
            float e0 = __expf(acc[nt][0] - mx0);
            float e1 = __expf(acc[nt][1] - mx0);
            float e2 = __expf(acc[nt][2] - mx1);
            float e3 = __expf(acc[nt][3] - mx1);
            acc[nt][0] = e0; acc[nt][1] = e1;
            acc[nt][2] = e2; acc[nt][3] = e3;
            sm0 += e0 + e1; sm1 += e2 + e3;
        }
        sm0 += __shfl_xor_sync(0xffffffffu, sm0, 1);
        sm0 += __shfl_xor_sync(0xffffffffu, sm0, 2);
        sm1 += __shfl_xor_sync(0xffffffffu, sm1, 1);
        sm1 += __shfl_xor_sync(0xffffffffu, sm1, 2);
        inv0 = 1.0f / sm0;
        inv1 = 1.0f / sm1;
    }

    // ---- AV ----
    float av[4][4] = {};
    #pragma unroll
    for (int kt = 0; kt < 7; kt++) {
        uint32_t vfr[4][2];
        #pragma unroll
        for (int np = 0; np < 2; np++) {
            int krow = kt*16 + ((lane >> 3) & 1) * 8 + (lane & 7);
            int ncol = np*16 + (lane >> 4) * 8;
            uint32_t addr = uV + krow*QSTR + ncol*2;
            uint32_t r0, r1, r2, r3;
            LDMATRIX_X4T(r0, r1, r2, r3, addr);
            vfr[np*2][0] = r0; vfr[np*2][1] = r1;
            vfr[np*2+1][0] = r2; vfr[np*2+1][1] = r3;
        }
        uint32_t pa[4];
        pa[0] = pack2f(acc[2*kt][0],   acc[2*kt][1]);
        pa[1] = pack2f(acc[2*kt][2],   acc[2*kt][3]);
        pa[2] = pack2f(acc[2*kt+1][0], acc[2*kt+1][1]);
        pa[3] = pack2f(acc[2*kt+1][2], acc[2*kt+1][3]);
        #pragma unroll
        for (int nt = 0; nt < 4; nt++)
            MMA_BF16(av[nt], pa, vfr[nt]);
    }

    // ---- store ----
    {
        int r0 = wid*16 + (lane >> 2);
        int cb = head*HD + (lane & 3) * 2;
        #pragma unroll
        for (int nt = 0; nt < 4; nt++) {
            if (r0 < N_)
                *(uint32_t*)(g_att + ((size_t)(bw*N_ + r0))*256 + cb + nt*8)
                    = pack2f(av[nt][0]*inv0, av[nt][1]*inv0);
            if (r0 + 8 < N_)
                *(uint32_t*)(g_att + ((size_t)(bw*N_ + r0 + 8))*256 + cb + nt*8)
                    = pack2f(av[nt][2]*inv1, av[nt][3]*inv1);
        }
    }
}

// ---------------- host launcher ---------------------------------------------
extern "C" void kernel_launch(void* const* d_in, const int* in_sizes, int n_in,
                              void* d_out, int out_size) {
    const float* x     = (const float*)d_in[0];
    const float* n1w   = (const float*)d_in[1];
    const float* n1b   = (const float*)d_in[2];
    const float* qkvw  = (const float*)d_in[3];
    const float* qkvb  = (const float*)d_in[4];
    const float* projw = (const float*)d_in[5];
    const float* projb = (const float*)d_in[6];
    const float* rpe   = (const float*)d_in[7];
    const float* n2w   = (const float*)d_in[8];
    const float* n2b   = (const float*)d_in[9];
    const float* fc1w  = (const float*)d_in[10];
    const float* fc1b  = (const float*)d_in[11];
    const float* fc2w  = (const float*)d_in[12];
    const float* fc2b  = (const float*)d_in[13];
    float* out = (float*)d_out;

    __nv_bfloat16 *p_xw, *p_qkv, *p_att, *p_hn, *p_h3, *p_wqkv, *p_wproj, *p_wfc1, *p_wfc2;
    float *p_x2;
    cudaGetSymbolAddress((void**)&p_xw,  g_xw);
    cudaGetSymbolAddress((void**)&p_qkv, g_qkv);
    cudaGetSymbolAddress((void**)&p_att, g_att);
    cudaGetSymbolAddress((void**)&p_x2,  g_x2);
    cudaGetSymbolAddress((void**)&p_hn,  g_hn);
    cudaGetSymbolAddress((void**)&p_h3,  g_h3);
    cudaGetSymbolAddress((void**)&p_wqkv,  g_wqkv);
    cudaGetSymbolAddress((void**)&p_wproj, g_wproj);
    cudaGetSymbolAddress((void**)&p_wfc1,  g_wfc1);
    cudaGetSymbolAddress((void**)&p_wfc2,  g_wfc2);

    cudaFuncSetAttribute(attn_tc, cudaFuncAttributeMaxDynamicSharedMemorySize, ATTN_SMEM);
    cudaFuncSetAttribute(gemm_mma<0>, cudaFuncAttributeMaxDynamicSharedMemorySize, GEMM_SMEM);
    cudaFuncSetAttribute(gemm_mma<1>, cudaFuncAttributeMaxDynamicSharedMemorySize, GEMM_SMEM);
    cudaFuncSetAttribute(gemm_mma<3>, cudaFuncAttributeMaxDynamicSharedMemorySize, GEMM_SMEM);
    cudaFuncSetAttribute(gemm_proj, cudaFuncAttributeMaxDynamicSharedMemorySize, PROJ_SMEM);

    // 0+1. merged setup (weights + bm table) and LN1
    setup_ln_kernel<<<SETUP_BLOCKS + LN_BLOCKS, 256>>>(qkvw, projw, fc1w, fc2w, rpe,
                                                       x, p_xw, n1w, n1b);
    // 2. QKV GEMM (128x128 tile, K=256, N=768) -> bf16
    gemm_mma<0><<<dim3(6, 392), 256, GEMM_SMEM>>>(p_xw, p_wqkv, qkvb, nullptr, nullptr, p_qkv, 256);
    // 3. register-resident attention (7 warps + smem bm prefetch)
    attn_tc<<<BW_*HEADS, 224, ATTN_SMEM>>>();
    // 4. proj GEMM (128x256 tile, 512 threads) + reverse/roll + residual + fused LN2
    gemm_proj<<<392, 512, PROJ_SMEM>>>(p_att, p_wproj, projb, x, p_x2, p_hn, n2w, n2b);
    // 5. fc1 GEMM (128x128, K=256, N=1024) + GELU -> bf16
    gemm_mma<1><<<dim3(8, 392), 256, GEMM_SMEM>>>(p_hn, p_wfc1, fc1b, nullptr, nullptr, p_h3, 256);
    // 6. fc2 GEMM (128x128, K=1024, N=256) + residual -> out
    gemm_mma<3><<<dim3(2, 392), 256, GEMM_SMEM>>>(p_h3, p_wfc2, fc2b, p_x2, out, nullptr, 1024);
}